// round 1
// baseline (speedup 1.0000x reference)
#include <cuda_runtime.h>
#include <math.h>
#include <stdint.h>

// ---------------- constants ----------------
#define Bb 4
#define Ss 1024
#define Tt 4096          // B*S tokens
#define Dd 1024
#define Hh 16
#define HDd 64
#define Ee 8
#define Ff 4096
#define CAP 4096         // per-expert row capacity (worst case)
#define EPSf 1e-6f

// ---------------- scratch (device globals; no allocation allowed) ----------------
__device__ float g_x1[(size_t)Tt * Dd];
__device__ float g_q[(size_t)Tt * Dd];
__device__ float g_k[(size_t)Tt * Dd];
__device__ float g_v[(size_t)Tt * Dd];
__device__ float g_scores[(size_t)Bb * Hh * Ss * Ss];   // 256 MB
__device__ float g_o[(size_t)Tt * Dd];
__device__ float g_tmp[(size_t)Tt * Dd];
__device__ float g_hidden[(size_t)Tt * Dd];
__device__ float g_xt[(size_t)Tt * Dd];
__device__ int   g_topidx[Tt * 2];
__device__ float g_topw[Tt * 2];
__device__ int   g_cnt[Ee];
__device__ int   g_assign[Ee * CAP];
__device__ float g_aw[Ee * CAP];
__device__ float g_h[(size_t)Ee * CAP * Ff];            // 512 MB

// ---------------- helpers ----------------
__device__ __forceinline__ float warp_red_sum(float v) {
#pragma unroll
    for (int o = 16; o; o >>= 1) v += __shfl_xor_sync(0xffffffffu, v, o);
    return v;
}
__device__ __forceinline__ float warp_red_max(float v) {
#pragma unroll
    for (int o = 16; o; o >>= 1) v = fmaxf(v, __shfl_xor_sync(0xffffffffu, v, o));
    return v;
}

__device__ __forceinline__ void fma44(float (&acc)[4][4], const float4 a, const float4 b) {
    const float av[4] = {a.x, a.y, a.z, a.w};
    const float bv[4] = {b.x, b.y, b.z, b.w};
#pragma unroll
    for (int i = 0; i < 4; i++)
#pragma unroll
        for (int j = 0; j < 4; j++) acc[i][j] = fmaf(av[i], bv[j], acc[i][j]);
}

// ---------------- RMSNorm over D=1024 per token ----------------
__global__ void rmsnorm_k(const float* __restrict__ in, const float* __restrict__ w,
                          float* __restrict__ out) {
    const int t = blockIdx.x;
    const float* x = in + (size_t)t * Dd;
    float ss = 0.f;
    for (int i = threadIdx.x; i < Dd; i += 256) { float v = x[i]; ss = fmaf(v, v, ss); }
    __shared__ float red[8];
    __shared__ float sres;
    float ws = warp_red_sum(ss);
    if ((threadIdx.x & 31) == 0) red[threadIdx.x >> 5] = ws;
    __syncthreads();
    if (threadIdx.x == 0) {
        float s = 0.f;
        for (int i = 0; i < 8; i++) s += red[i];
        sres = rsqrtf(s * (1.f / Dd) + EPSf);
    }
    __syncthreads();
    const float r = sres;
    for (int i = threadIdx.x; i < Dd; i += 256) out[(size_t)t * Dd + i] = x[i] * r * w[i];
}

// ---------------- per-head RMSNorm (HD=64), in-place; sc folds attn scale for q ----------------
__global__ void headnorm_k(float* __restrict__ qk, const float* __restrict__ w, float sc) {
    const int warp = (blockIdx.x << 3) + (threadIdx.x >> 5);
    const int lane = threadIdx.x & 31;
    float* p = qk + (size_t)warp * HDd;
    float v0 = p[lane], v1 = p[lane + 32];
    float ss = warp_red_sum(fmaf(v0, v0, v1 * v1));
    float r = rsqrtf(ss * (1.f / HDd) + EPSf) * sc;
    p[lane] = v0 * r * w[lane];
    p[lane + 32] = v1 * r * w[lane + 32];
}

// ---------------- generic NN SGEMM: C[M,N]=A[M,K]@B[K,N], dims multiples of 64/16 ----------------
__global__ void __launch_bounds__(256) sgemm_nn(const float* __restrict__ A,
                                                const float* __restrict__ B,
                                                float* __restrict__ C,
                                                int K, int lda, int ldb, int ldc) {
    __shared__ float As[16][68];
    __shared__ float Bs[16][68];
    const int tid = threadIdx.x;
    const int tx = tid & 15, ty = tid >> 4;
    const int m0 = blockIdx.y << 6, n0 = blockIdx.x << 6;
    const int ma = tid >> 2, ka = (tid & 3) << 2;
    const int kb = tid >> 4, nb = (tid & 15) << 2;
    float acc[4][4] = {};
    for (int k0 = 0; k0 < K; k0 += 16) {
        float4 a = *(const float4*)(A + (size_t)(m0 + ma) * lda + k0 + ka);
        As[ka + 0][ma] = a.x; As[ka + 1][ma] = a.y; As[ka + 2][ma] = a.z; As[ka + 3][ma] = a.w;
        *(float4*)&Bs[kb][nb] = *(const float4*)(B + (size_t)(k0 + kb) * ldb + n0 + nb);
        __syncthreads();
#pragma unroll
        for (int kk = 0; kk < 16; kk++)
            fma44(acc, *(const float4*)&As[kk][ty << 2], *(const float4*)&Bs[kk][tx << 2]);
        __syncthreads();
    }
#pragma unroll
    for (int i = 0; i < 4; i++) {
        float4 r = make_float4(acc[i][0], acc[i][1], acc[i][2], acc[i][3]);
        *(float4*)(C + (size_t)(m0 + (ty << 2) + i) * ldc + n0 + (tx << 2)) = r;
    }
}

// ---------------- attention scores: per (b,h): S = q @ k^T (scale folded in q) ----------------
__global__ void __launch_bounds__(256) attn_scores_k() {
    const int z = blockIdx.z, b = z >> 4, h = z & 15;
    const float* A  = g_q + (size_t)b * Ss * Dd + h * HDd;
    const float* Bm = g_k + (size_t)b * Ss * Dd + h * HDd;
    float* C = g_scores + (size_t)z * Ss * Ss;
    __shared__ float As[16][68];
    __shared__ float Bs[16][68];
    const int tid = threadIdx.x;
    const int tx = tid & 15, ty = tid >> 4;
    const int m0 = blockIdx.y << 6, n0 = blockIdx.x << 6;
    const int ma = tid >> 2, ka = (tid & 3) << 2;
    float acc[4][4] = {};
    for (int k0 = 0; k0 < HDd; k0 += 16) {
        float4 a = *(const float4*)(A + (size_t)(m0 + ma) * Dd + k0 + ka);
        As[ka + 0][ma] = a.x; As[ka + 1][ma] = a.y; As[ka + 2][ma] = a.z; As[ka + 3][ma] = a.w;
        float4 bq = *(const float4*)(Bm + (size_t)(n0 + ma) * Dd + k0 + ka);
        Bs[ka + 0][ma] = bq.x; Bs[ka + 1][ma] = bq.y; Bs[ka + 2][ma] = bq.z; Bs[ka + 3][ma] = bq.w;
        __syncthreads();
#pragma unroll
        for (int kk = 0; kk < 16; kk++)
            fma44(acc, *(const float4*)&As[kk][ty << 2], *(const float4*)&Bs[kk][tx << 2]);
        __syncthreads();
    }
#pragma unroll
    for (int i = 0; i < 4; i++) {
        float4 r = make_float4(acc[i][0], acc[i][1], acc[i][2], acc[i][3]);
        *(float4*)(C + (size_t)(m0 + (ty << 2) + i) * Ss + n0 + (tx << 2)) = r;
    }
}

// ---------------- row softmax over S=1024 ----------------
__global__ void softmax_k() {
    const size_t row = blockIdx.x;
    float* p = g_scores + row * (size_t)Ss;
    const int tid = threadIdx.x;
    float4 v = *(float4*)(p + tid * 4);
    __shared__ float red[8];
    __shared__ float sval;
    float wm = warp_red_max(fmaxf(fmaxf(v.x, v.y), fmaxf(v.z, v.w)));
    if ((tid & 31) == 0) red[tid >> 5] = wm;
    __syncthreads();
    if (tid == 0) {
        float m = red[0];
        for (int i = 1; i < 8; i++) m = fmaxf(m, red[i]);
        sval = m;
    }
    __syncthreads();
    const float mx = sval;
    v.x = __expf(v.x - mx); v.y = __expf(v.y - mx); v.z = __expf(v.z - mx); v.w = __expf(v.w - mx);
    __syncthreads();
    float wsm = warp_red_sum(v.x + v.y + v.z + v.w);
    if ((tid & 31) == 0) red[tid >> 5] = wsm;
    __syncthreads();
    if (tid == 0) {
        float s = 0.f;
        for (int i = 0; i < 8; i++) s += red[i];
        sval = 1.f / s;
    }
    __syncthreads();
    const float inv = sval;
    v.x *= inv; v.y *= inv; v.z *= inv; v.w *= inv;
    *(float4*)(p + tid * 4) = v;
}

// ---------------- attention output: per (b,h): O = attn @ v  (M=1024,N=64,K=1024) ----------------
__global__ void __launch_bounds__(256) attn_av_k() {
    const int z = blockIdx.z, b = z >> 4, h = z & 15;
    const float* A  = g_scores + (size_t)z * Ss * Ss;
    const float* Bm = g_v + (size_t)b * Ss * Dd + h * HDd;
    float* C = g_o + (size_t)b * Ss * Dd + h * HDd;
    __shared__ float As[16][68];
    __shared__ float Bs[16][68];
    const int tid = threadIdx.x;
    const int tx = tid & 15, ty = tid >> 4;
    const int m0 = blockIdx.y << 6, n0 = blockIdx.x << 6;
    const int ma = tid >> 2, ka = (tid & 3) << 2;
    const int kb = tid >> 4, nb = (tid & 15) << 2;
    float acc[4][4] = {};
    for (int k0 = 0; k0 < Ss; k0 += 16) {
        float4 a = *(const float4*)(A + (size_t)(m0 + ma) * Ss + k0 + ka);
        As[ka + 0][ma] = a.x; As[ka + 1][ma] = a.y; As[ka + 2][ma] = a.z; As[ka + 3][ma] = a.w;
        *(float4*)&Bs[kb][nb] = *(const float4*)(Bm + (size_t)(k0 + kb) * Dd + n0 + nb);
        __syncthreads();
#pragma unroll
        for (int kk = 0; kk < 16; kk++)
            fma44(acc, *(const float4*)&As[kk][ty << 2], *(const float4*)&Bs[kk][tx << 2]);
        __syncthreads();
    }
#pragma unroll
    for (int i = 0; i < 4; i++) {
        float4 r = make_float4(acc[i][0], acc[i][1], acc[i][2], acc[i][3]);
        *(float4*)(C + (size_t)(m0 + (ty << 2) + i) * Dd + n0 + (tx << 2)) = r;
    }
}

// ---------------- residual + layerscale: hidden = hs + gamma * tmp ----------------
__global__ void resid_gamma_k(const float* __restrict__ hs, const float* __restrict__ gamma) {
    const int i = blockIdx.x * 256 + threadIdx.x;
    g_hidden[i] = fmaf(gamma[i & (Dd - 1)], g_tmp[i], hs[i]);
}

// ---------------- router: logits, softmax, top-2, normalized weights ----------------
__global__ void router_k(const float* __restrict__ Gw, float* __restrict__ logits_out,
                         int write_logits) {
    const int t = blockIdx.x;
    const int tid = threadIdx.x;
    const int w = tid >> 5, lane = tid & 31;
    const float* x = g_xt + (size_t)t * Dd;
    float s = 0.f;
    for (int d = lane; d < Dd; d += 32) s = fmaf(x[d], Gw[d * Ee + w], s);
    s = warp_red_sum(s);
    __shared__ float lg[Ee];
    if (lane == 0) lg[w] = s;
    __syncthreads();
    if (tid == 0) {
        float mx = lg[0];
#pragma unroll
        for (int e = 1; e < Ee; e++) mx = fmaxf(mx, lg[e]);
        float p[Ee];
        float sum = 0.f;
#pragma unroll
        for (int e = 0; e < Ee; e++) { p[e] = __expf(lg[e] - mx); sum += p[e]; }
        int i0 = 0;
#pragma unroll
        for (int e = 1; e < Ee; e++) if (p[e] > p[i0]) i0 = e;
        int i1 = (i0 == 0) ? 1 : 0;
#pragma unroll
        for (int e = 0; e < Ee; e++) if (e != i0 && p[e] > p[i1]) i1 = e;
        float v0 = p[i0] / sum, v1 = p[i1] / sum;
        float inv = 1.f / (v0 + v1);
        g_topidx[t * 2 + 0] = i0;
        g_topidx[t * 2 + 1] = i1;
        g_topw[t * 2 + 0] = v0 * inv;
        g_topw[t * 2 + 1] = v1 * inv;
    }
    if (write_logits && tid < Ee) logits_out[(size_t)t * Ee + tid] = lg[tid];
}

// ---------------- routing compaction ----------------
__global__ void zero_cnt_k() { if (threadIdx.x < Ee) g_cnt[threadIdx.x] = 0; }

__global__ void assign_k() {
    const int t = blockIdx.x * 256 + threadIdx.x;
    if (t >= Tt) return;
#pragma unroll
    for (int j = 0; j < 2; j++) {
        int e = g_topidx[t * 2 + j];
        int pos = atomicAdd(&g_cnt[e], 1);
        g_assign[e * CAP + pos] = t;
        g_aw[e * CAP + pos] = g_topw[t * 2 + j];
    }
}

// ---------------- MoE fused gate/up GEMM + SiLU*up -> g_h ----------------
__global__ void __launch_bounds__(256) moe_gu_k(const float* __restrict__ Wg,
                                                const float* __restrict__ Wu) {
    const int e = blockIdx.z;
    const int cnt = g_cnt[e];
    const int m0 = blockIdx.y << 6;
    if (m0 >= cnt) return;
    const int n0 = blockIdx.x << 6;
    __shared__ int toks[64];
    __shared__ float As[16][68];
    __shared__ float Bg[16][68];
    __shared__ float Bu[16][68];
    const int tid = threadIdx.x;
    if (tid < 64) {
        int r = m0 + tid;
        toks[tid] = g_assign[e * CAP + min(r, cnt - 1)];
    }
    __syncthreads();
    const int tx = tid & 15, ty = tid >> 4;
    const int ma = tid >> 2, ka = (tid & 3) << 2;
    const int kb = tid >> 4, nb = (tid & 15) << 2;
    const float* WgE = Wg + (size_t)e * Dd * Ff;
    const float* WuE = Wu + (size_t)e * Dd * Ff;
    float ag[4][4] = {};
    float au[4][4] = {};
    for (int k0 = 0; k0 < Dd; k0 += 16) {
        float4 a = *(const float4*)(g_xt + (size_t)toks[ma] * Dd + k0 + ka);
        As[ka + 0][ma] = a.x; As[ka + 1][ma] = a.y; As[ka + 2][ma] = a.z; As[ka + 3][ma] = a.w;
        *(float4*)&Bg[kb][nb] = *(const float4*)(WgE + (size_t)(k0 + kb) * Ff + n0 + nb);
        *(float4*)&Bu[kb][nb] = *(const float4*)(WuE + (size_t)(k0 + kb) * Ff + n0 + nb);
        __syncthreads();
#pragma unroll
        for (int kk = 0; kk < 16; kk++) {
            float4 av = *(const float4*)&As[kk][ty << 2];
            fma44(ag, av, *(const float4*)&Bg[kk][tx << 2]);
            fma44(au, av, *(const float4*)&Bu[kk][tx << 2]);
        }
        __syncthreads();
    }
    float* Hp = g_h + (size_t)e * CAP * Ff;
#pragma unroll
    for (int i = 0; i < 4; i++) {
        int r = m0 + (ty << 2) + i;
        if (r < cnt) {
            float4 o;
            float gvx = ag[i][0]; o.x = gvx / (1.f + __expf(-gvx)) * au[i][0];
            float gvy = ag[i][1]; o.y = gvy / (1.f + __expf(-gvy)) * au[i][1];
            float gvz = ag[i][2]; o.z = gvz / (1.f + __expf(-gvz)) * au[i][2];
            float gvw = ag[i][3]; o.w = gvw / (1.f + __expf(-gvw)) * au[i][3];
            *(float4*)(Hp + (size_t)r * Ff + n0 + (tx << 2)) = o;
        }
    }
}

// ---------------- MoE down GEMM + weighted scatter-add into output ----------------
__global__ void __launch_bounds__(256) moe_down_k(const float* __restrict__ Wd,
                                                  float* __restrict__ out) {
    const int e = blockIdx.z;
    const int cnt = g_cnt[e];
    const int m0 = blockIdx.y << 6;
    if (m0 >= cnt) return;
    const int n0 = blockIdx.x << 6;
    const float* A  = g_h + (size_t)e * CAP * Ff;
    const float* Bm = Wd + (size_t)e * Ff * Dd;
    __shared__ float As[16][68];
    __shared__ float Bs[16][68];
    const int tid = threadIdx.x;
    const int tx = tid & 15, ty = tid >> 4;
    const int ma = tid >> 2, ka = (tid & 3) << 2;
    const int kb = tid >> 4, nb = (tid & 15) << 2;
    const int rr = min(m0 + ma, cnt - 1);
    float acc[4][4] = {};
    for (int k0 = 0; k0 < Ff; k0 += 16) {
        float4 a = *(const float4*)(A + (size_t)rr * Ff + k0 + ka);
        As[ka + 0][ma] = a.x; As[ka + 1][ma] = a.y; As[ka + 2][ma] = a.z; As[ka + 3][ma] = a.w;
        *(float4*)&Bs[kb][nb] = *(const float4*)(Bm + (size_t)(k0 + kb) * Dd + n0 + nb);
        __syncthreads();
#pragma unroll
        for (int kk = 0; kk < 16; kk++)
            fma44(acc, *(const float4*)&As[kk][ty << 2], *(const float4*)&Bs[kk][tx << 2]);
        __syncthreads();
    }
#pragma unroll
    for (int i = 0; i < 4; i++) {
        int r = m0 + (ty << 2) + i;
        if (r < cnt) {
            int tok = g_assign[e * CAP + r];
            float w = g_aw[e * CAP + r];
            float* op = out + (size_t)tok * Dd + n0 + (tx << 2);
            atomicAdd(op + 0, w * acc[i][0]);
            atomicAdd(op + 1, w * acc[i][1]);
            atomicAdd(op + 2, w * acc[i][2]);
            atomicAdd(op + 3, w * acc[i][3]);
        }
    }
}

// ---------------- copy residual into output hidden region ----------------
__global__ void copy_out_k(float* __restrict__ out) {
    const size_t i = ((size_t)blockIdx.x * 256 + threadIdx.x) * 4;
    *(float4*)(out + i) = *(const float4*)(g_hidden + i);
}

// ---------------- launch ----------------
extern "C" void kernel_launch(void* const* d_in, const int* in_sizes, int n_in,
                              void* d_out, int out_size) {
    (void)in_sizes; (void)n_in;
    const float* hs    = (const float*)d_in[0];
    const float* ln1   = (const float*)d_in[1];
    const float* ln2   = (const float*)d_in[2];
    const float* Wq    = (const float*)d_in[3];
    const float* Wk    = (const float*)d_in[4];
    const float* Wv    = (const float*)d_in[5];
    const float* Wo    = (const float*)d_in[6];
    const float* qn    = (const float*)d_in[7];
    const float* kn    = (const float*)d_in[8];
    const float* gamma = (const float*)d_in[9];
    const float* gw    = (const float*)d_in[10];
    const float* Wg    = (const float*)d_in[11];
    const float* Wu    = (const float*)d_in[12];
    const float* Wd    = (const float*)d_in[13];
    float* out = (float*)d_out;

    float *p_x1, *p_q, *p_k, *p_v, *p_o, *p_tmp, *p_hidden, *p_xt;
    cudaGetSymbolAddress((void**)&p_x1, g_x1);
    cudaGetSymbolAddress((void**)&p_q, g_q);
    cudaGetSymbolAddress((void**)&p_k, g_k);
    cudaGetSymbolAddress((void**)&p_v, g_v);
    cudaGetSymbolAddress((void**)&p_o, g_o);
    cudaGetSymbolAddress((void**)&p_tmp, g_tmp);
    cudaGetSymbolAddress((void**)&p_hidden, g_hidden);
    cudaGetSymbolAddress((void**)&p_xt, g_xt);

    // --- attention branch ---
    rmsnorm_k<<<Tt, 256>>>(hs, ln1, p_x1);
    dim3 gq(Dd / 64, Tt / 64);
    sgemm_nn<<<gq, 256>>>(p_x1, Wq, p_q, Dd, Dd, Dd, Dd);
    sgemm_nn<<<gq, 256>>>(p_x1, Wk, p_k, Dd, Dd, Dd, Dd);
    sgemm_nn<<<gq, 256>>>(p_x1, Wv, p_v, Dd, Dd, Dd, Dd);
    headnorm_k<<<Tt * Hh / 8, 256>>>(p_q, qn, 0.125f);   // fold HD^-0.5 into q
    headnorm_k<<<Tt * Hh / 8, 256>>>(p_k, kn, 1.0f);
    attn_scores_k<<<dim3(Ss / 64, Ss / 64, Bb * Hh), 256>>>();
    softmax_k<<<Bb * Hh * Ss, 256>>>();
    attn_av_k<<<dim3(1, Ss / 64, Bb * Hh), 256>>>();
    sgemm_nn<<<gq, 256>>>(p_o, Wo, p_tmp, Dd, Dd, Dd, Dd);
    resid_gamma_k<<<Tt * Dd / 256, 256>>>(hs, gamma);

    // --- MoE branch ---
    rmsnorm_k<<<Tt, 256>>>(p_hidden, ln2, p_xt);
    int write_logits = (out_size >= Tt * Dd + Tt * Ee) ? 1 : 0;
    router_k<<<Tt, 256>>>(gw, out + (size_t)Tt * Dd, write_logits);
    zero_cnt_k<<<1, 32>>>();
    assign_k<<<Tt / 256, 256>>>();
    moe_gu_k<<<dim3(Ff / 64, CAP / 64, Ee), 256>>>(Wg, Wu);
    copy_out_k<<<Tt * Dd / 1024, 256>>>(out);
    moe_down_k<<<dim3(Dd / 64, CAP / 64, Ee), 256>>>(Wd, out);
}

// round 3
// speedup vs baseline: 1.4461x; 1.4461x over previous
#include <cuda_runtime.h>
#include <cuda_bf16.h>
#include <math.h>
#include <stdint.h>

// ---------------- constants ----------------
#define Bb 4
#define Ss 1024
#define Tt 4096
#define Dd 1024
#define Hh 16
#define HDd 64
#define Ee 8
#define Ff 4096
#define CAP 4096
#define EPSf 1e-6f

#define RS 40                 // smem row stride in bf16 elements (conflict-free)
// mloop1 stage layout (elements)
#define STE1 20480
#define SA_H 0
#define SA_L 5120
#define SB_H 10240
#define SB_L 15360
// gu stage layout
#define STE2 30720
#define SG_H 10240
#define SG_L 15360
#define SU_H 20480
#define SU_L 25600

#define SMEM1 (2 * STE1 * 2)   // 81920 B
#define SMEM2 (2 * STE2 * 2)   // 122880 B

// ---------------- scratch ----------------
__device__ __align__(256) float g_x1[(size_t)Tt * Dd];
__device__ __align__(256) float g_q[(size_t)Tt * Dd];
__device__ __align__(256) float g_k[(size_t)Tt * Dd];
__device__ __align__(256) float g_v[(size_t)Tt * Dd];
__device__ __align__(256) float g_scores[(size_t)Bb * Hh * Ss * Ss];
__device__ __align__(256) float g_o[(size_t)Tt * Dd];
__device__ __align__(256) float g_tmp[(size_t)Tt * Dd];
__device__ __align__(256) float g_hidden[(size_t)Tt * Dd];
__device__ __align__(256) float g_xt[(size_t)Tt * Dd];
__device__ int   g_topidx[Tt * 2];
__device__ float g_topw[Tt * 2];
__device__ int   g_cnt[Ee];
__device__ int   g_assign[Ee * CAP];
__device__ float g_aw[Ee * CAP];

// split activations
__device__ __align__(256) __nv_bfloat16 g_x1h[(size_t)Tt * Dd];
__device__ __align__(256) __nv_bfloat16 g_x1l[(size_t)Tt * Dd];
__device__ __align__(256) __nv_bfloat16 g_oh[(size_t)Tt * Dd];
__device__ __align__(256) __nv_bfloat16 g_ol[(size_t)Tt * Dd];
__device__ __align__(256) __nv_bfloat16 g_xth[(size_t)Tt * Dd];
__device__ __align__(256) __nv_bfloat16 g_xtl[(size_t)Tt * Dd];
__device__ __align__(256) __nv_bfloat16 g_hh[(size_t)Ee * CAP * Ff];
__device__ __align__(256) __nv_bfloat16 g_hl[(size_t)Ee * CAP * Ff];

// split-bf16 transposed weights [N][K]
__device__ __align__(256) __nv_bfloat16 g_WgTh[(size_t)Ee * Ff * Dd];
__device__ __align__(256) __nv_bfloat16 g_WgTl[(size_t)Ee * Ff * Dd];
__device__ __align__(256) __nv_bfloat16 g_WuTh[(size_t)Ee * Ff * Dd];
__device__ __align__(256) __nv_bfloat16 g_WuTl[(size_t)Ee * Ff * Dd];
__device__ __align__(256) __nv_bfloat16 g_WdTh[(size_t)Ee * Dd * Ff];
__device__ __align__(256) __nv_bfloat16 g_WdTl[(size_t)Ee * Dd * Ff];
__device__ __align__(256) __nv_bfloat16 g_WqTh[(size_t)Dd * Dd];
__device__ __align__(256) __nv_bfloat16 g_WqTl[(size_t)Dd * Dd];
__device__ __align__(256) __nv_bfloat16 g_WkTh[(size_t)Dd * Dd];
__device__ __align__(256) __nv_bfloat16 g_WkTl[(size_t)Dd * Dd];
__device__ __align__(256) __nv_bfloat16 g_WvTh[(size_t)Dd * Dd];
__device__ __align__(256) __nv_bfloat16 g_WvTl[(size_t)Dd * Dd];
__device__ __align__(256) __nv_bfloat16 g_WoTh[(size_t)Dd * Dd];
__device__ __align__(256) __nv_bfloat16 g_WoTl[(size_t)Dd * Dd];

// ---------------- helpers ----------------
__device__ __forceinline__ float warp_red_sum(float v) {
#pragma unroll
    for (int o = 16; o; o >>= 1) v += __shfl_xor_sync(0xffffffffu, v, o);
    return v;
}
__device__ __forceinline__ float warp_red_max(float v) {
#pragma unroll
    for (int o = 16; o; o >>= 1) v = fmaxf(v, __shfl_xor_sync(0xffffffffu, v, o));
    return v;
}
__device__ __forceinline__ uint32_t smem_u32(const void* p) {
    uint32_t a;
    asm("{ .reg .u64 t; cvta.to.shared.u64 t, %1; cvt.u32.u64 %0, t; }" : "=r"(a) : "l"(p));
    return a;
}
#define CP16(sm, gp) \
    asm volatile("cp.async.ca.shared.global [%0], [%1], 16;" :: "r"(sm), "l"(gp))
#define CPCOMMIT() asm volatile("cp.async.commit_group;")
#define CPWAIT1() asm volatile("cp.async.wait_group 1;")

__device__ __forceinline__ void ldm4(uint32_t* r, uint32_t addr) {
    asm volatile("ldmatrix.sync.aligned.m8n8.x4.shared.b16 {%0,%1,%2,%3}, [%4];"
                 : "=r"(r[0]), "=r"(r[1]), "=r"(r[2]), "=r"(r[3]) : "r"(addr));
}
__device__ __forceinline__ void mma_bf16(float* c, const uint32_t* a, const uint32_t* b) {
    asm volatile(
        "mma.sync.aligned.m16n8k16.row.col.f32.bf16.bf16.f32 "
        "{%0,%1,%2,%3},{%4,%5,%6,%7},{%8,%9},{%0,%1,%2,%3};"
        : "+f"(c[0]), "+f"(c[1]), "+f"(c[2]), "+f"(c[3])
        : "r"(a[0]), "r"(a[1]), "r"(a[2]), "r"(a[3]), "r"(b[0]), "r"(b[1]));
}

__device__ __forceinline__ void split4(const float4 v, uint2& ph, uint2& pl) {
    __nv_bfloat16 hx = __float2bfloat16(v.x), hy = __float2bfloat16(v.y),
                  hz = __float2bfloat16(v.z), hw = __float2bfloat16(v.w);
    float lx = v.x - __bfloat162float(hx), ly = v.y - __bfloat162float(hy),
          lz = v.z - __bfloat162float(hz), lw = v.w - __bfloat162float(hw);
    __nv_bfloat16 gx = __float2bfloat16(lx), gy = __float2bfloat16(ly),
                  gz = __float2bfloat16(lz), gw = __float2bfloat16(lw);
    unsigned short bhx = *(unsigned short*)&hx, bhy = *(unsigned short*)&hy;
    unsigned short bhz = *(unsigned short*)&hz, bhw = *(unsigned short*)&hw;
    unsigned short blx = *(unsigned short*)&gx, bly = *(unsigned short*)&gy;
    unsigned short blz = *(unsigned short*)&gz, blw = *(unsigned short*)&gw;
    ph.x = (uint32_t)bhx | ((uint32_t)bhy << 16);
    ph.y = (uint32_t)bhz | ((uint32_t)bhw << 16);
    pl.x = (uint32_t)blx | ((uint32_t)bly << 16);
    pl.y = (uint32_t)blz | ((uint32_t)blw << 16);
}

// ---------------- weight transpose + split ----------------
__global__ void tsplit_k(const float* __restrict__ in, __nv_bfloat16* __restrict__ oh,
                         __nv_bfloat16* __restrict__ ol, int Kdim, int Ndim) {
    __shared__ float t[32][33];
    const int kb = blockIdx.y << 5, nb = blockIdx.x << 5;
    const size_t zo = (size_t)blockIdx.z * Kdim * Ndim;
    in += zo; oh += zo; ol += zo;
    const int tx = threadIdx.x, ty = threadIdx.y;
#pragma unroll
    for (int i = 0; i < 32; i += 8)
        t[ty + i][tx] = in[(size_t)(kb + ty + i) * Ndim + nb + tx];
    __syncthreads();
#pragma unroll
    for (int i = 0; i < 32; i += 8) {
        float v = t[tx][ty + i];
        __nv_bfloat16 h = __float2bfloat16(v);
        __nv_bfloat16 l = __float2bfloat16(v - __bfloat162float(h));
        size_t o = (size_t)(nb + ty + i) * Kdim + kb + tx;
        oh[o] = h; ol[o] = l;
    }
}

// ---------------- activation split ----------------
__global__ void split_act_k(const float* __restrict__ in, __nv_bfloat16* __restrict__ oh,
                            __nv_bfloat16* __restrict__ ol) {
    const size_t i = ((size_t)blockIdx.x * 256 + threadIdx.x) * 4;
    float4 v = *(const float4*)(in + i);
    uint2 ph, pl; split4(v, ph, pl);
    *(uint2*)(oh + i) = ph;
    *(uint2*)(ol + i) = pl;
}

// ---------------- RMSNorm ----------------
__global__ void rmsnorm_k(const float* __restrict__ in, const float* __restrict__ w,
                          float* __restrict__ out) {
    const int t = blockIdx.x;
    const float* x = in + (size_t)t * Dd;
    float ss = 0.f;
    for (int i = threadIdx.x; i < Dd; i += 256) { float v = x[i]; ss = fmaf(v, v, ss); }
    __shared__ float red[8];
    __shared__ float sres;
    float ws = warp_red_sum(ss);
    if ((threadIdx.x & 31) == 0) red[threadIdx.x >> 5] = ws;
    __syncthreads();
    if (threadIdx.x == 0) {
        float s = 0.f;
        for (int i = 0; i < 8; i++) s += red[i];
        sres = rsqrtf(s * (1.f / Dd) + EPSf);
    }
    __syncthreads();
    const float r = sres;
    for (int i = threadIdx.x; i < Dd; i += 256) out[(size_t)t * Dd + i] = x[i] * r * w[i];
}

// ---------------- per-head RMSNorm ----------------
__global__ void headnorm_k(float* __restrict__ qk, const float* __restrict__ w, float sc) {
    const int warp = (blockIdx.x << 3) + (threadIdx.x >> 5);
    const int lane = threadIdx.x & 31;
    float* p = qk + (size_t)warp * HDd;
    float v0 = p[lane], v1 = p[lane + 32];
    float ss = warp_red_sum(fmaf(v0, v0, v1 * v1));
    float r = rsqrtf(ss * (1.f / HDd) + EPSf) * sc;
    p[lane] = v0 * r * w[lane];
    p[lane + 32] = v1 * r * w[lane + 32];
}

// ---------------- HMMA dense GEMM: C[M,N] = A @ B^T, A [M,K] h/l, B [N,K] h/l ----------------
__global__ void __launch_bounds__(256) hgemm_dense(
    const __nv_bfloat16* __restrict__ Ah, const __nv_bfloat16* __restrict__ Al,
    const __nv_bfloat16* __restrict__ Bh, const __nv_bfloat16* __restrict__ Bl,
    float* __restrict__ C, int K, int N) {
    extern __shared__ __nv_bfloat16 sm[];
    const uint32_t sb = smem_u32(sm);
    const int tid = threadIdx.x, lane = tid & 31, wid = tid >> 5;
    const int m0 = blockIdx.x << 7, n0 = blockIdx.y << 7;
    const int wm = wid & 3, wn = wid >> 2;

    float acc[2][8][4];
#pragma unroll
    for (int a = 0; a < 2; a++)
#pragma unroll
        for (int b = 0; b < 8; b++)
#pragma unroll
            for (int c = 0; c < 4; c++) acc[a][b][c] = 0.f;

    const int r2 = tid >> 2, cc8 = (tid & 3) << 3;
    const int r2b = (tid + 256) >> 2;

    // prologue stage 0
    {
        uint32_t base = sb;
#pragma unroll
        for (int i = 0; i < 2; i++) {
            int row = i ? r2b : r2;
            uint32_t so = (uint32_t)(row * RS + cc8) * 2;
            size_t ga = (size_t)(m0 + row) * K + cc8;
            size_t gb = (size_t)(n0 + row) * K + cc8;
            CP16(base + SA_H * 2 + so, Ah + ga);
            CP16(base + SA_L * 2 + so, Al + ga);
            CP16(base + SB_H * 2 + so, Bh + gb);
            CP16(base + SB_L * 2 + so, Bl + gb);
        }
        CPCOMMIT();
    }
    const int nb = K >> 5;
    for (int it = 0; it < nb; it++) {
        if (it + 1 < nb) {
            uint32_t base = sb + (uint32_t)((it + 1) & 1) * STE1 * 2;
            int k0 = (it + 1) << 5;
#pragma unroll
            for (int i = 0; i < 2; i++) {
                int row = i ? r2b : r2;
                uint32_t so = (uint32_t)(row * RS + cc8) * 2;
                size_t ga = (size_t)(m0 + row) * K + k0 + cc8;
                size_t gb = (size_t)(n0 + row) * K + k0 + cc8;
                CP16(base + SA_H * 2 + so, Ah + ga);
                CP16(base + SA_L * 2 + so, Al + ga);
                CP16(base + SB_H * 2 + so, Bh + gb);
                CP16(base + SB_L * 2 + so, Bl + gb);
            }
        }
        CPCOMMIT();
        CPWAIT1();
        __syncthreads();
        uint32_t base = sb + (uint32_t)(it & 1) * STE1 * 2;
#pragma unroll
        for (int ks = 0; ks < 2; ks++) {
            uint32_t ah[2][4], al[2][4];
#pragma unroll
            for (int mt = 0; mt < 2; mt++) {
                uint32_t ao = (uint32_t)((wm * 32 + mt * 16 + (lane & 15)) * RS +
                                         ks * 16 + (lane >> 4) * 8) * 2;
                ldm4(ah[mt], base + SA_H * 2 + ao);
                ldm4(al[mt], base + SA_L * 2 + ao);
            }
            uint32_t bh[4][4], bl[4][4];
#pragma unroll
            for (int bt = 0; bt < 4; bt++) {
                uint32_t bo = (uint32_t)((wn * 64 + bt * 16 + ((lane >> 4) & 1) * 8 +
                                          (lane & 7)) * RS +
                                         ks * 16 + ((lane >> 3) & 1) * 8) * 2;
                ldm4(bh[bt], base + SB_H * 2 + bo);
                ldm4(bl[bt], base + SB_L * 2 + bo);
            }
#pragma unroll
            for (int mt = 0; mt < 2; mt++)
#pragma unroll
                for (int nt = 0; nt < 8; nt++) {
                    const uint32_t* bph = &bh[nt >> 1][(nt & 1) * 2];
                    const uint32_t* bpl = &bl[nt >> 1][(nt & 1) * 2];
                    mma_bf16(acc[mt][nt], ah[mt], bph);
                    mma_bf16(acc[mt][nt], ah[mt], bpl);
                    mma_bf16(acc[mt][nt], al[mt], bph);
                }
        }
        __syncthreads();
    }
    const int lr = lane >> 2, lc2 = (lane & 3) * 2;
#pragma unroll
    for (int mt = 0; mt < 2; mt++)
#pragma unroll
        for (int nt = 0; nt < 8; nt++) {
            int row = m0 + wm * 32 + mt * 16 + lr;
            int col = n0 + wn * 64 + nt * 8 + lc2;
            *(float2*)(C + (size_t)row * N + col) = make_float2(acc[mt][nt][0], acc[mt][nt][1]);
            *(float2*)(C + (size_t)(row + 8) * N + col) = make_float2(acc[mt][nt][2], acc[mt][nt][3]);
        }
}

// ---------------- MoE gate/up fused HMMA + SiLU*up -> split bf16 ----------------
__global__ void __launch_bounds__(256) moe_gu_h() {
    extern __shared__ __nv_bfloat16 sm[];
    __shared__ int toks[128];
    const int e = blockIdx.z;
    const int cnt = g_cnt[e];
    const int m0 = blockIdx.x << 7;
    if (m0 >= cnt) return;
    const int n0 = blockIdx.y << 7;
    const uint32_t sb = smem_u32(sm);
    const int tid = threadIdx.x, lane = tid & 31, wid = tid >> 5;
    const int wm = wid & 3, wn = wid >> 2;
    if (tid < 128) toks[tid] = g_assign[e * CAP + min(m0 + tid, cnt - 1)];
    __syncthreads();

    const size_t eo = (size_t)e * Ff * Dd;
    const __nv_bfloat16* Gh = g_WgTh + eo;
    const __nv_bfloat16* Gl = g_WgTl + eo;
    const __nv_bfloat16* Uh = g_WuTh + eo;
    const __nv_bfloat16* Ul = g_WuTl + eo;

    float ag[2][8][4], au[2][8][4];
#pragma unroll
    for (int a = 0; a < 2; a++)
#pragma unroll
        for (int b = 0; b < 8; b++)
#pragma unroll
            for (int c = 0; c < 4; c++) { ag[a][b][c] = 0.f; au[a][b][c] = 0.f; }

    const int r2 = tid >> 2, cc8 = (tid & 3) << 3;
    const int r2b = (tid + 256) >> 2;

    {
        uint32_t base = sb;
#pragma unroll
        for (int i = 0; i < 2; i++) {
            int row = i ? r2b : r2;
            uint32_t so = (uint32_t)(row * RS + cc8) * 2;
            size_t ga = (size_t)toks[row] * Dd + cc8;
            size_t gb = (size_t)(n0 + row) * Dd + cc8;
            CP16(base + SA_H * 2 + so, g_xth + ga);
            CP16(base + SA_L * 2 + so, g_xtl + ga);
            CP16(base + SG_H * 2 + so, Gh + gb);
            CP16(base + SG_L * 2 + so, Gl + gb);
            CP16(base + SU_H * 2 + so, Uh + gb);
            CP16(base + SU_L * 2 + so, Ul + gb);
        }
        CPCOMMIT();
    }
    const int nb = Dd >> 5;
    for (int it = 0; it < nb; it++) {
        if (it + 1 < nb) {
            uint32_t base = sb + (uint32_t)((it + 1) & 1) * STE2 * 2;
            int k0 = (it + 1) << 5;
#pragma unroll
            for (int i = 0; i < 2; i++) {
                int row = i ? r2b : r2;
                uint32_t so = (uint32_t)(row * RS + cc8) * 2;
                size_t ga = (size_t)toks[row] * Dd + k0 + cc8;
                size_t gb = (size_t)(n0 + row) * Dd + k0 + cc8;
                CP16(base + SA_H * 2 + so, g_xth + ga);
                CP16(base + SA_L * 2 + so, g_xtl + ga);
                CP16(base + SG_H * 2 + so, Gh + gb);
                CP16(base + SG_L * 2 + so, Gl + gb);
                CP16(base + SU_H * 2 + so, Uh + gb);
                CP16(base + SU_L * 2 + so, Ul + gb);
            }
        }
        CPCOMMIT();
        CPWAIT1();
        __syncthreads();
        uint32_t base = sb + (uint32_t)(it & 1) * STE2 * 2;
#pragma unroll
        for (int ks = 0; ks < 2; ks++) {
            uint32_t ah[2][4], al[2][4];
#pragma unroll
            for (int mt = 0; mt < 2; mt++) {
                uint32_t ao = (uint32_t)((wm * 32 + mt * 16 + (lane & 15)) * RS +
                                         ks * 16 + (lane >> 4) * 8) * 2;
                ldm4(ah[mt], base + SA_H * 2 + ao);
                ldm4(al[mt], base + SA_L * 2 + ao);
            }
            uint32_t boff[4];
#pragma unroll
            for (int bt = 0; bt < 4; bt++)
                boff[bt] = (uint32_t)((wn * 64 + bt * 16 + ((lane >> 4) & 1) * 8 +
                                       (lane & 7)) * RS +
                                      ks * 16 + ((lane >> 3) & 1) * 8) * 2;
            {
                uint32_t bh[4][4], bl[4][4];
#pragma unroll
                for (int bt = 0; bt < 4; bt++) {
                    ldm4(bh[bt], base + SG_H * 2 + boff[bt]);
                    ldm4(bl[bt], base + SG_L * 2 + boff[bt]);
                }
#pragma unroll
                for (int mt = 0; mt < 2; mt++)
#pragma unroll
                    for (int nt = 0; nt < 8; nt++) {
                        const uint32_t* bph = &bh[nt >> 1][(nt & 1) * 2];
                        const uint32_t* bpl = &bl[nt >> 1][(nt & 1) * 2];
                        mma_bf16(ag[mt][nt], ah[mt], bph);
                        mma_bf16(ag[mt][nt], ah[mt], bpl);
                        mma_bf16(ag[mt][nt], al[mt], bph);
                    }
            }
            {
                uint32_t bh[4][4], bl[4][4];
#pragma unroll
                for (int bt = 0; bt < 4; bt++) {
                    ldm4(bh[bt], base + SU_H * 2 + boff[bt]);
                    ldm4(bl[bt], base + SU_L * 2 + boff[bt]);
                }
#pragma unroll
                for (int mt = 0; mt < 2; mt++)
#pragma unroll
                    for (int nt = 0; nt < 8; nt++) {
                        const uint32_t* bph = &bh[nt >> 1][(nt & 1) * 2];
                        const uint32_t* bpl = &bl[nt >> 1][(nt & 1) * 2];
                        mma_bf16(au[mt][nt], ah[mt], bph);
                        mma_bf16(au[mt][nt], ah[mt], bpl);
                        mma_bf16(au[mt][nt], al[mt], bph);
                    }
            }
        }
        __syncthreads();
    }
    // epilogue: silu(g)*u -> split bf16 into g_hh/g_hl at compact rows
    const int lr = lane >> 2, lc2 = (lane & 3) * 2;
#pragma unroll
    for (int mt = 0; mt < 2; mt++)
#pragma unroll
        for (int nt = 0; nt < 8; nt++) {
            int r = m0 + wm * 32 + mt * 16 + lr;
            int col = n0 + wn * 64 + nt * 8 + lc2;
#pragma unroll
            for (int half = 0; half < 2; half++) {
                int rr = r + half * 8;
                if (rr < cnt) {
                    float gv0 = ag[mt][nt][half * 2], gv1 = ag[mt][nt][half * 2 + 1];
                    float uv0 = au[mt][nt][half * 2], uv1 = au[mt][nt][half * 2 + 1];
                    float v0 = gv0 / (1.f + __expf(-gv0)) * uv0;
                    float v1 = gv1 / (1.f + __expf(-gv1)) * uv1;
                    __nv_bfloat16 h0 = __float2bfloat16(v0);
                    __nv_bfloat16 h1 = __float2bfloat16(v1);
                    __nv_bfloat16 l0 = __float2bfloat16(v0 - __bfloat162float(h0));
                    __nv_bfloat16 l1 = __float2bfloat16(v1 - __bfloat162float(h1));
                    size_t o = ((size_t)e * CAP + rr) * Ff + col;
                    __nv_bfloat162 hp; hp.x = h0; hp.y = h1;
                    __nv_bfloat162 lp; lp.x = l0; lp.y = l1;
                    *(__nv_bfloat162*)(g_hh + o) = hp;
                    *(__nv_bfloat162*)(g_hl + o) = lp;
                }
            }
        }
}

// ---------------- MoE down HMMA + weighted scatter-add ----------------
__global__ void __launch_bounds__(256) moe_down_h(float* __restrict__ out) {
    extern __shared__ __nv_bfloat16 sm[];
    const int e = blockIdx.z;
    const int cnt = g_cnt[e];
    const int m0 = blockIdx.x << 7;
    if (m0 >= cnt) return;
    const int n0 = blockIdx.y << 7;
    const uint32_t sb = smem_u32(sm);
    const int tid = threadIdx.x, lane = tid & 31, wid = tid >> 5;
    const int wm = wid & 3, wn = wid >> 2;

    const __nv_bfloat16* Ah = g_hh + (size_t)e * CAP * Ff;
    const __nv_bfloat16* Al = g_hl + (size_t)e * CAP * Ff;
    const size_t eo = (size_t)e * Dd * Ff;
    const __nv_bfloat16* Bh = g_WdTh + eo;
    const __nv_bfloat16* Bl = g_WdTl + eo;

    float acc[2][8][4];
#pragma unroll
    for (int a = 0; a < 2; a++)
#pragma unroll
        for (int b = 0; b < 8; b++)
#pragma unroll
            for (int c = 0; c < 4; c++) acc[a][b][c] = 0.f;

    const int r2 = tid >> 2, cc8 = (tid & 3) << 3;
    const int r2b = (tid + 256) >> 2;
    const int cm1 = cnt - 1;

    {
        uint32_t base = sb;
#pragma unroll
        for (int i = 0; i < 2; i++) {
            int row = i ? r2b : r2;
            uint32_t so = (uint32_t)(row * RS + cc8) * 2;
            size_t ga = (size_t)min(m0 + row, cm1) * Ff + cc8;
            size_t gb = (size_t)(n0 + row) * Ff + cc8;
            CP16(base + SA_H * 2 + so, Ah + ga);
            CP16(base + SA_L * 2 + so, Al + ga);
            CP16(base + SB_H * 2 + so, Bh + gb);
            CP16(base + SB_L * 2 + so, Bl + gb);
        }
        CPCOMMIT();
    }
    const int nb = Ff >> 5;
    for (int it = 0; it < nb; it++) {
        if (it + 1 < nb) {
            uint32_t base = sb + (uint32_t)((it + 1) & 1) * STE1 * 2;
            int k0 = (it + 1) << 5;
#pragma unroll
            for (int i = 0; i < 2; i++) {
                int row = i ? r2b : r2;
                uint32_t so = (uint32_t)(row * RS + cc8) * 2;
                size_t ga = (size_t)min(m0 + row, cm1) * Ff + k0 + cc8;
                size_t gb = (size_t)(n0 + row) * Ff + k0 + cc8;
                CP16(base + SA_H * 2 + so, Ah + ga);
                CP16(base + SA_L * 2 + so, Al + ga);
                CP16(base + SB_H * 2 + so, Bh + gb);
                CP16(base + SB_L * 2 + so, Bl + gb);
            }
        }
        CPCOMMIT();
        CPWAIT1();
        __syncthreads();
        uint32_t base = sb + (uint32_t)(it & 1) * STE1 * 2;
#pragma unroll
        for (int ks = 0; ks < 2; ks++) {
            uint32_t ah[2][4], al[2][4];
#pragma unroll
            for (int mt = 0; mt < 2; mt++) {
                uint32_t ao = (uint32_t)((wm * 32 + mt * 16 + (lane & 15)) * RS +
                                         ks * 16 + (lane >> 4) * 8) * 2;
                ldm4(ah[mt], base + SA_H * 2 + ao);
                ldm4(al[mt], base + SA_L * 2 + ao);
            }
            uint32_t bh[4][4], bl[4][4];
#pragma unroll
            for (int bt = 0; bt < 4; bt++) {
                uint32_t bo = (uint32_t)((wn * 64 + bt * 16 + ((lane >> 4) & 1) * 8 +
                                          (lane & 7)) * RS +
                                         ks * 16 + ((lane >> 3) & 1) * 8) * 2;
                ldm4(bh[bt], base + SB_H * 2 + bo);
                ldm4(bl[bt], base + SB_L * 2 + bo);
            }
#pragma unroll
            for (int mt = 0; mt < 2; mt++)
#pragma unroll
                for (int nt = 0; nt < 8; nt++) {
                    const uint32_t* bph = &bh[nt >> 1][(nt & 1) * 2];
                    const uint32_t* bpl = &bl[nt >> 1][(nt & 1) * 2];
                    mma_bf16(acc[mt][nt], ah[mt], bph);
                    mma_bf16(acc[mt][nt], ah[mt], bpl);
                    mma_bf16(acc[mt][nt], al[mt], bph);
                }
        }
        __syncthreads();
    }
    const int lr = lane >> 2, lc2 = (lane & 3) * 2;
#pragma unroll
    for (int mt = 0; mt < 2; mt++)
#pragma unroll
        for (int half = 0; half < 2; half++) {
            int r = m0 + wm * 32 + mt * 16 + lr + half * 8;
            if (r < cnt) {
                int tok = g_assign[e * CAP + r];
                float w = g_aw[e * CAP + r];
                float* op = out + (size_t)tok * Dd;
#pragma unroll
                for (int nt = 0; nt < 8; nt++) {
                    int col = n0 + wn * 64 + nt * 8 + lc2;
                    atomicAdd(op + col, w * acc[mt][nt][half * 2]);
                    atomicAdd(op + col + 1, w * acc[mt][nt][half * 2 + 1]);
                }
            }
        }
}

// ---------------- attention scores ----------------
__global__ void __launch_bounds__(256) attn_scores_k() {
    const int z = blockIdx.z, b = z >> 4, h = z & 15;
    const float* A  = g_q + (size_t)b * Ss * Dd + h * HDd;
    const float* Bm = g_k + (size_t)b * Ss * Dd + h * HDd;
    float* C = g_scores + (size_t)z * Ss * Ss;
    __shared__ float As[16][68];
    __shared__ float Bs[16][68];
    const int tid = threadIdx.x;
    const int tx = tid & 15, ty = tid >> 4;
    const int m0 = blockIdx.y << 6, n0 = blockIdx.x << 6;
    const int ma = tid >> 2, ka = (tid & 3) << 2;
    float acc[4][4] = {};
    for (int k0 = 0; k0 < HDd; k0 += 16) {
        float4 a = *(const float4*)(A + (size_t)(m0 + ma) * Dd + k0 + ka);
        As[ka + 0][ma] = a.x; As[ka + 1][ma] = a.y; As[ka + 2][ma] = a.z; As[ka + 3][ma] = a.w;
        float4 bq = *(const float4*)(Bm + (size_t)(n0 + ma) * Dd + k0 + ka);
        Bs[ka + 0][ma] = bq.x; Bs[ka + 1][ma] = bq.y; Bs[ka + 2][ma] = bq.z; Bs[ka + 3][ma] = bq.w;
        __syncthreads();
#pragma unroll
        for (int kk = 0; kk < 16; kk++) {
            float4 av = *(const float4*)&As[kk][ty << 2];
            float4 bv = *(const float4*)&Bs[kk][tx << 2];
            const float aa[4] = {av.x, av.y, av.z, av.w};
            const float bb[4] = {bv.x, bv.y, bv.z, bv.w};
#pragma unroll
            for (int i = 0; i < 4; i++)
#pragma unroll
                for (int j = 0; j < 4; j++) acc[i][j] = fmaf(aa[i], bb[j], acc[i][j]);
        }
        __syncthreads();
    }
#pragma unroll
    for (int i = 0; i < 4; i++) {
        float4 r = make_float4(acc[i][0], acc[i][1], acc[i][2], acc[i][3]);
        *(float4*)(C + (size_t)(m0 + (ty << 2) + i) * Ss + n0 + (tx << 2)) = r;
    }
}

// ---------------- row softmax ----------------
__global__ void softmax_k() {
    const size_t row = blockIdx.x;
    float* p = g_scores + row * (size_t)Ss;
    const int tid = threadIdx.x;
    float4 v = *(float4*)(p + tid * 4);
    __shared__ float red[8];
    __shared__ float sval;
    float wm = warp_red_max(fmaxf(fmaxf(v.x, v.y), fmaxf(v.z, v.w)));
    if ((tid & 31) == 0) red[tid >> 5] = wm;
    __syncthreads();
    if (tid == 0) {
        float m = red[0];
        for (int i = 1; i < 8; i++) m = fmaxf(m, red[i]);
        sval = m;
    }
    __syncthreads();
    const float mx = sval;
    v.x = __expf(v.x - mx); v.y = __expf(v.y - mx); v.z = __expf(v.z - mx); v.w = __expf(v.w - mx);
    __syncthreads();
    float wsm = warp_red_sum(v.x + v.y + v.z + v.w);
    if ((tid & 31) == 0) red[tid >> 5] = wsm;
    __syncthreads();
    if (tid == 0) {
        float s = 0.f;
        for (int i = 0; i < 8; i++) s += red[i];
        sval = 1.f / s;
    }
    __syncthreads();
    const float inv = sval;
    v.x *= inv; v.y *= inv; v.z *= inv; v.w *= inv;
    *(float4*)(p + tid * 4) = v;
}

// ---------------- attention output ----------------
__global__ void __launch_bounds__(256) attn_av_k() {
    const int z = blockIdx.z, b = z >> 4, h = z & 15;
    const float* A  = g_scores + (size_t)z * Ss * Ss;
    const float* Bm = g_v + (size_t)b * Ss * Dd + h * HDd;
    float* C = g_o + (size_t)b * Ss * Dd + h * HDd;
    __shared__ float As[16][68];
    __shared__ float Bs[16][68];
    const int tid = threadIdx.x;
    const int tx = tid & 15, ty = tid >> 4;
    const int m0 = blockIdx.y << 6, n0 = blockIdx.x << 6;
    const int ma = tid >> 2, ka = (tid & 3) << 2;
    const int kb = tid >> 4, nb = (tid & 15) << 2;
    float acc[4][4] = {};
    for (int k0 = 0; k0 < Ss; k0 += 16) {
        float4 a = *(const float4*)(A + (size_t)(m0 + ma) * Ss + k0 + ka);
        As[ka + 0][ma] = a.x; As[ka + 1][ma] = a.y; As[ka + 2][ma] = a.z; As[ka + 3][ma] = a.w;
        *(float4*)&Bs[kb][nb] = *(const float4*)(Bm + (size_t)(k0 + kb) * Dd + n0 + nb);
        __syncthreads();
#pragma unroll
        for (int kk = 0; kk < 16; kk++) {
            float4 av = *(const float4*)&As[kk][ty << 2];
            float4 bv = *(const float4*)&Bs[kk][tx << 2];
            const float aa[4] = {av.x, av.y, av.z, av.w};
            const float bb[4] = {bv.x, bv.y, bv.z, bv.w};
#pragma unroll
            for (int i = 0; i < 4; i++)
#pragma unroll
                for (int j = 0; j < 4; j++) acc[i][j] = fmaf(aa[i], bb[j], acc[i][j]);
        }
        __syncthreads();
    }
#pragma unroll
    for (int i = 0; i < 4; i++) {
        float4 r = make_float4(acc[i][0], acc[i][1], acc[i][2], acc[i][3]);
        *(float4*)(C + (size_t)(m0 + (ty << 2) + i) * Dd + n0 + (tx << 2)) = r;
    }
}

// ---------------- residual + layerscale ----------------
__global__ void resid_gamma_k(const float* __restrict__ hs, const float* __restrict__ gamma) {
    const int i = blockIdx.x * 256 + threadIdx.x;
    g_hidden[i] = fmaf(gamma[i & (Dd - 1)], g_tmp[i], hs[i]);
}

// ---------------- router ----------------
__global__ void router_k(const float* __restrict__ Gw, float* __restrict__ logits_out,
                         int write_logits) {
    const int t = blockIdx.x;
    const int tid = threadIdx.x;
    const int w = tid >> 5, lane = tid & 31;
    const float* x = g_xt + (size_t)t * Dd;
    float s = 0.f;
    for (int d = lane; d < Dd; d += 32) s = fmaf(x[d], Gw[d * Ee + w], s);
    s = warp_red_sum(s);
    __shared__ float lg[Ee];
    if (lane == 0) lg[w] = s;
    __syncthreads();
    if (tid == 0) {
        float mx = lg[0];
#pragma unroll
        for (int e = 1; e < Ee; e++) mx = fmaxf(mx, lg[e]);
        float p[Ee];
        float sum = 0.f;
#pragma unroll
        for (int e = 0; e < Ee; e++) { p[e] = __expf(lg[e] - mx); sum += p[e]; }
        int i0 = 0;
#pragma unroll
        for (int e = 1; e < Ee; e++) if (p[e] > p[i0]) i0 = e;
        int i1 = (i0 == 0) ? 1 : 0;
#pragma unroll
        for (int e = 0; e < Ee; e++) if (e != i0 && p[e] > p[i1]) i1 = e;
        float v0 = p[i0] / sum, v1 = p[i1] / sum;
        float inv = 1.f / (v0 + v1);
        g_topidx[t * 2 + 0] = i0;
        g_topidx[t * 2 + 1] = i1;
        g_topw[t * 2 + 0] = v0 * inv;
        g_topw[t * 2 + 1] = v1 * inv;
    }
    if (write_logits && tid < Ee) logits_out[(size_t)t * Ee + tid] = lg[tid];
}

// ---------------- routing compaction ----------------
__global__ void zero_cnt_k() { if (threadIdx.x < Ee) g_cnt[threadIdx.x] = 0; }

__global__ void assign_k() {
    const int t = blockIdx.x * 256 + threadIdx.x;
    if (t >= Tt) return;
#pragma unroll
    for (int j = 0; j < 2; j++) {
        int e = g_topidx[t * 2 + j];
        int pos = atomicAdd(&g_cnt[e], 1);
        g_assign[e * CAP + pos] = t;
        g_aw[e * CAP + pos] = g_topw[t * 2 + j];
    }
}

// ---------------- copy residual into out ----------------
__global__ void copy_out_k(float* __restrict__ out) {
    const size_t i = ((size_t)blockIdx.x * 256 + threadIdx.x) * 4;
    *(float4*)(out + i) = *(const float4*)(g_hidden + i);
}

// ---------------- launch ----------------
extern "C" void kernel_launch(void* const* d_in, const int* in_sizes, int n_in,
                              void* d_out, int out_size) {
    (void)in_sizes; (void)n_in;
    const float* hs    = (const float*)d_in[0];
    const float* ln1   = (const float*)d_in[1];
    const float* ln2   = (const float*)d_in[2];
    const float* Wq    = (const float*)d_in[3];
    const float* Wk    = (const float*)d_in[4];
    const float* Wv    = (const float*)d_in[5];
    const float* Wo    = (const float*)d_in[6];
    const float* qn    = (const float*)d_in[7];
    const float* kn    = (const float*)d_in[8];
    const float* gamma = (const float*)d_in[9];
    const float* gw    = (const float*)d_in[10];
    const float* Wg    = (const float*)d_in[11];
    const float* Wu    = (const float*)d_in[12];
    const float* Wd    = (const float*)d_in[13];
    float* out = (float*)d_out;

    float *p_x1, *p_q, *p_k, *p_v, *p_o, *p_tmp, *p_hidden, *p_xt;
    cudaGetSymbolAddress((void**)&p_x1, g_x1);
    cudaGetSymbolAddress((void**)&p_q, g_q);
    cudaGetSymbolAddress((void**)&p_k, g_k);
    cudaGetSymbolAddress((void**)&p_v, g_v);
    cudaGetSymbolAddress((void**)&p_o, g_o);
    cudaGetSymbolAddress((void**)&p_tmp, g_tmp);
    cudaGetSymbolAddress((void**)&p_hidden, g_hidden);
    cudaGetSymbolAddress((void**)&p_xt, g_xt);

    __nv_bfloat16 *wgh, *wgl, *wuh, *wul, *wdh, *wdl;
    __nv_bfloat16 *wqh, *wql, *wkh, *wkl, *wvh, *wvl, *woh, *wol;
    __nv_bfloat16 *x1h, *x1l, *oh, *ol, *xth, *xtl;
    cudaGetSymbolAddress((void**)&wgh, g_WgTh); cudaGetSymbolAddress((void**)&wgl, g_WgTl);
    cudaGetSymbolAddress((void**)&wuh, g_WuTh); cudaGetSymbolAddress((void**)&wul, g_WuTl);
    cudaGetSymbolAddress((void**)&wdh, g_WdTh); cudaGetSymbolAddress((void**)&wdl, g_WdTl);
    cudaGetSymbolAddress((void**)&wqh, g_WqTh); cudaGetSymbolAddress((void**)&wql, g_WqTl);
    cudaGetSymbolAddress((void**)&wkh, g_WkTh); cudaGetSymbolAddress((void**)&wkl, g_WkTl);
    cudaGetSymbolAddress((void**)&wvh, g_WvTh); cudaGetSymbolAddress((void**)&wvl, g_WvTl);
    cudaGetSymbolAddress((void**)&woh, g_WoTh); cudaGetSymbolAddress((void**)&wol, g_WoTl);
    cudaGetSymbolAddress((void**)&x1h, g_x1h);  cudaGetSymbolAddress((void**)&x1l, g_x1l);
    cudaGetSymbolAddress((void**)&oh, g_oh);    cudaGetSymbolAddress((void**)&ol, g_ol);
    cudaGetSymbolAddress((void**)&xth, g_xth);  cudaGetSymbolAddress((void**)&xtl, g_xtl);

    cudaFuncSetAttribute(hgemm_dense, cudaFuncAttributeMaxDynamicSharedMemorySize, SMEM1);
    cudaFuncSetAttribute(moe_down_h, cudaFuncAttributeMaxDynamicSharedMemorySize, SMEM1);
    cudaFuncSetAttribute(moe_gu_h, cudaFuncAttributeMaxDynamicSharedMemorySize, SMEM2);

    dim3 tb32(32, 8);
    tsplit_k<<<dim3(32, 32, 1), tb32>>>(Wq, wqh, wql, Dd, Dd);
    tsplit_k<<<dim3(32, 32, 1), tb32>>>(Wk, wkh, wkl, Dd, Dd);
    tsplit_k<<<dim3(32, 32, 1), tb32>>>(Wv, wvh, wvl, Dd, Dd);
    tsplit_k<<<dim3(32, 32, 1), tb32>>>(Wo, woh, wol, Dd, Dd);
    tsplit_k<<<dim3(Ff / 32, Dd / 32, Ee), tb32>>>(Wg, wgh, wgl, Dd, Ff);
    tsplit_k<<<dim3(Ff / 32, Dd / 32, Ee), tb32>>>(Wu, wuh, wul, Dd, Ff);
    tsplit_k<<<dim3(Dd / 32, Ff / 32, Ee), tb32>>>(Wd, wdh, wdl, Ff, Dd);

    // --- attention branch ---
    rmsnorm_k<<<Tt, 256>>>(hs, ln1, p_x1);
    split_act_k<<<Tt * Dd / 1024, 256>>>(p_x1, x1h, x1l);
    hgemm_dense<<<dim3(32, 8), 256, SMEM1>>>(x1h, x1l, wqh, wql, p_q, Dd, Dd);
    hgemm_dense<<<dim3(32, 8), 256, SMEM1>>>(x1h, x1l, wkh, wkl, p_k, Dd, Dd);
    hgemm_dense<<<dim3(32, 8), 256, SMEM1>>>(x1h, x1l, wvh, wvl, p_v, Dd, Dd);
    headnorm_k<<<Tt * Hh / 8, 256>>>(p_q, qn, 0.125f);
    headnorm_k<<<Tt * Hh / 8, 256>>>(p_k, kn, 1.0f);
    attn_scores_k<<<dim3(Ss / 64, Ss / 64, Bb * Hh), 256>>>();
    softmax_k<<<Bb * Hh * Ss, 256>>>();
    attn_av_k<<<dim3(1, Ss / 64, Bb * Hh), 256>>>();
    split_act_k<<<Tt * Dd / 1024, 256>>>(p_o, oh, ol);
    hgemm_dense<<<dim3(32, 8), 256, SMEM1>>>(oh, ol, woh, wol, p_tmp, Dd, Dd);
    resid_gamma_k<<<Tt * Dd / 256, 256>>>(hs, gamma);

    // --- MoE branch ---
    rmsnorm_k<<<Tt, 256>>>(p_hidden, ln2, p_xt);
    int write_logits = (out_size >= Tt * Dd + Tt * Ee) ? 1 : 0;
    router_k<<<Tt, 256>>>(gw, out + (size_t)Tt * Dd, write_logits);
    split_act_k<<<Tt * Dd / 1024, 256>>>(p_xt, xth, xtl);
    zero_cnt_k<<<1, 32>>>();
    assign_k<<<Tt / 256, 256>>>();
    moe_gu_h<<<dim3(CAP / 128, Ff / 128, Ee), 256, SMEM2>>>();
    copy_out_k<<<Tt * Dd / 1024, 256>>>(out);
    moe_down_h<<<dim3(CAP / 128, Dd / 128, Ee), 256, SMEM1>>>(out);
}

// round 4
// speedup vs baseline: 4.8108x; 3.3268x over previous
#include <cuda_runtime.h>
#include <cuda_fp16.h>
#include <math.h>
#include <stdint.h>

// ---------------- constants ----------------
#define Bb 4
#define Ss 1024
#define Tt 4096
#define Dd 1024
#define Hh 16
#define HDd 64
#define Ee 8
#define Ff 4096
#define CAP 4096
#define EPSf 1e-6f

#define RS 40              // smem row stride (fp16 elems)

// stage layouts (element offsets)
#define STEd 10240         // dense/scores: A(5120)+B(5120)
#define OFB  5120
#define STEa 7680          // av: A(5120)+B(2560)
#define STEg 15360         // gu: A+G+U
#define OFG  5120
#define OFU  10240

#define SMEMd (2 * STEd * 2)
#define SMEMa (2 * STEa * 2)
#define SMEMg (2 * STEg * 2)

// ---------------- scratch ----------------
__device__ __align__(256) float g_q[(size_t)Tt * Dd];
__device__ __align__(256) float g_k[(size_t)Tt * Dd];
__device__ __align__(256) float g_v[(size_t)Tt * Dd];
__device__ __align__(256) float g_tmp[(size_t)Tt * Dd];
__device__ __align__(256) float g_hidden[(size_t)Tt * Dd];
__device__ __align__(256) float g_xt[(size_t)Tt * Dd];
__device__ __align__(256) float g_moeout[(size_t)Ee * CAP * Dd];
__device__ int   g_topidx[Tt * 2];
__device__ float g_topw[Tt * 2];
__device__ int   g_slotid[Tt * 2];
__device__ int   g_cnt[Ee];
__device__ int   g_assign[Ee * CAP];

// fp16 activations
__device__ __align__(256) __half g_x16[(size_t)Tt * Dd];
__device__ __align__(256) __half g_q16[(size_t)Tt * Dd];
__device__ __align__(256) __half g_k16[(size_t)Tt * Dd];
__device__ __align__(256) __half g_vT[(size_t)Bb * Hh * HDd * Ss];
__device__ __align__(256) __half g_o16[(size_t)Tt * Dd];
__device__ __align__(256) __half g_xt16[(size_t)Tt * Dd];
__device__ __align__(256) __half g_scoresh[(size_t)Bb * Hh * Ss * Ss];
__device__ __align__(256) __half g_probs[(size_t)Bb * Hh * Ss * Ss];
__device__ __align__(256) __half g_h16[(size_t)Ee * CAP * Ff];

// fp16 transposed weights [N][K]
__device__ __align__(256) __half g_WgT[(size_t)Ee * Ff * Dd];
__device__ __align__(256) __half g_WuT[(size_t)Ee * Ff * Dd];
__device__ __align__(256) __half g_WdT[(size_t)Ee * Dd * Ff];
__device__ __align__(256) __half g_WqT[(size_t)Dd * Dd];
__device__ __align__(256) __half g_WkT[(size_t)Dd * Dd];
__device__ __align__(256) __half g_WvT[(size_t)Dd * Dd];
__device__ __align__(256) __half g_WoT[(size_t)Dd * Dd];

// ---------------- helpers ----------------
__device__ __forceinline__ float warp_red_sum(float v) {
#pragma unroll
    for (int o = 16; o; o >>= 1) v += __shfl_xor_sync(0xffffffffu, v, o);
    return v;
}
__device__ __forceinline__ float warp_red_max(float v) {
#pragma unroll
    for (int o = 16; o; o >>= 1) v = fmaxf(v, __shfl_xor_sync(0xffffffffu, v, o));
    return v;
}
__device__ __forceinline__ uint32_t smem_u32(const void* p) {
    uint32_t a;
    asm("{ .reg .u64 t; cvta.to.shared.u64 t, %1; cvt.u32.u64 %0, t; }" : "=r"(a) : "l"(p));
    return a;
}
#define CP16(sm, gp) \
    asm volatile("cp.async.ca.shared.global [%0], [%1], 16;" :: "r"(sm), "l"(gp))
#define CPCOMMIT() asm volatile("cp.async.commit_group;")
#define CPWAIT1() asm volatile("cp.async.wait_group 1;")

__device__ __forceinline__ void ldm4(uint32_t* r, uint32_t addr) {
    asm volatile("ldmatrix.sync.aligned.m8n8.x4.shared.b16 {%0,%1,%2,%3}, [%4];"
                 : "=r"(r[0]), "=r"(r[1]), "=r"(r[2]), "=r"(r[3]) : "r"(addr));
}
__device__ __forceinline__ void mma_f16(float* c, const uint32_t* a, const uint32_t* b) {
    asm volatile(
        "mma.sync.aligned.m16n8k16.row.col.f32.f16.f16.f32 "
        "{%0,%1,%2,%3},{%4,%5,%6,%7},{%8,%9},{%0,%1,%2,%3};"
        : "+f"(c[0]), "+f"(c[1]), "+f"(c[2]), "+f"(c[3])
        : "r"(a[0]), "r"(a[1]), "r"(a[2]), "r"(a[3]), "r"(b[0]), "r"(b[1]));
}

// ---------------- weight transpose + fp16 convert: [K][N] fp32 -> [N][K] fp16 ----------------
__global__ void tconv_k(const float* __restrict__ in, __half* __restrict__ o,
                        int Kdim, int Ndim) {
    __shared__ float t[32][33];
    const int kb = blockIdx.y << 5, nb = blockIdx.x << 5;
    const size_t zo = (size_t)blockIdx.z * Kdim * Ndim;
    in += zo; o += zo;
    const int tx = threadIdx.x, ty = threadIdx.y;
#pragma unroll
    for (int i = 0; i < 32; i += 8)
        t[ty + i][tx] = in[(size_t)(kb + ty + i) * Ndim + nb + tx];
    __syncthreads();
#pragma unroll
    for (int i = 0; i < 32; i += 8)
        o[(size_t)(nb + ty + i) * Kdim + kb + tx] = __float2half_rn(t[tx][ty + i]);
}

// ---------------- RMSNorm -> fp16 (optionally fp32 too) ----------------
__global__ void rmsnorm_h(const float* __restrict__ in, const float* __restrict__ w,
                          __half* __restrict__ o16, float* __restrict__ of) {
    const int t = blockIdx.x;
    const float* x = in + (size_t)t * Dd;
    float ss = 0.f;
    for (int i = threadIdx.x; i < Dd; i += 256) { float v = x[i]; ss = fmaf(v, v, ss); }
    __shared__ float red[8];
    __shared__ float sres;
    float ws = warp_red_sum(ss);
    if ((threadIdx.x & 31) == 0) red[threadIdx.x >> 5] = ws;
    __syncthreads();
    if (threadIdx.x == 0) {
        float s = 0.f;
        for (int i = 0; i < 8; i++) s += red[i];
        sres = rsqrtf(s * (1.f / Dd) + EPSf);
    }
    __syncthreads();
    const float r = sres;
    for (int i = threadIdx.x; i < Dd; i += 256) {
        float v = x[i] * r * w[i];
        o16[(size_t)t * Dd + i] = __float2half_rn(v);
        if (of) of[(size_t)t * Dd + i] = v;
    }
}

// ---------------- per-head RMSNorm fp32 -> fp16 ----------------
__global__ void headnorm16_k(const float* __restrict__ qk, const float* __restrict__ w,
                             float sc, __half* __restrict__ o16) {
    const int warp = (blockIdx.x << 3) + (threadIdx.x >> 5);
    const int lane = threadIdx.x & 31;
    const float* p = qk + (size_t)warp * HDd;
    float v0 = p[lane], v1 = p[lane + 32];
    float ss = warp_red_sum(fmaf(v0, v0, v1 * v1));
    float r = rsqrtf(ss * (1.f / HDd) + EPSf) * sc;
    __half* q = o16 + (size_t)warp * HDd;
    q[lane] = __float2half_rn(v0 * r * w[lane]);
    q[lane + 32] = __float2half_rn(v1 * r * w[lane + 32]);
}

// ---------------- v transpose: fp32 [S][HD] per (b,h) -> fp16 [HD][S] ----------------
__global__ void vT_k() {
    __shared__ float t[32][33];
    const int z = blockIdx.z, b = z >> 4, h = z & 15;
    const int k0 = blockIdx.x << 5;   // token dim
    const int n0 = blockIdx.y << 5;   // head dim
    const float* src = g_v + (size_t)b * Ss * Dd + h * HDd;
    __half* dst = g_vT + (size_t)z * HDd * Ss;
    const int tx = threadIdx.x, ty = threadIdx.y;
#pragma unroll
    for (int i = 0; i < 32; i += 8)
        t[ty + i][tx] = src[(size_t)(k0 + ty + i) * Dd + n0 + tx];
    __syncthreads();
#pragma unroll
    for (int i = 0; i < 32; i += 8)
        dst[(size_t)(n0 + ty + i) * Ss + k0 + tx] = __float2half_rn(t[tx][ty + i]);
}

// ---------------- fp16 dense GEMM: C[M,N] fp32 = A16[M,K] @ B16[N,K]^T ----------------
__global__ void __launch_bounds__(256) hgemm16(
    const __half* __restrict__ A, const __half* __restrict__ B,
    float* __restrict__ C, int K, int N) {
    extern __shared__ __half sm[];
    const uint32_t sb = smem_u32(sm);
    const int tid = threadIdx.x, lane = tid & 31, wid = tid >> 5;
    const int m0 = blockIdx.x << 7, n0 = blockIdx.y << 7;
    const int wm = wid & 3, wn = wid >> 2;

    float acc[2][8][4];
#pragma unroll
    for (int a = 0; a < 2; a++)
#pragma unroll
        for (int b = 0; b < 8; b++)
#pragma unroll
            for (int c = 0; c < 4; c++) acc[a][b][c] = 0.f;

    {
        uint32_t base = sb;
#pragma unroll
        for (int i = 0; i < 2; i++) {
            int idx = tid + (i << 8);
            int row = idx >> 2, ch8 = (idx & 3) << 3;
            uint32_t so = (uint32_t)(row * RS + ch8) * 2;
            CP16(base + so, A + (size_t)(m0 + row) * K + ch8);
            CP16(base + OFB * 2 + so, B + (size_t)(n0 + row) * K + ch8);
        }
        CPCOMMIT();
    }
    const int nb = K >> 5;
    for (int it = 0; it < nb; it++) {
        if (it + 1 < nb) {
            uint32_t base = sb + (uint32_t)((it + 1) & 1) * STEd * 2;
            int k0 = (it + 1) << 5;
#pragma unroll
            for (int i = 0; i < 2; i++) {
                int idx = tid + (i << 8);
                int row = idx >> 2, ch8 = (idx & 3) << 3;
                uint32_t so = (uint32_t)(row * RS + ch8) * 2;
                CP16(base + so, A + (size_t)(m0 + row) * K + k0 + ch8);
                CP16(base + OFB * 2 + so, B + (size_t)(n0 + row) * K + k0 + ch8);
            }
        }
        CPCOMMIT();
        CPWAIT1();
        __syncthreads();
        uint32_t base = sb + (uint32_t)(it & 1) * STEd * 2;
#pragma unroll
        for (int ks = 0; ks < 2; ks++) {
            uint32_t a[2][4];
#pragma unroll
            for (int mt = 0; mt < 2; mt++) {
                uint32_t ao = (uint32_t)((wm * 32 + mt * 16 + (lane & 15)) * RS +
                                         ks * 16 + (lane >> 4) * 8) * 2;
                ldm4(a[mt], base + ao);
            }
            uint32_t bq[4][4];
#pragma unroll
            for (int bt = 0; bt < 4; bt++) {
                uint32_t bo = (uint32_t)((wn * 64 + bt * 16 + ((lane >> 4) & 1) * 8 +
                                          (lane & 7)) * RS +
                                         ks * 16 + ((lane >> 3) & 1) * 8) * 2;
                ldm4(bq[bt], base + OFB * 2 + bo);
            }
#pragma unroll
            for (int mt = 0; mt < 2; mt++)
#pragma unroll
                for (int nt = 0; nt < 8; nt++)
                    mma_f16(acc[mt][nt], a[mt], &bq[nt >> 1][(nt & 1) * 2]);
        }
        __syncthreads();
    }
    const int lr = lane >> 2, lc2 = (lane & 3) * 2;
#pragma unroll
    for (int mt = 0; mt < 2; mt++)
#pragma unroll
        for (int nt = 0; nt < 8; nt++) {
            int row = m0 + wm * 32 + mt * 16 + lr;
            int col = n0 + wn * 64 + nt * 8 + lc2;
            *(float2*)(C + (size_t)row * N + col) = make_float2(acc[mt][nt][0], acc[mt][nt][1]);
            *(float2*)(C + (size_t)(row + 8) * N + col) = make_float2(acc[mt][nt][2], acc[mt][nt][3]);
        }
}

// ---------------- attention scores: per (b,h) S16 = q16 @ k16^T, K=64 ----------------
__global__ void __launch_bounds__(256) attn_scores16() {
    extern __shared__ __half sm[];
    const uint32_t sb = smem_u32(sm);
    const int z = blockIdx.z, b = z >> 4, h = z & 15;
    const int tid = threadIdx.x, lane = tid & 31, wid = tid >> 5;
    const int m0 = blockIdx.x << 7, n0 = blockIdx.y << 7;
    const int wm = wid & 3, wn = wid >> 2;
    const __half* A = g_q16 + (size_t)b * Ss * Dd + h * HDd;
    const __half* B = g_k16 + (size_t)b * Ss * Dd + h * HDd;

    float acc[2][8][4];
#pragma unroll
    for (int a = 0; a < 2; a++)
#pragma unroll
        for (int c = 0; c < 8; c++)
#pragma unroll
            for (int d = 0; d < 4; d++) acc[a][c][d] = 0.f;

    {
        uint32_t base = sb;
#pragma unroll
        for (int i = 0; i < 2; i++) {
            int idx = tid + (i << 8);
            int row = idx >> 2, ch8 = (idx & 3) << 3;
            uint32_t so = (uint32_t)(row * RS + ch8) * 2;
            CP16(base + so, A + (size_t)(m0 + row) * Dd + ch8);
            CP16(base + OFB * 2 + so, B + (size_t)(n0 + row) * Dd + ch8);
        }
        CPCOMMIT();
    }
    for (int it = 0; it < 2; it++) {
        if (it == 0) {
            uint32_t base = sb + STEd * 2;
#pragma unroll
            for (int i = 0; i < 2; i++) {
                int idx = tid + (i << 8);
                int row = idx >> 2, ch8 = (idx & 3) << 3;
                uint32_t so = (uint32_t)(row * RS + ch8) * 2;
                CP16(base + so, A + (size_t)(m0 + row) * Dd + 32 + ch8);
                CP16(base + OFB * 2 + so, B + (size_t)(n0 + row) * Dd + 32 + ch8);
            }
        }
        CPCOMMIT();
        CPWAIT1();
        __syncthreads();
        uint32_t base = sb + (uint32_t)(it & 1) * STEd * 2;
#pragma unroll
        for (int ks = 0; ks < 2; ks++) {
            uint32_t a[2][4];
#pragma unroll
            for (int mt = 0; mt < 2; mt++) {
                uint32_t ao = (uint32_t)((wm * 32 + mt * 16 + (lane & 15)) * RS +
                                         ks * 16 + (lane >> 4) * 8) * 2;
                ldm4(a[mt], base + ao);
            }
            uint32_t bq[4][4];
#pragma unroll
            for (int bt = 0; bt < 4; bt++) {
                uint32_t bo = (uint32_t)((wn * 64 + bt * 16 + ((lane >> 4) & 1) * 8 +
                                          (lane & 7)) * RS +
                                         ks * 16 + ((lane >> 3) & 1) * 8) * 2;
                ldm4(bq[bt], base + OFB * 2 + bo);
            }
#pragma unroll
            for (int mt = 0; mt < 2; mt++)
#pragma unroll
                for (int nt = 0; nt < 8; nt++)
                    mma_f16(acc[mt][nt], a[mt], &bq[nt >> 1][(nt & 1) * 2]);
        }
        __syncthreads();
    }
    __half* C = g_scoresh + (size_t)z * Ss * Ss;
    const int lr = lane >> 2, lc2 = (lane & 3) * 2;
#pragma unroll
    for (int mt = 0; mt < 2; mt++)
#pragma unroll
        for (int nt = 0; nt < 8; nt++) {
            int row = m0 + wm * 32 + mt * 16 + lr;
            int col = n0 + wn * 64 + nt * 8 + lc2;
            __half2 p0; p0.x = __float2half_rn(acc[mt][nt][0]); p0.y = __float2half_rn(acc[mt][nt][1]);
            __half2 p1; p1.x = __float2half_rn(acc[mt][nt][2]); p1.y = __float2half_rn(acc[mt][nt][3]);
            *(__half2*)(C + (size_t)row * Ss + col) = p0;
            *(__half2*)(C + (size_t)(row + 8) * Ss + col) = p1;
        }
}

// ---------------- row softmax fp16 -> fp16 probs ----------------
__global__ void softmax16_k() {
    const size_t row = blockIdx.x;
    const __half* p = g_scoresh + row * (size_t)Ss;
    __half* q = g_probs + row * (size_t)Ss;
    const int tid = threadIdx.x;
    __half2 h01 = *(const __half2*)(p + tid * 4);
    __half2 h23 = *(const __half2*)(p + tid * 4 + 2);
    float4 v = make_float4(__half2float(h01.x), __half2float(h01.y),
                           __half2float(h23.x), __half2float(h23.y));
    __shared__ float red[8];
    __shared__ float sval;
    float wm = warp_red_max(fmaxf(fmaxf(v.x, v.y), fmaxf(v.z, v.w)));
    if ((tid & 31) == 0) red[tid >> 5] = wm;
    __syncthreads();
    if (tid == 0) {
        float m = red[0];
        for (int i = 1; i < 8; i++) m = fmaxf(m, red[i]);
        sval = m;
    }
    __syncthreads();
    const float mx = sval;
    v.x = __expf(v.x - mx); v.y = __expf(v.y - mx); v.z = __expf(v.z - mx); v.w = __expf(v.w - mx);
    __syncthreads();
    float wsm = warp_red_sum(v.x + v.y + v.z + v.w);
    if ((tid & 31) == 0) red[tid >> 5] = wsm;
    __syncthreads();
    if (tid == 0) {
        float s = 0.f;
        for (int i = 0; i < 8; i++) s += red[i];
        sval = 1.f / s;
    }
    __syncthreads();
    const float inv = sval;
    __half2 o01, o23;
    o01.x = __float2half_rn(v.x * inv); o01.y = __float2half_rn(v.y * inv);
    o23.x = __float2half_rn(v.z * inv); o23.y = __float2half_rn(v.w * inv);
    *(__half2*)(q + tid * 4) = o01;
    *(__half2*)(q + tid * 4 + 2) = o23;
}

// ---------------- attention AV: per (b,h) o16 = probs @ vT^T (tile 128x64) ----------------
__global__ void __launch_bounds__(256) attn_av16() {
    extern __shared__ __half sm[];
    const uint32_t sb = smem_u32(sm);
    const int z = blockIdx.z, b = z >> 4, h = z & 15;
    const int tid = threadIdx.x, lane = tid & 31, wid = tid >> 5;
    const int m0 = blockIdx.x << 7;
    const int wm = wid & 3, wn = wid >> 2;
    const __half* A = g_probs + (size_t)z * Ss * Ss;
    const __half* B = g_vT + (size_t)z * HDd * Ss;

    float acc[2][4][4];
#pragma unroll
    for (int a = 0; a < 2; a++)
#pragma unroll
        for (int c = 0; c < 4; c++)
#pragma unroll
            for (int d = 0; d < 4; d++) acc[a][c][d] = 0.f;

    {
        uint32_t base = sb;
#pragma unroll
        for (int i = 0; i < 2; i++) {
            int idx = tid + (i << 8);
            int row = idx >> 2, ch8 = (idx & 3) << 3;
            uint32_t so = (uint32_t)(row * RS + ch8) * 2;
            CP16(base + so, A + (size_t)(m0 + row) * Ss + ch8);
        }
        {
            int row = tid >> 2, ch8 = (tid & 3) << 3;
            uint32_t so = (uint32_t)(row * RS + ch8) * 2;
            CP16(base + OFB * 2 + so, B + (size_t)row * Ss + ch8);
        }
        CPCOMMIT();
    }
    const int nb = Ss >> 5;
    for (int it = 0; it < nb; it++) {
        if (it + 1 < nb) {
            uint32_t base = sb + (uint32_t)((it + 1) & 1) * STEa * 2;
            int k0 = (it + 1) << 5;
#pragma unroll
            for (int i = 0; i < 2; i++) {
                int idx = tid + (i << 8);
                int row = idx >> 2, ch8 = (idx & 3) << 3;
                uint32_t so = (uint32_t)(row * RS + ch8) * 2;
                CP16(base + so, A + (size_t)(m0 + row) * Ss + k0 + ch8);
            }
            {
                int row = tid >> 2, ch8 = (tid & 3) << 3;
                uint32_t so = (uint32_t)(row * RS + ch8) * 2;
                CP16(base + OFB * 2 + so, B + (size_t)row * Ss + k0 + ch8);
            }
        }
        CPCOMMIT();
        CPWAIT1();
        __syncthreads();
        uint32_t base = sb + (uint32_t)(it & 1) * STEa * 2;
#pragma unroll
        for (int ks = 0; ks < 2; ks++) {
            uint32_t a[2][4];
#pragma unroll
            for (int mt = 0; mt < 2; mt++) {
                uint32_t ao = (uint32_t)((wm * 32 + mt * 16 + (lane & 15)) * RS +
                                         ks * 16 + (lane >> 4) * 8) * 2;
                ldm4(a[mt], base + ao);
            }
            uint32_t bq[2][4];
#pragma unroll
            for (int bt = 0; bt < 2; bt++) {
                uint32_t bo = (uint32_t)((wn * 32 + bt * 16 + ((lane >> 4) & 1) * 8 +
                                          (lane & 7)) * RS +
                                         ks * 16 + ((lane >> 3) & 1) * 8) * 2;
                ldm4(bq[bt], base + OFB * 2 + bo);
            }
#pragma unroll
            for (int mt = 0; mt < 2; mt++)
#pragma unroll
                for (int nt = 0; nt < 4; nt++)
                    mma_f16(acc[mt][nt], a[mt], &bq[nt >> 1][(nt & 1) * 2]);
        }
        __syncthreads();
    }
    __half* C = g_o16 + (size_t)b * Ss * Dd + h * HDd;
    const int lr = lane >> 2, lc2 = (lane & 3) * 2;
#pragma unroll
    for (int mt = 0; mt < 2; mt++)
#pragma unroll
        for (int nt = 0; nt < 4; nt++) {
            int row = m0 + wm * 32 + mt * 16 + lr;
            int col = wn * 32 + nt * 8 + lc2;
            __half2 p0; p0.x = __float2half_rn(acc[mt][nt][0]); p0.y = __float2half_rn(acc[mt][nt][1]);
            __half2 p1; p1.x = __float2half_rn(acc[mt][nt][2]); p1.y = __float2half_rn(acc[mt][nt][3]);
            *(__half2*)(C + (size_t)row * Dd + col) = p0;
            *(__half2*)(C + (size_t)(row + 8) * Dd + col) = p1;
        }
}

// ---------------- residual + layerscale ----------------
__global__ void resid_gamma_k(const float* __restrict__ hs, const float* __restrict__ gamma) {
    const int i = blockIdx.x * 256 + threadIdx.x;
    g_hidden[i] = fmaf(gamma[i & (Dd - 1)], g_tmp[i], hs[i]);
}

// ---------------- router ----------------
__global__ void router_k(const float* __restrict__ Gw, float* __restrict__ logits_out,
                         int write_logits) {
    const int t = blockIdx.x;
    const int tid = threadIdx.x;
    const int w = tid >> 5, lane = tid & 31;
    const float* x = g_xt + (size_t)t * Dd;
    float s = 0.f;
    for (int d = lane; d < Dd; d += 32) s = fmaf(x[d], Gw[d * Ee + w], s);
    s = warp_red_sum(s);
    __shared__ float lg[Ee];
    if (lane == 0) lg[w] = s;
    __syncthreads();
    if (tid == 0) {
        float mx = lg[0];
#pragma unroll
        for (int e = 1; e < Ee; e++) mx = fmaxf(mx, lg[e]);
        float p[Ee];
        float sum = 0.f;
#pragma unroll
        for (int e = 0; e < Ee; e++) { p[e] = __expf(lg[e] - mx); sum += p[e]; }
        int i0 = 0;
#pragma unroll
        for (int e = 1; e < Ee; e++) if (p[e] > p[i0]) i0 = e;
        int i1 = (i0 == 0) ? 1 : 0;
#pragma unroll
        for (int e = 0; e < Ee; e++) if (e != i0 && p[e] > p[i1]) i1 = e;
        float v0 = p[i0] / sum, v1 = p[i1] / sum;
        float inv = 1.f / (v0 + v1);
        g_topidx[t * 2 + 0] = i0;
        g_topidx[t * 2 + 1] = i1;
        g_topw[t * 2 + 0] = v0 * inv;
        g_topw[t * 2 + 1] = v1 * inv;
    }
    if (write_logits && tid < Ee) logits_out[(size_t)t * Ee + tid] = lg[tid];
}

// ---------------- routing compaction ----------------
__global__ void zero_cnt_k() { if (threadIdx.x < Ee) g_cnt[threadIdx.x] = 0; }

__global__ void assign_k() {
    const int t = blockIdx.x * 256 + threadIdx.x;
    if (t >= Tt) return;
#pragma unroll
    for (int j = 0; j < 2; j++) {
        int e = g_topidx[t * 2 + j];
        int pos = atomicAdd(&g_cnt[e], 1);
        g_assign[e * CAP + pos] = t;
        g_slotid[t * 2 + j] = e * CAP + pos;
    }
}

// ---------------- MoE gate/up fp16 + SiLU*up -> fp16 h ----------------
__global__ void __launch_bounds__(256) moe_gu16() {
    extern __shared__ __half sm[];
    __shared__ int toks[128];
    const int e = blockIdx.z;
    const int cnt = g_cnt[e];
    const int m0 = blockIdx.x << 7;
    if (m0 >= cnt) return;
    const int n0 = blockIdx.y << 7;
    const uint32_t sb = smem_u32(sm);
    const int tid = threadIdx.x, lane = tid & 31, wid = tid >> 5;
    const int wm = wid & 3, wn = wid >> 2;
    if (tid < 128) toks[tid] = g_assign[e * CAP + min(m0 + tid, cnt - 1)];
    __syncthreads();

    const size_t eo = (size_t)e * Ff * Dd;
    const __half* G = g_WgT + eo;
    const __half* U = g_WuT + eo;

    float ag[2][8][4], au[2][8][4];
#pragma unroll
    for (int a = 0; a < 2; a++)
#pragma unroll
        for (int c = 0; c < 8; c++)
#pragma unroll
            for (int d = 0; d < 4; d++) { ag[a][c][d] = 0.f; au[a][c][d] = 0.f; }

    {
        uint32_t base = sb;
#pragma unroll
        for (int i = 0; i < 2; i++) {
            int idx = tid + (i << 8);
            int row = idx >> 2, ch8 = (idx & 3) << 3;
            uint32_t so = (uint32_t)(row * RS + ch8) * 2;
            CP16(base + so, g_xt16 + (size_t)toks[row] * Dd + ch8);
            CP16(base + OFG * 2 + so, G + (size_t)(n0 + row) * Dd + ch8);
            CP16(base + OFU * 2 + so, U + (size_t)(n0 + row) * Dd + ch8);
        }
        CPCOMMIT();
    }
    const int nb = Dd >> 5;
    for (int it = 0; it < nb; it++) {
        if (it + 1 < nb) {
            uint32_t base = sb + (uint32_t)((it + 1) & 1) * STEg * 2;
            int k0 = (it + 1) << 5;
#pragma unroll
            for (int i = 0; i < 2; i++) {
                int idx = tid + (i << 8);
                int row = idx >> 2, ch8 = (idx & 3) << 3;
                uint32_t so = (uint32_t)(row * RS + ch8) * 2;
                CP16(base + so, g_xt16 + (size_t)toks[row] * Dd + k0 + ch8);
                CP16(base + OFG * 2 + so, G + (size_t)(n0 + row) * Dd + k0 + ch8);
                CP16(base + OFU * 2 + so, U + (size_t)(n0 + row) * Dd + k0 + ch8);
            }
        }
        CPCOMMIT();
        CPWAIT1();
        __syncthreads();
        uint32_t base = sb + (uint32_t)(it & 1) * STEg * 2;
#pragma unroll
        for (int ks = 0; ks < 2; ks++) {
            uint32_t a[2][4];
#pragma unroll
            for (int mt = 0; mt < 2; mt++) {
                uint32_t ao = (uint32_t)((wm * 32 + mt * 16 + (lane & 15)) * RS +
                                         ks * 16 + (lane >> 4) * 8) * 2;
                ldm4(a[mt], base + ao);
            }
            uint32_t boff[4];
#pragma unroll
            for (int bt = 0; bt < 4; bt++)
                boff[bt] = (uint32_t)((wn * 64 + bt * 16 + ((lane >> 4) & 1) * 8 +
                                       (lane & 7)) * RS +
                                      ks * 16 + ((lane >> 3) & 1) * 8) * 2;
            {
                uint32_t bg[4][4];
#pragma unroll
                for (int bt = 0; bt < 4; bt++) ldm4(bg[bt], base + OFG * 2 + boff[bt]);
#pragma unroll
                for (int mt = 0; mt < 2; mt++)
#pragma unroll
                    for (int nt = 0; nt < 8; nt++)
                        mma_f16(ag[mt][nt], a[mt], &bg[nt >> 1][(nt & 1) * 2]);
            }
            {
                uint32_t bu[4][4];
#pragma unroll
                for (int bt = 0; bt < 4; bt++) ldm4(bu[bt], base + OFU * 2 + boff[bt]);
#pragma unroll
                for (int mt = 0; mt < 2; mt++)
#pragma unroll
                    for (int nt = 0; nt < 8; nt++)
                        mma_f16(au[mt][nt], a[mt], &bu[nt >> 1][(nt & 1) * 2]);
            }
        }
        __syncthreads();
    }
    const int lr = lane >> 2, lc2 = (lane & 3) * 2;
#pragma unroll
    for (int mt = 0; mt < 2; mt++)
#pragma unroll
        for (int nt = 0; nt < 8; nt++) {
            int r = m0 + wm * 32 + mt * 16 + lr;
            int col = n0 + wn * 64 + nt * 8 + lc2;
#pragma unroll
            for (int half = 0; half < 2; half++) {
                int rr = r + half * 8;
                if (rr < cnt) {
                    float gv0 = ag[mt][nt][half * 2], gv1 = ag[mt][nt][half * 2 + 1];
                    float uv0 = au[mt][nt][half * 2], uv1 = au[mt][nt][half * 2 + 1];
                    float v0 = gv0 / (1.f + __expf(-gv0)) * uv0;
                    float v1 = gv1 / (1.f + __expf(-gv1)) * uv1;
                    __half2 hp;
                    hp.x = __float2half_rn(v0);
                    hp.y = __float2half_rn(v1);
                    *(__half2*)(g_h16 + ((size_t)e * CAP + rr) * Ff + col) = hp;
                }
            }
        }
}

// ---------------- MoE down fp16 -> g_moeout fp32 (slot rows) ----------------
__global__ void __launch_bounds__(256) moe_down16() {
    extern __shared__ __half sm[];
    const int e = blockIdx.z;
    const int cnt = g_cnt[e];
    const int m0 = blockIdx.x << 7;
    if (m0 >= cnt) return;
    const int n0 = blockIdx.y << 7;
    const uint32_t sb = smem_u32(sm);
    const int tid = threadIdx.x, lane = tid & 31, wid = tid >> 5;
    const int wm = wid & 3, wn = wid >> 2;
    const int cm1 = cnt - 1;

    const __half* A = g_h16 + (size_t)e * CAP * Ff;
    const __half* B = g_WdT + (size_t)e * Dd * Ff;

    float acc[2][8][4];
#pragma unroll
    for (int a = 0; a < 2; a++)
#pragma unroll
        for (int c = 0; c < 8; c++)
#pragma unroll
            for (int d = 0; d < 4; d++) acc[a][c][d] = 0.f;

    {
        uint32_t base = sb;
#pragma unroll
        for (int i = 0; i < 2; i++) {
            int idx = tid + (i << 8);
            int row = idx >> 2, ch8 = (idx & 3) << 3;
            uint32_t so = (uint32_t)(row * RS + ch8) * 2;
            CP16(base + so, A + (size_t)min(m0 + row, cm1) * Ff + ch8);
            CP16(base + OFB * 2 + so, B + (size_t)(n0 + row) * Ff + ch8);
        }
        CPCOMMIT();
    }
    const int nb = Ff >> 5;
    for (int it = 0; it < nb; it++) {
        if (it + 1 < nb) {
            uint32_t base = sb + (uint32_t)((it + 1) & 1) * STEd * 2;
            int k0 = (it + 1) << 5;
#pragma unroll
            for (int i = 0; i < 2; i++) {
                int idx = tid + (i << 8);
                int row = idx >> 2, ch8 = (idx & 3) << 3;
                uint32_t so = (uint32_t)(row * RS + ch8) * 2;
                CP16(base + so, A + (size_t)min(m0 + row, cm1) * Ff + k0 + ch8);
                CP16(base + OFB * 2 + so, B + (size_t)(n0 + row) * Ff + k0 + ch8);
            }
        }
        CPCOMMIT();
        CPWAIT1();
        __syncthreads();
        uint32_t base = sb + (uint32_t)(it & 1) * STEd * 2;
#pragma unroll
        for (int ks = 0; ks < 2; ks++) {
            uint32_t a[2][4];
#pragma unroll
            for (int mt = 0; mt < 2; mt++) {
                uint32_t ao = (uint32_t)((wm * 32 + mt * 16 + (lane & 15)) * RS +
                                         ks * 16 + (lane >> 4) * 8) * 2;
                ldm4(a[mt], base + ao);
            }
            uint32_t bq[4][4];
#pragma unroll
            for (int bt = 0; bt < 4; bt++) {
                uint32_t bo = (uint32_t)((wn * 64 + bt * 16 + ((lane >> 4) & 1) * 8 +
                                          (lane & 7)) * RS +
                                         ks * 16 + ((lane >> 3) & 1) * 8) * 2;
                ldm4(bq[bt], base + OFB * 2 + bo);
            }
#pragma unroll
            for (int mt = 0; mt < 2; mt++)
#pragma unroll
                for (int nt = 0; nt < 8; nt++)
                    mma_f16(acc[mt][nt], a[mt], &bq[nt >> 1][(nt & 1) * 2]);
        }
        __syncthreads();
    }
    const int lr = lane >> 2, lc2 = (lane & 3) * 2;
#pragma unroll
    for (int mt = 0; mt < 2; mt++)
#pragma unroll
        for (int half = 0; half < 2; half++) {
            int r = m0 + wm * 32 + mt * 16 + lr + half * 8;
            if (r < cnt) {
                float* op = g_moeout + ((size_t)e * CAP + r) * Dd;
#pragma unroll
                for (int nt = 0; nt < 8; nt++) {
                    int col = n0 + wn * 64 + nt * 8 + lc2;
                    *(float2*)(op + col) = make_float2(acc[mt][nt][half * 2],
                                                       acc[mt][nt][half * 2 + 1]);
                }
            }
        }
}

// ---------------- final gather: out = hidden + w0*moe[slot0] + w1*moe[slot1] ----------------
__global__ void final_k(float* __restrict__ out) {
    const size_t i4 = ((size_t)blockIdx.x * 256 + threadIdx.x) * 4;
    const int t = (int)(i4 >> 10);
    const int c = (int)(i4 & 1023);
    const int s0 = g_slotid[t * 2 + 0], s1 = g_slotid[t * 2 + 1];
    const float w0 = g_topw[t * 2 + 0], w1 = g_topw[t * 2 + 1];
    float4 hv = *(const float4*)(g_hidden + i4);
    float4 m0 = *(const float4*)(g_moeout + (size_t)s0 * Dd + c);
    float4 m1 = *(const float4*)(g_moeout + (size_t)s1 * Dd + c);
    hv.x += w0 * m0.x + w1 * m1.x;
    hv.y += w0 * m0.y + w1 * m1.y;
    hv.z += w0 * m0.z + w1 * m1.z;
    hv.w += w0 * m0.w + w1 * m1.w;
    *(float4*)(out + i4) = hv;
}

// ---------------- launch ----------------
extern "C" void kernel_launch(void* const* d_in, const int* in_sizes, int n_in,
                              void* d_out, int out_size) {
    (void)in_sizes; (void)n_in;
    const float* hs    = (const float*)d_in[0];
    const float* ln1   = (const float*)d_in[1];
    const float* ln2   = (const float*)d_in[2];
    const float* Wq    = (const float*)d_in[3];
    const float* Wk    = (const float*)d_in[4];
    const float* Wv    = (const float*)d_in[5];
    const float* Wo    = (const float*)d_in[6];
    const float* qn    = (const float*)d_in[7];
    const float* kn    = (const float*)d_in[8];
    const float* gamma = (const float*)d_in[9];
    const float* gw    = (const float*)d_in[10];
    const float* Wg    = (const float*)d_in[11];
    const float* Wu    = (const float*)d_in[12];
    const float* Wd    = (const float*)d_in[13];
    float* out = (float*)d_out;

    float *p_q, *p_k, *p_tmp, *p_hidden, *p_xt;
    cudaGetSymbolAddress((void**)&p_q, g_q);
    cudaGetSymbolAddress((void**)&p_k, g_k);
    cudaGetSymbolAddress((void**)&p_tmp, g_tmp);
    cudaGetSymbolAddress((void**)&p_hidden, g_hidden);
    cudaGetSymbolAddress((void**)&p_xt, g_xt);
    float* p_v; cudaGetSymbolAddress((void**)&p_v, g_v);

    __half *wg16, *wu16, *wd16, *wq16, *wk16, *wv16, *wo16;
    __half *x16, *q16, *k16, *o16, *xt16;
    cudaGetSymbolAddress((void**)&wg16, g_WgT);
    cudaGetSymbolAddress((void**)&wu16, g_WuT);
    cudaGetSymbolAddress((void**)&wd16, g_WdT);
    cudaGetSymbolAddress((void**)&wq16, g_WqT);
    cudaGetSymbolAddress((void**)&wk16, g_WkT);
    cudaGetSymbolAddress((void**)&wv16, g_WvT);
    cudaGetSymbolAddress((void**)&wo16, g_WoT);
    cudaGetSymbolAddress((void**)&x16, g_x16);
    cudaGetSymbolAddress((void**)&q16, g_q16);
    cudaGetSymbolAddress((void**)&k16, g_k16);
    cudaGetSymbolAddress((void**)&o16, g_o16);
    cudaGetSymbolAddress((void**)&xt16, g_xt16);

    cudaFuncSetAttribute(hgemm16, cudaFuncAttributeMaxDynamicSharedMemorySize, SMEMd);
    cudaFuncSetAttribute(attn_scores16, cudaFuncAttributeMaxDynamicSharedMemorySize, SMEMd);
    cudaFuncSetAttribute(attn_av16, cudaFuncAttributeMaxDynamicSharedMemorySize, SMEMa);
    cudaFuncSetAttribute(moe_gu16, cudaFuncAttributeMaxDynamicSharedMemorySize, SMEMg);
    cudaFuncSetAttribute(moe_down16, cudaFuncAttributeMaxDynamicSharedMemorySize, SMEMd);

    dim3 tb32(32, 8);
    tconv_k<<<dim3(32, 32, 1), tb32>>>(Wq, wq16, Dd, Dd);
    tconv_k<<<dim3(32, 32, 1), tb32>>>(Wk, wk16, Dd, Dd);
    tconv_k<<<dim3(32, 32, 1), tb32>>>(Wv, wv16, Dd, Dd);
    tconv_k<<<dim3(32, 32, 1), tb32>>>(Wo, wo16, Dd, Dd);
    tconv_k<<<dim3(Ff / 32, Dd / 32, Ee), tb32>>>(Wg, wg16, Dd, Ff);
    tconv_k<<<dim3(Ff / 32, Dd / 32, Ee), tb32>>>(Wu, wu16, Dd, Ff);
    tconv_k<<<dim3(Dd / 32, Ff / 32, Ee), tb32>>>(Wd, wd16, Ff, Dd);

    // --- attention branch ---
    rmsnorm_h<<<Tt, 256>>>(hs, ln1, x16, nullptr);
    hgemm16<<<dim3(32, 8), 256, SMEMd>>>(x16, wq16, p_q, Dd, Dd);
    hgemm16<<<dim3(32, 8), 256, SMEMd>>>(x16, wk16, p_k, Dd, Dd);
    hgemm16<<<dim3(32, 8), 256, SMEMd>>>(x16, wv16, p_v, Dd, Dd);
    headnorm16_k<<<Tt * Hh / 8, 256>>>(p_q, qn, 0.125f, q16);
    headnorm16_k<<<Tt * Hh / 8, 256>>>(p_k, kn, 1.0f, k16);
    vT_k<<<dim3(32, 2, 64), tb32>>>();
    attn_scores16<<<dim3(8, 8, 64), 256, SMEMd>>>();
    softmax16_k<<<Bb * Hh * Ss, 256>>>();
    attn_av16<<<dim3(8, 1, 64), 256, SMEMa>>>();
    hgemm16<<<dim3(32, 8), 256, SMEMd>>>(o16, wo16, p_tmp, Dd, Dd);
    resid_gamma_k<<<Tt * Dd / 256, 256>>>(hs, gamma);

    // --- MoE branch ---
    rmsnorm_h<<<Tt, 256>>>(p_hidden, ln2, xt16, p_xt);
    int write_logits = (out_size >= Tt * Dd + Tt * Ee) ? 1 : 0;
    router_k<<<Tt, 256>>>(gw, out + (size_t)Tt * Dd, write_logits);
    zero_cnt_k<<<1, 32>>>();
    assign_k<<<Tt / 256, 256>>>();
    moe_gu16<<<dim3(CAP / 128, Ff / 128, Ee), 256, SMEMg>>>();
    moe_down16<<<dim3(CAP / 128, Dd / 128, Ee), 256, SMEMd>>>();
    final_k<<<Tt * Dd / 1024, 256>>>(out);
}

// round 5
// speedup vs baseline: 5.9360x; 1.2339x over previous
#include <cuda_runtime.h>
#include <cuda_fp16.h>
#include <math.h>
#include <stdint.h>

// ---------------- constants ----------------
#define Bb 4
#define Ss 1024
#define Tt 4096
#define Dd 1024
#define Hh 16
#define HDd 64
#define Ee 8
#define Ff 4096
#define CAP 4096
#define EPSf 1e-6f

#define RS  40             // A-tile smem row stride (halves)
#define RSB 136            // B-tile ([K][N]) smem row stride (halves)

// dense / down stage layout (halves): A[128][40] then B[32][136]
#define OFB  5120
#define STEd 9472
// gu stage: A then G then U
#define OFG  5120
#define OFU  9472
#define STEg 13824

#define SMEMd (2 * STEd * 2)
#define SMEMg (2 * STEg * 2)

// fmha smem (halves): Q[128][72], K0,V0,K1,V1 each [128][72]
#define FK0 9216
#define FV0 18432
#define FKV 18432          // stage stride
#define SMEMf (46080 * 2)

// ---------------- scratch ----------------
__device__ __align__(256) float g_hidden[(size_t)Tt * Dd];
__device__ __align__(256) float g_xt[(size_t)Tt * Dd];
__device__ __align__(256) float g_moeout[(size_t)Ee * CAP * Dd];
__device__ int   g_topidx[Tt * 2];
__device__ float g_topw[Tt * 2];
__device__ int   g_slotid[Tt * 2];
__device__ int   g_cnt[Ee];
__device__ int   g_assign[Ee * CAP];

__device__ __align__(256) __half g_x16[(size_t)Tt * Dd];
__device__ __align__(256) __half g_q16[(size_t)Tt * Dd];
__device__ __align__(256) __half g_k16[(size_t)Tt * Dd];
__device__ __align__(256) __half g_v16[(size_t)Tt * Dd];
__device__ __align__(256) __half g_o16[(size_t)Tt * Dd];
__device__ __align__(256) __half g_xt16[(size_t)Tt * Dd];
__device__ __align__(256) __half g_h16[(size_t)Ee * CAP * Ff];

// fp16 weights, ORIGINAL layout [K][N]
__device__ __align__(256) __half g_Wg16[(size_t)Ee * Dd * Ff];
__device__ __align__(256) __half g_Wu16[(size_t)Ee * Dd * Ff];
__device__ __align__(256) __half g_Wd16[(size_t)Ee * Ff * Dd];
__device__ __align__(256) __half g_Wq16[(size_t)Dd * Dd];
__device__ __align__(256) __half g_Wk16[(size_t)Dd * Dd];
__device__ __align__(256) __half g_Wv16[(size_t)Dd * Dd];
__device__ __align__(256) __half g_Wo16[(size_t)Dd * Dd];

// ---------------- helpers ----------------
__device__ __forceinline__ float warp_red_sum(float v) {
#pragma unroll
    for (int o = 16; o; o >>= 1) v += __shfl_xor_sync(0xffffffffu, v, o);
    return v;
}
__device__ __forceinline__ uint32_t smem_u32(const void* p) {
    uint32_t a;
    asm("{ .reg .u64 t; cvta.to.shared.u64 t, %1; cvt.u32.u64 %0, t; }" : "=r"(a) : "l"(p));
    return a;
}
#define CP16(sm, gp) \
    asm volatile("cp.async.ca.shared.global [%0], [%1], 16;" :: "r"(sm), "l"(gp))
#define CPCOMMIT() asm volatile("cp.async.commit_group;")
#define CPWAIT1() asm volatile("cp.async.wait_group 1;")

__device__ __forceinline__ void ldm4(uint32_t* r, uint32_t addr) {
    asm volatile("ldmatrix.sync.aligned.m8n8.x4.shared.b16 {%0,%1,%2,%3}, [%4];"
                 : "=r"(r[0]), "=r"(r[1]), "=r"(r[2]), "=r"(r[3]) : "r"(addr));
}
__device__ __forceinline__ void ldm4t(uint32_t* r, uint32_t addr) {
    asm volatile("ldmatrix.sync.aligned.m8n8.x4.trans.shared.b16 {%0,%1,%2,%3}, [%4];"
                 : "=r"(r[0]), "=r"(r[1]), "=r"(r[2]), "=r"(r[3]) : "r"(addr));
}
__device__ __forceinline__ void mma_f16(float* c, const uint32_t* a, const uint32_t* b) {
    asm volatile(
        "mma.sync.aligned.m16n8k16.row.col.f32.f16.f16.f32 "
        "{%0,%1,%2,%3},{%4,%5,%6,%7},{%8,%9},{%0,%1,%2,%3};"
        : "+f"(c[0]), "+f"(c[1]), "+f"(c[2]), "+f"(c[3])
        : "r"(a[0]), "r"(a[1]), "r"(a[2]), "r"(a[3]), "r"(b[0]), "r"(b[1]));
}
__device__ __forceinline__ uint32_t pack_h2(float a, float b) {
    __half2 h; h.x = __float2half_rn(a); h.y = __float2half_rn(b);
    return *(uint32_t*)&h;
}
// fast exp on FMA pipe (rel err ~4e-5), valid for x in [-60, 60]
__device__ __forceinline__ float fexp(float x) {
    x = fminf(fmaxf(x, -60.f), 60.f);
    float z = x * 1.442695041f;
    float j = z + 12582912.f;
    int i = __float_as_int(j) - 0x4b400000;
    float f = z - (j - 12582912.f);
    float p = fmaf(f, 0.009618129f, 0.055504110f);
    p = fmaf(f, p, 0.240226507f);
    p = fmaf(f, p, 0.693147181f);
    p = fmaf(f, p, 1.0f);
    return __int_as_float(__float_as_int(p) + (i << 23));
}
__device__ __forceinline__ float frcp(float d) {
    float r = __uint_as_float(0x7ef311c3u - __float_as_uint(d));
    r = r * (2.0f - d * r);
    r = r * (2.0f - d * r);
    r = r * (2.0f - d * r);
    return r;
}

// ---------------- streaming weight convert fp32 -> fp16 (same layout) ----------------
__global__ void wconv_k(const float* __restrict__ in, __half* __restrict__ o) {
    const size_t i = ((size_t)blockIdx.x * 256 + threadIdx.x) * 4;
    float4 v = *(const float4*)(in + i);
    uint2 p;
    p.x = pack_h2(v.x, v.y);
    p.y = pack_h2(v.z, v.w);
    *(uint2*)(o + i) = p;
}

// ---------------- RMSNorm -> fp16 (optionally fp32 too) ----------------
__global__ void rmsnorm_h(const float* __restrict__ in, const float* __restrict__ w,
                          __half* __restrict__ o16, float* __restrict__ of) {
    const int t = blockIdx.x;
    const float* x = in + (size_t)t * Dd;
    float ss = 0.f;
    for (int i = threadIdx.x; i < Dd; i += 256) { float v = x[i]; ss = fmaf(v, v, ss); }
    __shared__ float red[8];
    __shared__ float sres;
    float ws = warp_red_sum(ss);
    if ((threadIdx.x & 31) == 0) red[threadIdx.x >> 5] = ws;
    __syncthreads();
    if (threadIdx.x == 0) {
        float s = 0.f;
        for (int i = 0; i < 8; i++) s += red[i];
        sres = rsqrtf(s * (1.f / Dd) + EPSf);
    }
    __syncthreads();
    const float r = sres;
    for (int i = threadIdx.x; i < Dd; i += 256) {
        float v = x[i] * r * w[i];
        o16[(size_t)t * Dd + i] = __float2half_rn(v);
        if (of) of[(size_t)t * Dd + i] = v;
    }
}

// ---------------- per-head RMSNorm fp16 in-place ----------------
__global__ void headnorm_h(__half* __restrict__ qk, const float* __restrict__ w, float sc) {
    const int warp = (blockIdx.x << 3) + (threadIdx.x >> 5);
    const int lane = threadIdx.x & 31;
    __half* p = qk + (size_t)warp * HDd;
    float v0 = __half2float(p[lane]), v1 = __half2float(p[lane + 32]);
    float ss = warp_red_sum(fmaf(v0, v0, v1 * v1));
    float r = rsqrtf(ss * (1.f / HDd) + EPSf) * sc;
    p[lane] = __float2half_rn(v0 * r * w[lane]);
    p[lane + 32] = __float2half_rn(v1 * r * w[lane + 32]);
}

// ---------------- dense GEMM: A16[M,K] @ B16[K,N] -> fp16 / fp32 / resid+gamma ----------------
__global__ void __launch_bounds__(256) hgemm16(
    const __half* __restrict__ A, const __half* __restrict__ B,
    float* __restrict__ Cf, __half* __restrict__ C16,
    const float* __restrict__ resid, const float* __restrict__ gamma,
    int K, int N) {
    extern __shared__ __half sm[];
    const uint32_t sb = smem_u32(sm);
    const int tid = threadIdx.x, lane = tid & 31, wid = tid >> 5;
    const int m0 = blockIdx.x << 7, n0 = blockIdx.y << 7;
    const int wm = wid & 3, wn = wid >> 2;

    float acc[2][8][4];
#pragma unroll
    for (int a = 0; a < 2; a++)
#pragma unroll
        for (int b = 0; b < 8; b++)
#pragma unroll
            for (int c = 0; c < 4; c++) acc[a][b][c] = 0.f;

    {
        uint32_t base = sb;
#pragma unroll
        for (int i = 0; i < 2; i++) {
            int c = tid + (i << 8);
            int row = c >> 2, ch = (c & 3) << 3;
            CP16(base + (uint32_t)(row * RS + ch) * 2, A + (size_t)(m0 + row) * K + ch);
        }
#pragma unroll
        for (int i = 0; i < 2; i++) {
            int c = tid + (i << 8);
            int row = c >> 4, ch = (c & 15) << 3;
            CP16(base + (uint32_t)(OFB + row * RSB + ch) * 2, B + (size_t)row * N + n0 + ch);
        }
        CPCOMMIT();
    }
    const int nb = K >> 5;
    for (int it = 0; it < nb; it++) {
        if (it + 1 < nb) {
            uint32_t base = sb + (uint32_t)((it + 1) & 1) * STEd * 2;
            int k0 = (it + 1) << 5;
#pragma unroll
            for (int i = 0; i < 2; i++) {
                int c = tid + (i << 8);
                int row = c >> 2, ch = (c & 3) << 3;
                CP16(base + (uint32_t)(row * RS + ch) * 2, A + (size_t)(m0 + row) * K + k0 + ch);
            }
#pragma unroll
            for (int i = 0; i < 2; i++) {
                int c = tid + (i << 8);
                int row = c >> 4, ch = (c & 15) << 3;
                CP16(base + (uint32_t)(OFB + row * RSB + ch) * 2,
                     B + (size_t)(k0 + row) * N + n0 + ch);
            }
        }
        CPCOMMIT();
        CPWAIT1();
        __syncthreads();
        uint32_t base = sb + (uint32_t)(it & 1) * STEd * 2;
#pragma unroll
        for (int ks = 0; ks < 2; ks++) {
            uint32_t a[2][4];
#pragma unroll
            for (int mt = 0; mt < 2; mt++)
                ldm4(a[mt], base + (uint32_t)((wm * 32 + mt * 16 + (lane & 15)) * RS +
                                              ks * 16 + (lane >> 4) * 8) * 2);
            uint32_t bq[4][4];
#pragma unroll
            for (int bt = 0; bt < 4; bt++)
                ldm4t(bq[bt], base + (uint32_t)(OFB +
                                                (ks * 16 + (lane & 7) + ((lane >> 3) & 1) * 8) * RSB +
                                                wn * 64 + bt * 16 + (lane >> 4) * 8) * 2);
#pragma unroll
            for (int mt = 0; mt < 2; mt++)
#pragma unroll
                for (int nt = 0; nt < 8; nt++)
                    mma_f16(acc[mt][nt], a[mt], &bq[nt >> 1][(nt & 1) * 2]);
        }
        __syncthreads();
    }
    const int lr = lane >> 2, lc2 = (lane & 3) * 2;
#pragma unroll
    for (int mt = 0; mt < 2; mt++)
#pragma unroll
        for (int nt = 0; nt < 8; nt++) {
            int row = m0 + wm * 32 + mt * 16 + lr;
            int col = n0 + wn * 64 + nt * 8 + lc2;
            if (C16) {
                *(uint32_t*)(C16 + (size_t)row * N + col) = pack_h2(acc[mt][nt][0], acc[mt][nt][1]);
                *(uint32_t*)(C16 + (size_t)(row + 8) * N + col) = pack_h2(acc[mt][nt][2], acc[mt][nt][3]);
            } else if (resid) {
                float ga = gamma[col], gb = gamma[col + 1];
                float2 r0 = *(const float2*)(resid + (size_t)row * N + col);
                float2 r1 = *(const float2*)(resid + (size_t)(row + 8) * N + col);
                *(float2*)(Cf + (size_t)row * N + col) =
                    make_float2(fmaf(ga, acc[mt][nt][0], r0.x), fmaf(gb, acc[mt][nt][1], r0.y));
                *(float2*)(Cf + (size_t)(row + 8) * N + col) =
                    make_float2(fmaf(ga, acc[mt][nt][2], r1.x), fmaf(gb, acc[mt][nt][3], r1.y));
            } else {
                *(float2*)(Cf + (size_t)row * N + col) = make_float2(acc[mt][nt][0], acc[mt][nt][1]);
                *(float2*)(Cf + (size_t)(row + 8) * N + col) = make_float2(acc[mt][nt][2], acc[mt][nt][3]);
            }
        }
}

// ---------------- flash attention: per (b,h), 128 q rows per block ----------------
__global__ void __launch_bounds__(256) fmha_k() {
    extern __shared__ __half sm[];
    const uint32_t sb = smem_u32(sm);
    const int z = blockIdx.y, b = z >> 4, h = z & 15;
    const int m0 = blockIdx.x << 7;
    const int tid = threadIdx.x, lane = tid & 31, wm = tid >> 5;
    const __half* Q = g_q16 + (size_t)b * Ss * Dd + h * HDd;
    const __half* Kp = g_k16 + (size_t)b * Ss * Dd + h * HDd;
    const __half* Vp = g_v16 + (size_t)b * Ss * Dd + h * HDd;

    {
#pragma unroll
        for (int i = 0; i < 4; i++) {
            int c = tid + (i << 8);
            int row = c >> 3, ch = (c & 7) << 3;
            CP16(sb + (uint32_t)(row * 72 + ch) * 2, Q + (size_t)(m0 + row) * Dd + ch);
        }
#pragma unroll
        for (int i = 0; i < 4; i++) {
            int c = tid + (i << 8);
            int row = c >> 3, ch = (c & 7) << 3;
            CP16(sb + (uint32_t)(FK0 + row * 72 + ch) * 2, Kp + (size_t)row * Dd + ch);
            CP16(sb + (uint32_t)(FV0 + row * 72 + ch) * 2, Vp + (size_t)row * Dd + ch);
        }
        CPCOMMIT();
    }
    uint32_t aq[4][4];
    float o_acc[8][4];
#pragma unroll
    for (int i = 0; i < 8; i++)
#pragma unroll
        for (int j = 0; j < 4; j++) o_acc[i][j] = 0.f;
    float m_prev0 = -1e30f, m_prev1 = -1e30f, l0 = 0.f, l1 = 0.f;

    for (int it = 0; it < 8; it++) {
        if (it < 7) {
            uint32_t kb = sb + (uint32_t)(FK0 + ((it + 1) & 1) * FKV) * 2;
            uint32_t vb = sb + (uint32_t)(FV0 + ((it + 1) & 1) * FKV) * 2;
            int s0 = (it + 1) << 7;
#pragma unroll
            for (int i = 0; i < 4; i++) {
                int c = tid + (i << 8);
                int row = c >> 3, ch = (c & 7) << 3;
                CP16(kb + (uint32_t)(row * 72 + ch) * 2, Kp + (size_t)(s0 + row) * Dd + ch);
                CP16(vb + (uint32_t)(row * 72 + ch) * 2, Vp + (size_t)(s0 + row) * Dd + ch);
            }
        }
        CPCOMMIT();
        CPWAIT1();
        __syncthreads();
        if (it == 0) {
#pragma unroll
            for (int kb = 0; kb < 4; kb++)
                ldm4(aq[kb], sb + (uint32_t)((wm * 16 + (lane & 15)) * 72 +
                                             kb * 16 + (lane >> 4) * 8) * 2);
        }
        const uint32_t kbase = sb + (uint32_t)(FK0 + (it & 1) * FKV) * 2;
        const uint32_t vbase = sb + (uint32_t)(FV0 + (it & 1) * FKV) * 2;
        float s_acc[16][4];
#pragma unroll
        for (int i = 0; i < 16; i++)
#pragma unroll
            for (int j = 0; j < 4; j++) s_acc[i][j] = 0.f;
#pragma unroll
        for (int kb = 0; kb < 4; kb++)
#pragma unroll
            for (int nb2 = 0; nb2 < 8; nb2++) {
                uint32_t bk[4];
                ldm4(bk, kbase + (uint32_t)((nb2 * 16 + ((lane >> 4) & 1) * 8 + (lane & 7)) * 72 +
                                            kb * 16 + ((lane >> 3) & 1) * 8) * 2);
                mma_f16(s_acc[nb2 * 2], aq[kb], bk);
                mma_f16(s_acc[nb2 * 2 + 1], aq[kb], bk + 2);
            }
        // online softmax
        float mx0 = -1e30f, mx1 = -1e30f;
#pragma unroll
        for (int t = 0; t < 16; t++) {
            mx0 = fmaxf(mx0, fmaxf(s_acc[t][0], s_acc[t][1]));
            mx1 = fmaxf(mx1, fmaxf(s_acc[t][2], s_acc[t][3]));
        }
        mx0 = fmaxf(mx0, __shfl_xor_sync(0xffffffffu, mx0, 1));
        mx0 = fmaxf(mx0, __shfl_xor_sync(0xffffffffu, mx0, 2));
        mx1 = fmaxf(mx1, __shfl_xor_sync(0xffffffffu, mx1, 1));
        mx1 = fmaxf(mx1, __shfl_xor_sync(0xffffffffu, mx1, 2));
        float mn0 = fmaxf(m_prev0, mx0), mn1 = fmaxf(m_prev1, mx1);
        float sc0 = fexp(m_prev0 - mn0), sc1 = fexp(m_prev1 - mn1);
        m_prev0 = mn0; m_prev1 = mn1;
        float rs0 = 0.f, rs1 = 0.f;
#pragma unroll
        for (int t = 0; t < 16; t++) {
            s_acc[t][0] = fexp(s_acc[t][0] - mn0);
            s_acc[t][1] = fexp(s_acc[t][1] - mn0);
            s_acc[t][2] = fexp(s_acc[t][2] - mn1);
            s_acc[t][3] = fexp(s_acc[t][3] - mn1);
            rs0 += s_acc[t][0] + s_acc[t][1];
            rs1 += s_acc[t][2] + s_acc[t][3];
        }
        rs0 += __shfl_xor_sync(0xffffffffu, rs0, 1);
        rs0 += __shfl_xor_sync(0xffffffffu, rs0, 2);
        rs1 += __shfl_xor_sync(0xffffffffu, rs1, 1);
        rs1 += __shfl_xor_sync(0xffffffffu, rs1, 2);
        l0 = l0 * sc0 + rs0;
        l1 = l1 * sc1 + rs1;
#pragma unroll
        for (int ot = 0; ot < 8; ot++) {
            o_acc[ot][0] *= sc0; o_acc[ot][1] *= sc0;
            o_acc[ot][2] *= sc1; o_acc[ot][3] *= sc1;
        }
        // O += P @ V
#pragma unroll
        for (int pb = 0; pb < 8; pb++) {
            uint32_t ap[4];
            ap[0] = pack_h2(s_acc[2 * pb][0], s_acc[2 * pb][1]);
            ap[1] = pack_h2(s_acc[2 * pb][2], s_acc[2 * pb][3]);
            ap[2] = pack_h2(s_acc[2 * pb + 1][0], s_acc[2 * pb + 1][1]);
            ap[3] = pack_h2(s_acc[2 * pb + 1][2], s_acc[2 * pb + 1][3]);
#pragma unroll
            for (int nb2 = 0; nb2 < 4; nb2++) {
                uint32_t bv[4];
                ldm4t(bv, vbase + (uint32_t)((pb * 16 + (lane & 7) + ((lane >> 3) & 1) * 8) * 72 +
                                             nb2 * 16 + (lane >> 4) * 8) * 2);
                mma_f16(o_acc[nb2 * 2], ap, bv);
                mma_f16(o_acc[nb2 * 2 + 1], ap, bv + 2);
            }
        }
        __syncthreads();
    }
    const float inv0 = 1.f / l0, inv1 = 1.f / l1;
    __half* O = g_o16 + (size_t)b * Ss * Dd + h * HDd;
    const int r = m0 + wm * 16 + (lane >> 2), c2 = (lane & 3) * 2;
#pragma unroll
    for (int ot = 0; ot < 8; ot++) {
        int col = ot * 8 + c2;
        *(uint32_t*)(O + (size_t)r * Dd + col) =
            pack_h2(o_acc[ot][0] * inv0, o_acc[ot][1] * inv0);
        *(uint32_t*)(O + (size_t)(r + 8) * Dd + col) =
            pack_h2(o_acc[ot][2] * inv1, o_acc[ot][3] * inv1);
    }
}

// ---------------- router ----------------
__global__ void router_k(const float* __restrict__ Gw, float* __restrict__ logits_out,
                         int write_logits) {
    const int t = blockIdx.x;
    const int tid = threadIdx.x;
    const int w = tid >> 5, lane = tid & 31;
    const float* x = g_xt + (size_t)t * Dd;
    float s = 0.f;
    for (int d = lane; d < Dd; d += 32) s = fmaf(x[d], Gw[d * Ee + w], s);
    s = warp_red_sum(s);
    __shared__ float lg[Ee];
    if (lane == 0) lg[w] = s;
    __syncthreads();
    if (tid == 0) {
        float mx = lg[0];
#pragma unroll
        for (int e = 1; e < Ee; e++) mx = fmaxf(mx, lg[e]);
        float p[Ee];
        float sum = 0.f;
#pragma unroll
        for (int e = 0; e < Ee; e++) { p[e] = __expf(lg[e] - mx); sum += p[e]; }
        int i0 = 0;
#pragma unroll
        for (int e = 1; e < Ee; e++) if (p[e] > p[i0]) i0 = e;
        int i1 = (i0 == 0) ? 1 : 0;
#pragma unroll
        for (int e = 0; e < Ee; e++) if (e != i0 && p[e] > p[i1]) i1 = e;
        float v0 = p[i0] / sum, v1 = p[i1] / sum;
        float inv = 1.f / (v0 + v1);
        g_topidx[t * 2 + 0] = i0;
        g_topidx[t * 2 + 1] = i1;
        g_topw[t * 2 + 0] = v0 * inv;
        g_topw[t * 2 + 1] = v1 * inv;
    }
    if (write_logits && tid < Ee) logits_out[(size_t)t * Ee + tid] = lg[tid];
}

__global__ void zero_cnt_k() { if (threadIdx.x < Ee) g_cnt[threadIdx.x] = 0; }

__global__ void assign_k() {
    const int t = blockIdx.x * 256 + threadIdx.x;
    if (t >= Tt) return;
#pragma unroll
    for (int j = 0; j < 2; j++) {
        int e = g_topidx[t * 2 + j];
        int pos = atomicAdd(&g_cnt[e], 1);
        g_assign[e * CAP + pos] = t;
        g_slotid[t * 2 + j] = e * CAP + pos;
    }
}

// ---------------- MoE gate/up + SiLU -> fp16 h ----------------
__global__ void __launch_bounds__(256) moe_gu16() {
    extern __shared__ __half sm[];
    __shared__ int toks[128];
    const int e = blockIdx.z;
    const int cnt = g_cnt[e];
    const int m0 = blockIdx.x << 7;
    if (m0 >= cnt) return;
    const int n0 = blockIdx.y << 7;
    const uint32_t sb = smem_u32(sm);
    const int tid = threadIdx.x, lane = tid & 31, wid = tid >> 5;
    const int wm = wid & 3, wn = wid >> 2;
    if (tid < 128) toks[tid] = g_assign[e * CAP + min(m0 + tid, cnt - 1)];
    __syncthreads();

    const size_t eo = (size_t)e * Dd * Ff;
    const __half* G = g_Wg16 + eo;
    const __half* U = g_Wu16 + eo;

    float ag[2][8][4], au[2][8][4];
#pragma unroll
    for (int a = 0; a < 2; a++)
#pragma unroll
        for (int c = 0; c < 8; c++)
#pragma unroll
            for (int d = 0; d < 4; d++) { ag[a][c][d] = 0.f; au[a][c][d] = 0.f; }

    {
        uint32_t base = sb;
#pragma unroll
        for (int i = 0; i < 2; i++) {
            int c = tid + (i << 8);
            int row = c >> 2, ch = (c & 3) << 3;
            CP16(base + (uint32_t)(row * RS + ch) * 2, g_xt16 + (size_t)toks[row] * Dd + ch);
        }
#pragma unroll
        for (int i = 0; i < 2; i++) {
            int c = tid + (i << 8);
            int row = c >> 4, ch = (c & 15) << 3;
            CP16(base + (uint32_t)(OFG + row * RSB + ch) * 2, G + (size_t)row * Ff + n0 + ch);
            CP16(base + (uint32_t)(OFU + row * RSB + ch) * 2, U + (size_t)row * Ff + n0 + ch);
        }
        CPCOMMIT();
    }
    const int nb = Dd >> 5;
    for (int it = 0; it < nb; it++) {
        if (it + 1 < nb) {
            uint32_t base = sb + (uint32_t)((it + 1) & 1) * STEg * 2;
            int k0 = (it + 1) << 5;
#pragma unroll
            for (int i = 0; i < 2; i++) {
                int c = tid + (i << 8);
                int row = c >> 2, ch = (c & 3) << 3;
                CP16(base + (uint32_t)(row * RS + ch) * 2,
                     g_xt16 + (size_t)toks[row] * Dd + k0 + ch);
            }
#pragma unroll
            for (int i = 0; i < 2; i++) {
                int c = tid + (i << 8);
                int row = c >> 4, ch = (c & 15) << 3;
                CP16(base + (uint32_t)(OFG + row * RSB + ch) * 2,
                     G + (size_t)(k0 + row) * Ff + n0 + ch);
                CP16(base + (uint32_t)(OFU + row * RSB + ch) * 2,
                     U + (size_t)(k0 + row) * Ff + n0 + ch);
            }
        }
        CPCOMMIT();
        CPWAIT1();
        __syncthreads();
        uint32_t base = sb + (uint32_t)(it & 1) * STEg * 2;
#pragma unroll
        for (int ks = 0; ks < 2; ks++) {
            uint32_t a[2][4];
#pragma unroll
            for (int mt = 0; mt < 2; mt++)
                ldm4(a[mt], base + (uint32_t)((wm * 32 + mt * 16 + (lane & 15)) * RS +
                                              ks * 16 + (lane >> 4) * 8) * 2);
            uint32_t roff = (uint32_t)((ks * 16 + (lane & 7) + ((lane >> 3) & 1) * 8) * RSB) * 2;
            uint32_t coff[4];
#pragma unroll
            for (int bt = 0; bt < 4; bt++)
                coff[bt] = (uint32_t)(wn * 64 + bt * 16 + (lane >> 4) * 8) * 2;
            {
                uint32_t bg[4][4];
#pragma unroll
                for (int bt = 0; bt < 4; bt++)
                    ldm4t(bg[bt], base + OFG * 2 + roff + coff[bt]);
#pragma unroll
                for (int mt = 0; mt < 2; mt++)
#pragma unroll
                    for (int nt = 0; nt < 8; nt++)
                        mma_f16(ag[mt][nt], a[mt], &bg[nt >> 1][(nt & 1) * 2]);
            }
            {
                uint32_t bu[4][4];
#pragma unroll
                for (int bt = 0; bt < 4; bt++)
                    ldm4t(bu[bt], base + OFU * 2 + roff + coff[bt]);
#pragma unroll
                for (int mt = 0; mt < 2; mt++)
#pragma unroll
                    for (int nt = 0; nt < 8; nt++)
                        mma_f16(au[mt][nt], a[mt], &bu[nt >> 1][(nt & 1) * 2]);
            }
        }
        __syncthreads();
    }
    const int lr = lane >> 2, lc2 = (lane & 3) * 2;
#pragma unroll
    for (int mt = 0; mt < 2; mt++)
#pragma unroll
        for (int nt = 0; nt < 8; nt++) {
            int r = m0 + wm * 32 + mt * 16 + lr;
            int col = n0 + wn * 64 + nt * 8 + lc2;
#pragma unroll
            for (int half = 0; half < 2; half++) {
                int rr = r + half * 8;
                if (rr < cnt) {
                    float gv0 = ag[mt][nt][half * 2], gv1 = ag[mt][nt][half * 2 + 1];
                    float uv0 = au[mt][nt][half * 2], uv1 = au[mt][nt][half * 2 + 1];
                    float v0 = gv0 * frcp(1.f + fexp(-gv0)) * uv0;
                    float v1 = gv1 * frcp(1.f + fexp(-gv1)) * uv1;
                    *(uint32_t*)(g_h16 + ((size_t)e * CAP + rr) * Ff + col) = pack_h2(v0, v1);
                }
            }
        }
}

// ---------------- MoE down -> g_moeout fp32 (slot rows) ----------------
__global__ void __launch_bounds__(256) moe_down16() {
    extern __shared__ __half sm[];
    const int e = blockIdx.z;
    const int cnt = g_cnt[e];
    const int m0 = blockIdx.x << 7;
    if (m0 >= cnt) return;
    const int n0 = blockIdx.y << 7;
    const uint32_t sb = smem_u32(sm);
    const int tid = threadIdx.x, lane = tid & 31, wid = tid >> 5;
    const int wm = wid & 3, wn = wid >> 2;
    const int cm1 = cnt - 1;

    const __half* A = g_h16 + (size_t)e * CAP * Ff;
    const __half* B = g_Wd16 + (size_t)e * Ff * Dd;

    float acc[2][8][4];
#pragma unroll
    for (int a = 0; a < 2; a++)
#pragma unroll
        for (int c = 0; c < 8; c++)
#pragma unroll
            for (int d = 0; d < 4; d++) acc[a][c][d] = 0.f;

    {
        uint32_t base = sb;
#pragma unroll
        for (int i = 0; i < 2; i++) {
            int c = tid + (i << 8);
            int row = c >> 2, ch = (c & 3) << 3;
            CP16(base + (uint32_t)(row * RS + ch) * 2, A + (size_t)min(m0 + row, cm1) * Ff + ch);
        }
#pragma unroll
        for (int i = 0; i < 2; i++) {
            int c = tid + (i << 8);
            int row = c >> 4, ch = (c & 15) << 3;
            CP16(base + (uint32_t)(OFB + row * RSB + ch) * 2, B + (size_t)row * Dd + n0 + ch);
        }
        CPCOMMIT();
    }
    const int nb = Ff >> 5;
    for (int it = 0; it < nb; it++) {
        if (it + 1 < nb) {
            uint32_t base = sb + (uint32_t)((it + 1) & 1) * STEd * 2;
            int k0 = (it + 1) << 5;
#pragma unroll
            for (int i = 0; i < 2; i++) {
                int c = tid + (i << 8);
                int row = c >> 2, ch = (c & 3) << 3;
                CP16(base + (uint32_t)(row * RS + ch) * 2,
                     A + (size_t)min(m0 + row, cm1) * Ff + k0 + ch);
            }
#pragma unroll
            for (int i = 0; i < 2; i++) {
                int c = tid + (i << 8);
                int row = c >> 4, ch = (c & 15) << 3;
                CP16(base + (uint32_t)(OFB + row * RSB + ch) * 2,
                     B + (size_t)(k0 + row) * Dd + n0 + ch);
            }
        }
        CPCOMMIT();
        CPWAIT1();
        __syncthreads();
        uint32_t base = sb + (uint32_t)(it & 1) * STEd * 2;
#pragma unroll
        for (int ks = 0; ks < 2; ks++) {
            uint32_t a[2][4];
#pragma unroll
            for (int mt = 0; mt < 2; mt++)
                ldm4(a[mt], base + (uint32_t)((wm * 32 + mt * 16 + (lane & 15)) * RS +
                                              ks * 16 + (lane >> 4) * 8) * 2);
            uint32_t bq[4][4];
#pragma unroll
            for (int bt = 0; bt < 4; bt++)
                ldm4t(bq[bt], base + (uint32_t)(OFB +
                                                (ks * 16 + (lane & 7) + ((lane >> 3) & 1) * 8) * RSB +
                                                wn * 64 + bt * 16 + (lane >> 4) * 8) * 2);
#pragma unroll
            for (int mt = 0; mt < 2; mt++)
#pragma unroll
                for (int nt = 0; nt < 8; nt++)
                    mma_f16(acc[mt][nt], a[mt], &bq[nt >> 1][(nt & 1) * 2]);
        }
        __syncthreads();
    }
    const int lr = lane >> 2, lc2 = (lane & 3) * 2;
#pragma unroll
    for (int mt = 0; mt < 2; mt++)
#pragma unroll
        for (int half = 0; half < 2; half++) {
            int r = m0 + wm * 32 + mt * 16 + lr + half * 8;
            if (r < cnt) {
                float* op = g_moeout + ((size_t)e * CAP + r) * Dd;
#pragma unroll
                for (int nt = 0; nt < 8; nt++) {
                    int col = n0 + wn * 64 + nt * 8 + lc2;
                    *(float2*)(op + col) = make_float2(acc[mt][nt][half * 2],
                                                       acc[mt][nt][half * 2 + 1]);
                }
            }
        }
}

// ---------------- final gather ----------------
__global__ void final_k(float* __restrict__ out) {
    const size_t i4 = ((size_t)blockIdx.x * 256 + threadIdx.x) * 4;
    const int t = (int)(i4 >> 10);
    const int c = (int)(i4 & 1023);
    const int s0 = g_slotid[t * 2 + 0], s1 = g_slotid[t * 2 + 1];
    const float w0 = g_topw[t * 2 + 0], w1 = g_topw[t * 2 + 1];
    float4 hv = *(const float4*)(g_hidden + i4);
    float4 m0 = *(const float4*)(g_moeout + (size_t)s0 * Dd + c);
    float4 m1 = *(const float4*)(g_moeout + (size_t)s1 * Dd + c);
    hv.x += w0 * m0.x + w1 * m1.x;
    hv.y += w0 * m0.y + w1 * m1.y;
    hv.z += w0 * m0.z + w1 * m1.z;
    hv.w += w0 * m0.w + w1 * m1.w;
    *(float4*)(out + i4) = hv;
}

// ---------------- launch ----------------
extern "C" void kernel_launch(void* const* d_in, const int* in_sizes, int n_in,
                              void* d_out, int out_size) {
    (void)in_sizes; (void)n_in;
    const float* hs    = (const float*)d_in[0];
    const float* ln1   = (const float*)d_in[1];
    const float* ln2   = (const float*)d_in[2];
    const float* Wq    = (const float*)d_in[3];
    const float* Wk    = (const float*)d_in[4];
    const float* Wv    = (const float*)d_in[5];
    const float* Wo    = (const float*)d_in[6];
    const float* qn    = (const float*)d_in[7];
    const float* kn    = (const float*)d_in[8];
    const float* gamma = (const float*)d_in[9];
    const float* gw    = (const float*)d_in[10];
    const float* Wg    = (const float*)d_in[11];
    const float* Wu    = (const float*)d_in[12];
    const float* Wd    = (const float*)d_in[13];
    float* out = (float*)d_out;

    float *p_hidden, *p_xt;
    cudaGetSymbolAddress((void**)&p_hidden, g_hidden);
    cudaGetSymbolAddress((void**)&p_xt, g_xt);

    __half *wq16, *wk16, *wv16, *wo16, *wg16, *wu16, *wd16;
    __half *x16, *q16, *k16, *v16, *o16, *xt16;
    cudaGetSymbolAddress((void**)&wq16, g_Wq16);
    cudaGetSymbolAddress((void**)&wk16, g_Wk16);
    cudaGetSymbolAddress((void**)&wv16, g_Wv16);
    cudaGetSymbolAddress((void**)&wo16, g_Wo16);
    cudaGetSymbolAddress((void**)&wg16, g_Wg16);
    cudaGetSymbolAddress((void**)&wu16, g_Wu16);
    cudaGetSymbolAddress((void**)&wd16, g_Wd16);
    cudaGetSymbolAddress((void**)&x16, g_x16);
    cudaGetSymbolAddress((void**)&q16, g_q16);
    cudaGetSymbolAddress((void**)&k16, g_k16);
    cudaGetSymbolAddress((void**)&v16, g_v16);
    cudaGetSymbolAddress((void**)&o16, g_o16);
    cudaGetSymbolAddress((void**)&xt16, g_xt16);

    cudaFuncSetAttribute(hgemm16, cudaFuncAttributeMaxDynamicSharedMemorySize, SMEMd);
    cudaFuncSetAttribute(moe_down16, cudaFuncAttributeMaxDynamicSharedMemorySize, SMEMd);
    cudaFuncSetAttribute(moe_gu16, cudaFuncAttributeMaxDynamicSharedMemorySize, SMEMg);
    cudaFuncSetAttribute(fmha_k, cudaFuncAttributeMaxDynamicSharedMemorySize, SMEMf);

    // weight converts (streaming, same layout)
    wconv_k<<<Dd * Dd / 1024, 256>>>(Wq, wq16);
    wconv_k<<<Dd * Dd / 1024, 256>>>(Wk, wk16);
    wconv_k<<<Dd * Dd / 1024, 256>>>(Wv, wv16);
    wconv_k<<<Dd * Dd / 1024, 256>>>(Wo, wo16);
    wconv_k<<<(int)((size_t)Ee * Dd * Ff / 1024), 256>>>(Wg, wg16);
    wconv_k<<<(int)((size_t)Ee * Dd * Ff / 1024), 256>>>(Wu, wu16);
    wconv_k<<<(int)((size_t)Ee * Ff * Dd / 1024), 256>>>(Wd, wd16);

    // --- attention branch ---
    rmsnorm_h<<<Tt, 256>>>(hs, ln1, x16, nullptr);
    hgemm16<<<dim3(32, 8), 256, SMEMd>>>(x16, wq16, nullptr, q16, nullptr, nullptr, Dd, Dd);
    hgemm16<<<dim3(32, 8), 256, SMEMd>>>(x16, wk16, nullptr, k16, nullptr, nullptr, Dd, Dd);
    hgemm16<<<dim3(32, 8), 256, SMEMd>>>(x16, wv16, nullptr, v16, nullptr, nullptr, Dd, Dd);
    headnorm_h<<<Tt * Hh / 8, 256>>>(q16, qn, 0.125f);
    headnorm_h<<<Tt * Hh / 8, 256>>>(k16, kn, 1.0f);
    fmha_k<<<dim3(8, 64), 256, SMEMf>>>();
    hgemm16<<<dim3(32, 8), 256, SMEMd>>>(o16, wo16, p_hidden, nullptr, hs, gamma, Dd, Dd);

    // --- MoE branch ---
    rmsnorm_h<<<Tt, 256>>>(p_hidden, ln2, xt16, p_xt);
    int write_logits = (out_size >= Tt * Dd + Tt * Ee) ? 1 : 0;
    router_k<<<Tt, 256>>>(gw, out + (size_t)Tt * Dd, write_logits);
    zero_cnt_k<<<1, 32>>>();
    assign_k<<<Tt / 256, 256>>>();
    moe_gu16<<<dim3(CAP / 128, Ff / 128, Ee), 256, SMEMg>>>();
    moe_down16<<<dim3(CAP / 128, Dd / 128, Ee), 256, SMEMd>>>();
    final_k<<<Tt * Dd / 1024, 256>>>(out);
}

// round 6
// speedup vs baseline: 6.3890x; 1.0763x over previous
#include <cuda_runtime.h>
#include <cuda_fp16.h>
#include <math.h>
#include <stdint.h>

// ---------------- constants ----------------
#define Bb 4
#define Ss 1024
#define Tt 4096
#define Dd 1024
#define Hh 16
#define HDd 64
#define Ee 8
#define Ff 4096
#define CAP 4096
#define EPSf 1e-6f

#define RS  72             // A-tile smem row stride (halves), k64
#define RSB 136            // B-tile ([K][N]) smem row stride (halves)

// k64 stage layouts (halves)
#define OFB  9216          // dense/down: A[128][72] then B[64][136]
#define STEd 17920
#define OFG  9216          // gu: A[128][72], G[64][136], U[64][136]
#define OFU  17920
#define STEg 26624

#define SMEMd (2 * STEd * 2)   // 71680 B
#define SMEMg (2 * STEg * 2)   // 106496 B

// fmha smem (halves): Q[128][72], K0,V0,K1,V1 each [128][72]
#define FK0 9216
#define FV0 18432
#define FKV 18432
#define SMEMf (46080 * 2)

// ---------------- scratch ----------------
__device__ __align__(256) float g_hidden[(size_t)Tt * Dd];
__device__ __align__(256) float g_xt[(size_t)Tt * Dd];
__device__ __align__(256) float g_moeout[(size_t)Ee * CAP * Dd];
__device__ int   g_topidx[Tt * 2];
__device__ float g_topw[Tt * 2];
__device__ int   g_slotid[Tt * 2];
__device__ int   g_cnt[Ee];
__device__ int   g_assign[Ee * CAP];

__device__ __align__(256) __half g_x16[(size_t)Tt * Dd];
__device__ __align__(256) __half g_q16[(size_t)Tt * Dd];
__device__ __align__(256) __half g_k16[(size_t)Tt * Dd];
__device__ __align__(256) __half g_v16[(size_t)Tt * Dd];
__device__ __align__(256) __half g_o16[(size_t)Tt * Dd];
__device__ __align__(256) __half g_xt16[(size_t)Tt * Dd];
__device__ __align__(256) __half g_h16[(size_t)Ee * CAP * Ff];

// fp16 weights, ORIGINAL layout [K][N]
__device__ __align__(256) __half g_Wg16[(size_t)Ee * Dd * Ff];
__device__ __align__(256) __half g_Wu16[(size_t)Ee * Dd * Ff];
__device__ __align__(256) __half g_Wd16[(size_t)Ee * Ff * Dd];
__device__ __align__(256) __half g_Wq16[(size_t)Dd * Dd];
__device__ __align__(256) __half g_Wk16[(size_t)Dd * Dd];
__device__ __align__(256) __half g_Wv16[(size_t)Dd * Dd];
__device__ __align__(256) __half g_Wo16[(size_t)Dd * Dd];

// ---------------- helpers ----------------
__device__ __forceinline__ float warp_red_sum(float v) {
#pragma unroll
    for (int o = 16; o; o >>= 1) v += __shfl_xor_sync(0xffffffffu, v, o);
    return v;
}
__device__ __forceinline__ uint32_t smem_u32(const void* p) {
    uint32_t a;
    asm("{ .reg .u64 t; cvta.to.shared.u64 t, %1; cvt.u32.u64 %0, t; }" : "=r"(a) : "l"(p));
    return a;
}
#define CP16(sm, gp) \
    asm volatile("cp.async.ca.shared.global [%0], [%1], 16;" :: "r"(sm), "l"(gp))
#define CPCOMMIT() asm volatile("cp.async.commit_group;")
#define CPWAIT1() asm volatile("cp.async.wait_group 1;")

__device__ __forceinline__ void ldm4(uint32_t* r, uint32_t addr) {
    asm volatile("ldmatrix.sync.aligned.m8n8.x4.shared.b16 {%0,%1,%2,%3}, [%4];"
                 : "=r"(r[0]), "=r"(r[1]), "=r"(r[2]), "=r"(r[3]) : "r"(addr));
}
__device__ __forceinline__ void ldm4t(uint32_t* r, uint32_t addr) {
    asm volatile("ldmatrix.sync.aligned.m8n8.x4.trans.shared.b16 {%0,%1,%2,%3}, [%4];"
                 : "=r"(r[0]), "=r"(r[1]), "=r"(r[2]), "=r"(r[3]) : "r"(addr));
}
__device__ __forceinline__ void mma_f16(float* c, const uint32_t* a, const uint32_t* b) {
    asm volatile(
        "mma.sync.aligned.m16n8k16.row.col.f32.f16.f16.f32 "
        "{%0,%1,%2,%3},{%4,%5,%6,%7},{%8,%9},{%0,%1,%2,%3};"
        : "+f"(c[0]), "+f"(c[1]), "+f"(c[2]), "+f"(c[3])
        : "r"(a[0]), "r"(a[1]), "r"(a[2]), "r"(a[3]), "r"(b[0]), "r"(b[1]));
}
__device__ __forceinline__ uint32_t pack_h2(float a, float b) {
    __half2 h; h.x = __float2half_rn(a); h.y = __float2half_rn(b);
    return *(uint32_t*)&h;
}
// fast exp on FMA pipe (rel err ~4e-5)
__device__ __forceinline__ float fexp(float x) {
    x = fminf(fmaxf(x, -60.f), 60.f);
    float z = x * 1.442695041f;
    float j = z + 12582912.f;
    int i = __float_as_int(j) - 0x4b400000;
    float f = z - (j - 12582912.f);
    float p = fmaf(f, 0.009618129f, 0.055504110f);
    p = fmaf(f, p, 0.240226507f);
    p = fmaf(f, p, 0.693147181f);
    p = fmaf(f, p, 1.0f);
    return __int_as_float(__float_as_int(p) + (i << 23));
}
__device__ __forceinline__ float frcp(float d) {
    float r = __uint_as_float(0x7ef311c3u - __float_as_uint(d));
    r = r * (2.0f - d * r);
    r = r * (2.0f - d * r);
    r = r * (2.0f - d * r);
    return r;
}

// ---------------- streaming weight convert fp32 -> fp16 (8 elems/thread) ----------------
__global__ void wconv_k(const float* __restrict__ in, __half* __restrict__ o) {
    const size_t i = ((size_t)blockIdx.x * 256 + threadIdx.x) * 8;
    float4 a = *(const float4*)(in + i);
    float4 b = *(const float4*)(in + i + 4);
    uint4 p;
    p.x = pack_h2(a.x, a.y);
    p.y = pack_h2(a.z, a.w);
    p.z = pack_h2(b.x, b.y);
    p.w = pack_h2(b.z, b.w);
    *(uint4*)(o + i) = p;
}

// ---------------- RMSNorm -> fp16 (optionally fp32 too) ----------------
__global__ void rmsnorm_h(const float* __restrict__ in, const float* __restrict__ w,
                          __half* __restrict__ o16, float* __restrict__ of) {
    const int t = blockIdx.x;
    const float* x = in + (size_t)t * Dd;
    float ss = 0.f;
    for (int i = threadIdx.x; i < Dd; i += 256) { float v = x[i]; ss = fmaf(v, v, ss); }
    __shared__ float red[8];
    __shared__ float sres;
    float ws = warp_red_sum(ss);
    if ((threadIdx.x & 31) == 0) red[threadIdx.x >> 5] = ws;
    __syncthreads();
    if (threadIdx.x == 0) {
        float s = 0.f;
        for (int i = 0; i < 8; i++) s += red[i];
        sres = rsqrtf(s * (1.f / Dd) + EPSf);
    }
    __syncthreads();
    const float r = sres;
    for (int i = threadIdx.x; i < Dd; i += 256) {
        float v = x[i] * r * w[i];
        o16[(size_t)t * Dd + i] = __float2half_rn(v);
        if (of) of[(size_t)t * Dd + i] = v;
    }
}

// ---------------- per-head RMSNorm fp16 in-place: y=0 -> q (scaled), y=1 -> k ----------------
__global__ void headnorm_h(__half* __restrict__ q16, __half* __restrict__ k16,
                           const float* __restrict__ qn, const float* __restrict__ kn) {
    const int warp = (blockIdx.x << 3) + (threadIdx.x >> 5);
    const int lane = threadIdx.x & 31;
    __half* p = (blockIdx.y ? k16 : q16) + (size_t)warp * HDd;
    const float* w = blockIdx.y ? kn : qn;
    const float sc = blockIdx.y ? 1.0f : 0.125f;
    float v0 = __half2float(p[lane]), v1 = __half2float(p[lane + 32]);
    float ss = warp_red_sum(fmaf(v0, v0, v1 * v1));
    float r = rsqrtf(ss * (1.f / HDd) + EPSf) * sc;
    p[lane] = __float2half_rn(v0 * r * w[lane]);
    p[lane + 32] = __float2half_rn(v1 * r * w[lane + 32]);
}

// ---------------- dense GEMM k64: A16[M,K] @ B16[K,N] -> fp16 / fp32 / resid+gamma ----------------
__global__ void __launch_bounds__(256, 2) hgemm16(
    const __half* __restrict__ A, const __half* __restrict__ B,
    float* __restrict__ Cf, __half* __restrict__ C16,
    const float* __restrict__ resid, const float* __restrict__ gamma,
    int K, int N) {
    extern __shared__ __half sm[];
    const uint32_t sb = smem_u32(sm);
    const int tid = threadIdx.x, lane = tid & 31, wid = tid >> 5;
    const int m0 = blockIdx.x << 7, n0 = blockIdx.y << 7;
    const int wm = wid & 3, wn = wid >> 2;

    float acc[2][8][4];
#pragma unroll
    for (int a = 0; a < 2; a++)
#pragma unroll
        for (int b = 0; b < 8; b++)
#pragma unroll
            for (int c = 0; c < 4; c++) acc[a][b][c] = 0.f;

    const int ra = tid >> 3, ca = (tid & 7) << 3;     // A: 128 rows x 64
    const int rb = tid >> 4, cb = (tid & 15) << 3;    // B: 64 rows x 128
    {
        uint32_t base = sb;
#pragma unroll
        for (int i = 0; i < 4; i++)
            CP16(base + (uint32_t)((ra + i * 32) * RS + ca) * 2,
                 A + (size_t)(m0 + ra + i * 32) * K + ca);
#pragma unroll
        for (int i = 0; i < 4; i++)
            CP16(base + (uint32_t)(OFB + (rb + i * 16) * RSB + cb) * 2,
                 B + (size_t)(rb + i * 16) * N + n0 + cb);
        CPCOMMIT();
    }
    const int nb = K >> 6;
    for (int it = 0; it < nb; it++) {
        if (it + 1 < nb) {
            uint32_t base = sb + (uint32_t)((it + 1) & 1) * STEd * 2;
            int k0 = (it + 1) << 6;
#pragma unroll
            for (int i = 0; i < 4; i++)
                CP16(base + (uint32_t)((ra + i * 32) * RS + ca) * 2,
                     A + (size_t)(m0 + ra + i * 32) * K + k0 + ca);
#pragma unroll
            for (int i = 0; i < 4; i++)
                CP16(base + (uint32_t)(OFB + (rb + i * 16) * RSB + cb) * 2,
                     B + (size_t)(k0 + rb + i * 16) * N + n0 + cb);
        }
        CPCOMMIT();
        CPWAIT1();
        __syncthreads();
        uint32_t base = sb + (uint32_t)(it & 1) * STEd * 2;
#pragma unroll
        for (int ks = 0; ks < 4; ks++) {
            uint32_t a[2][4];
#pragma unroll
            for (int mt = 0; mt < 2; mt++)
                ldm4(a[mt], base + (uint32_t)((wm * 32 + mt * 16 + (lane & 15)) * RS +
                                              ks * 16 + (lane >> 4) * 8) * 2);
            uint32_t bq[4][4];
#pragma unroll
            for (int bt = 0; bt < 4; bt++)
                ldm4t(bq[bt], base + (uint32_t)(OFB +
                                                (ks * 16 + (lane & 7) + ((lane >> 3) & 1) * 8) * RSB +
                                                wn * 64 + bt * 16 + (lane >> 4) * 8) * 2);
#pragma unroll
            for (int mt = 0; mt < 2; mt++)
#pragma unroll
                for (int nt = 0; nt < 8; nt++)
                    mma_f16(acc[mt][nt], a[mt], &bq[nt >> 1][(nt & 1) * 2]);
        }
        __syncthreads();
    }
    const int lr = lane >> 2, lc2 = (lane & 3) * 2;
#pragma unroll
    for (int mt = 0; mt < 2; mt++)
#pragma unroll
        for (int nt = 0; nt < 8; nt++) {
            int row = m0 + wm * 32 + mt * 16 + lr;
            int col = n0 + wn * 64 + nt * 8 + lc2;
            if (C16) {
                *(uint32_t*)(C16 + (size_t)row * N + col) = pack_h2(acc[mt][nt][0], acc[mt][nt][1]);
                *(uint32_t*)(C16 + (size_t)(row + 8) * N + col) = pack_h2(acc[mt][nt][2], acc[mt][nt][3]);
            } else if (resid) {
                float ga = gamma[col], gb = gamma[col + 1];
                float2 r0 = *(const float2*)(resid + (size_t)row * N + col);
                float2 r1 = *(const float2*)(resid + (size_t)(row + 8) * N + col);
                *(float2*)(Cf + (size_t)row * N + col) =
                    make_float2(fmaf(ga, acc[mt][nt][0], r0.x), fmaf(gb, acc[mt][nt][1], r0.y));
                *(float2*)(Cf + (size_t)(row + 8) * N + col) =
                    make_float2(fmaf(ga, acc[mt][nt][2], r1.x), fmaf(gb, acc[mt][nt][3], r1.y));
            } else {
                *(float2*)(Cf + (size_t)row * N + col) = make_float2(acc[mt][nt][0], acc[mt][nt][1]);
                *(float2*)(Cf + (size_t)(row + 8) * N + col) = make_float2(acc[mt][nt][2], acc[mt][nt][3]);
            }
        }
}

// ---------------- flash attention ----------------
__global__ void __launch_bounds__(256) fmha_k() {
    extern __shared__ __half sm[];
    const uint32_t sb = smem_u32(sm);
    const int z = blockIdx.y, b = z >> 4, h = z & 15;
    const int m0 = blockIdx.x << 7;
    const int tid = threadIdx.x, lane = tid & 31, wm = tid >> 5;
    const __half* Q = g_q16 + (size_t)b * Ss * Dd + h * HDd;
    const __half* Kp = g_k16 + (size_t)b * Ss * Dd + h * HDd;
    const __half* Vp = g_v16 + (size_t)b * Ss * Dd + h * HDd;

    {
#pragma unroll
        for (int i = 0; i < 4; i++) {
            int c = tid + (i << 8);
            int row = c >> 3, ch = (c & 7) << 3;
            CP16(sb + (uint32_t)(row * 72 + ch) * 2, Q + (size_t)(m0 + row) * Dd + ch);
        }
#pragma unroll
        for (int i = 0; i < 4; i++) {
            int c = tid + (i << 8);
            int row = c >> 3, ch = (c & 7) << 3;
            CP16(sb + (uint32_t)(FK0 + row * 72 + ch) * 2, Kp + (size_t)row * Dd + ch);
            CP16(sb + (uint32_t)(FV0 + row * 72 + ch) * 2, Vp + (size_t)row * Dd + ch);
        }
        CPCOMMIT();
    }
    uint32_t aq[4][4];
    float o_acc[8][4];
#pragma unroll
    for (int i = 0; i < 8; i++)
#pragma unroll
        for (int j = 0; j < 4; j++) o_acc[i][j] = 0.f;
    float m_prev0 = -1e30f, m_prev1 = -1e30f, l0 = 0.f, l1 = 0.f;

    for (int it = 0; it < 8; it++) {
        if (it < 7) {
            uint32_t kb = sb + (uint32_t)(FK0 + ((it + 1) & 1) * FKV) * 2;
            uint32_t vb = sb + (uint32_t)(FV0 + ((it + 1) & 1) * FKV) * 2;
            int s0 = (it + 1) << 7;
#pragma unroll
            for (int i = 0; i < 4; i++) {
                int c = tid + (i << 8);
                int row = c >> 3, ch = (c & 7) << 3;
                CP16(kb + (uint32_t)(row * 72 + ch) * 2, Kp + (size_t)(s0 + row) * Dd + ch);
                CP16(vb + (uint32_t)(row * 72 + ch) * 2, Vp + (size_t)(s0 + row) * Dd + ch);
            }
        }
        CPCOMMIT();
        CPWAIT1();
        __syncthreads();
        if (it == 0) {
#pragma unroll
            for (int kb = 0; kb < 4; kb++)
                ldm4(aq[kb], sb + (uint32_t)((wm * 16 + (lane & 15)) * 72 +
                                             kb * 16 + (lane >> 4) * 8) * 2);
        }
        const uint32_t kbase = sb + (uint32_t)(FK0 + (it & 1) * FKV) * 2;
        const uint32_t vbase = sb + (uint32_t)(FV0 + (it & 1) * FKV) * 2;
        float s_acc[16][4];
#pragma unroll
        for (int i = 0; i < 16; i++)
#pragma unroll
            for (int j = 0; j < 4; j++) s_acc[i][j] = 0.f;
#pragma unroll
        for (int kb = 0; kb < 4; kb++)
#pragma unroll
            for (int nb2 = 0; nb2 < 8; nb2++) {
                uint32_t bk[4];
                ldm4(bk, kbase + (uint32_t)((nb2 * 16 + ((lane >> 4) & 1) * 8 + (lane & 7)) * 72 +
                                            kb * 16 + ((lane >> 3) & 1) * 8) * 2);
                mma_f16(s_acc[nb2 * 2], aq[kb], bk);
                mma_f16(s_acc[nb2 * 2 + 1], aq[kb], bk + 2);
            }
        float mx0 = -1e30f, mx1 = -1e30f;
#pragma unroll
        for (int t = 0; t < 16; t++) {
            mx0 = fmaxf(mx0, fmaxf(s_acc[t][0], s_acc[t][1]));
            mx1 = fmaxf(mx1, fmaxf(s_acc[t][2], s_acc[t][3]));
        }
        mx0 = fmaxf(mx0, __shfl_xor_sync(0xffffffffu, mx0, 1));
        mx0 = fmaxf(mx0, __shfl_xor_sync(0xffffffffu, mx0, 2));
        mx1 = fmaxf(mx1, __shfl_xor_sync(0xffffffffu, mx1, 1));
        mx1 = fmaxf(mx1, __shfl_xor_sync(0xffffffffu, mx1, 2));
        float mn0 = fmaxf(m_prev0, mx0), mn1 = fmaxf(m_prev1, mx1);
        float sc0 = fexp(m_prev0 - mn0), sc1 = fexp(m_prev1 - mn1);
        m_prev0 = mn0; m_prev1 = mn1;
        float rs0 = 0.f, rs1 = 0.f;
#pragma unroll
        for (int t = 0; t < 16; t++) {
            s_acc[t][0] = fexp(s_acc[t][0] - mn0);
            s_acc[t][1] = fexp(s_acc[t][1] - mn0);
            s_acc[t][2] = fexp(s_acc[t][2] - mn1);
            s_acc[t][3] = fexp(s_acc[t][3] - mn1);
            rs0 += s_acc[t][0] + s_acc[t][1];
            rs1 += s_acc[t][2] + s_acc[t][3];
        }
        rs0 += __shfl_xor_sync(0xffffffffu, rs0, 1);
        rs0 += __shfl_xor_sync(0xffffffffu, rs0, 2);
        rs1 += __shfl_xor_sync(0xffffffffu, rs1, 1);
        rs1 += __shfl_xor_sync(0xffffffffu, rs1, 2);
        l0 = l0 * sc0 + rs0;
        l1 = l1 * sc1 + rs1;
#pragma unroll
        for (int ot = 0; ot < 8; ot++) {
            o_acc[ot][0] *= sc0; o_acc[ot][1] *= sc0;
            o_acc[ot][2] *= sc1; o_acc[ot][3] *= sc1;
        }
#pragma unroll
        for (int pb = 0; pb < 8; pb++) {
            uint32_t ap[4];
            ap[0] = pack_h2(s_acc[2 * pb][0], s_acc[2 * pb][1]);
            ap[1] = pack_h2(s_acc[2 * pb][2], s_acc[2 * pb][3]);
            ap[2] = pack_h2(s_acc[2 * pb + 1][0], s_acc[2 * pb + 1][1]);
            ap[3] = pack_h2(s_acc[2 * pb + 1][2], s_acc[2 * pb + 1][3]);
#pragma unroll
            for (int nb2 = 0; nb2 < 4; nb2++) {
                uint32_t bv[4];
                ldm4t(bv, vbase + (uint32_t)((pb * 16 + (lane & 7) + ((lane >> 3) & 1) * 8) * 72 +
                                             nb2 * 16 + (lane >> 4) * 8) * 2);
                mma_f16(o_acc[nb2 * 2], ap, bv);
                mma_f16(o_acc[nb2 * 2 + 1], ap, bv + 2);
            }
        }
        __syncthreads();
    }
    const float inv0 = 1.f / l0, inv1 = 1.f / l1;
    __half* O = g_o16 + (size_t)b * Ss * Dd + h * HDd;
    const int r = m0 + wm * 16 + (lane >> 2), c2 = (lane & 3) * 2;
#pragma unroll
    for (int ot = 0; ot < 8; ot++) {
        int col = ot * 8 + c2;
        *(uint32_t*)(O + (size_t)r * Dd + col) =
            pack_h2(o_acc[ot][0] * inv0, o_acc[ot][1] * inv0);
        *(uint32_t*)(O + (size_t)(r + 8) * Dd + col) =
            pack_h2(o_acc[ot][2] * inv1, o_acc[ot][3] * inv1);
    }
}

// ---------------- router ----------------
__global__ void router_k(const float* __restrict__ Gw, float* __restrict__ logits_out,
                         int write_logits) {
    const int t = blockIdx.x;
    const int tid = threadIdx.x;
    const int w = tid >> 5, lane = tid & 31;
    const float* x = g_xt + (size_t)t * Dd;
    float s = 0.f;
    for (int d = lane; d < Dd; d += 32) s = fmaf(x[d], Gw[d * Ee + w], s);
    s = warp_red_sum(s);
    __shared__ float lg[Ee];
    if (lane == 0) lg[w] = s;
    __syncthreads();
    if (tid == 0) {
        float mx = lg[0];
#pragma unroll
        for (int e = 1; e < Ee; e++) mx = fmaxf(mx, lg[e]);
        float p[Ee];
        float sum = 0.f;
#pragma unroll
        for (int e = 0; e < Ee; e++) { p[e] = __expf(lg[e] - mx); sum += p[e]; }
        int i0 = 0;
#pragma unroll
        for (int e = 1; e < Ee; e++) if (p[e] > p[i0]) i0 = e;
        int i1 = (i0 == 0) ? 1 : 0;
#pragma unroll
        for (int e = 0; e < Ee; e++) if (e != i0 && p[e] > p[i1]) i1 = e;
        float v0 = p[i0] / sum, v1 = p[i1] / sum;
        float inv = 1.f / (v0 + v1);
        g_topidx[t * 2 + 0] = i0;
        g_topidx[t * 2 + 1] = i1;
        g_topw[t * 2 + 0] = v0 * inv;
        g_topw[t * 2 + 1] = v1 * inv;
    }
    if (write_logits && tid < Ee) logits_out[(size_t)t * Ee + tid] = lg[tid];
}

__global__ void zero_cnt_k() { if (threadIdx.x < Ee) g_cnt[threadIdx.x] = 0; }

__global__ void assign_k() {
    const int t = blockIdx.x * 256 + threadIdx.x;
    if (t >= Tt) return;
#pragma unroll
    for (int j = 0; j < 2; j++) {
        int e = g_topidx[t * 2 + j];
        int pos = atomicAdd(&g_cnt[e], 1);
        g_assign[e * CAP + pos] = t;
        g_slotid[t * 2 + j] = e * CAP + pos;
    }
}

// ---------------- MoE gate/up k64 + SiLU -> fp16 h ----------------
__global__ void __launch_bounds__(256) moe_gu16() {
    extern __shared__ __half sm[];
    __shared__ int toks[128];
    const int e = blockIdx.z;
    const int cnt = g_cnt[e];
    const int m0 = blockIdx.x << 7;
    if (m0 >= cnt) return;
    const int n0 = blockIdx.y << 7;
    const uint32_t sb = smem_u32(sm);
    const int tid = threadIdx.x, lane = tid & 31, wid = tid >> 5;
    const int wm = wid & 3, wn = wid >> 2;
    if (tid < 128) toks[tid] = g_assign[e * CAP + min(m0 + tid, cnt - 1)];
    __syncthreads();

    const size_t eo = (size_t)e * Dd * Ff;
    const __half* G = g_Wg16 + eo;
    const __half* U = g_Wu16 + eo;

    float ag[2][8][4], au[2][8][4];
#pragma unroll
    for (int a = 0; a < 2; a++)
#pragma unroll
        for (int c = 0; c < 8; c++)
#pragma unroll
            for (int d = 0; d < 4; d++) { ag[a][c][d] = 0.f; au[a][c][d] = 0.f; }

    const int ra = tid >> 3, ca = (tid & 7) << 3;
    const int rb = tid >> 4, cb = (tid & 15) << 3;
    {
        uint32_t base = sb;
#pragma unroll
        for (int i = 0; i < 4; i++)
            CP16(base + (uint32_t)((ra + i * 32) * RS + ca) * 2,
                 g_xt16 + (size_t)toks[ra + i * 32] * Dd + ca);
#pragma unroll
        for (int i = 0; i < 4; i++) {
            CP16(base + (uint32_t)(OFG + (rb + i * 16) * RSB + cb) * 2,
                 G + (size_t)(rb + i * 16) * Ff + n0 + cb);
            CP16(base + (uint32_t)(OFU + (rb + i * 16) * RSB + cb) * 2,
                 U + (size_t)(rb + i * 16) * Ff + n0 + cb);
        }
        CPCOMMIT();
    }
    const int nb = Dd >> 6;
    for (int it = 0; it < nb; it++) {
        if (it + 1 < nb) {
            uint32_t base = sb + (uint32_t)((it + 1) & 1) * STEg * 2;
            int k0 = (it + 1) << 6;
#pragma unroll
            for (int i = 0; i < 4; i++)
                CP16(base + (uint32_t)((ra + i * 32) * RS + ca) * 2,
                     g_xt16 + (size_t)toks[ra + i * 32] * Dd + k0 + ca);
#pragma unroll
            for (int i = 0; i < 4; i++) {
                CP16(base + (uint32_t)(OFG + (rb + i * 16) * RSB + cb) * 2,
                     G + (size_t)(k0 + rb + i * 16) * Ff + n0 + cb);
                CP16(base + (uint32_t)(OFU + (rb + i * 16) * RSB + cb) * 2,
                     U + (size_t)(k0 + rb + i * 16) * Ff + n0 + cb);
            }
        }
        CPCOMMIT();
        CPWAIT1();
        __syncthreads();
        uint32_t base = sb + (uint32_t)(it & 1) * STEg * 2;
#pragma unroll
        for (int ks = 0; ks < 4; ks++) {
            uint32_t a[2][4];
#pragma unroll
            for (int mt = 0; mt < 2; mt++)
                ldm4(a[mt], base + (uint32_t)((wm * 32 + mt * 16 + (lane & 15)) * RS +
                                              ks * 16 + (lane >> 4) * 8) * 2);
            uint32_t roff = (uint32_t)((ks * 16 + (lane & 7) + ((lane >> 3) & 1) * 8) * RSB) * 2;
            uint32_t coff[4];
#pragma unroll
            for (int bt = 0; bt < 4; bt++)
                coff[bt] = (uint32_t)(wn * 64 + bt * 16 + (lane >> 4) * 8) * 2;
            {
                uint32_t bg[4][4];
#pragma unroll
                for (int bt = 0; bt < 4; bt++)
                    ldm4t(bg[bt], base + OFG * 2 + roff + coff[bt]);
#pragma unroll
                for (int mt = 0; mt < 2; mt++)
#pragma unroll
                    for (int nt = 0; nt < 8; nt++)
                        mma_f16(ag[mt][nt], a[mt], &bg[nt >> 1][(nt & 1) * 2]);
            }
            {
                uint32_t bu[4][4];
#pragma unroll
                for (int bt = 0; bt < 4; bt++)
                    ldm4t(bu[bt], base + OFU * 2 + roff + coff[bt]);
#pragma unroll
                for (int mt = 0; mt < 2; mt++)
#pragma unroll
                    for (int nt = 0; nt < 8; nt++)
                        mma_f16(au[mt][nt], a[mt], &bu[nt >> 1][(nt & 1) * 2]);
            }
        }
        __syncthreads();
    }
    const int lr = lane >> 2, lc2 = (lane & 3) * 2;
#pragma unroll
    for (int mt = 0; mt < 2; mt++)
#pragma unroll
        for (int nt = 0; nt < 8; nt++) {
            int r = m0 + wm * 32 + mt * 16 + lr;
            int col = n0 + wn * 64 + nt * 8 + lc2;
#pragma unroll
            for (int half = 0; half < 2; half++) {
                int rr = r + half * 8;
                if (rr < cnt) {
                    float gv0 = ag[mt][nt][half * 2], gv1 = ag[mt][nt][half * 2 + 1];
                    float uv0 = au[mt][nt][half * 2], uv1 = au[mt][nt][half * 2 + 1];
                    float v0 = gv0 * frcp(1.f + fexp(-gv0)) * uv0;
                    float v1 = gv1 * frcp(1.f + fexp(-gv1)) * uv1;
                    *(uint32_t*)(g_h16 + ((size_t)e * CAP + rr) * Ff + col) = pack_h2(v0, v1);
                }
            }
        }
}

// ---------------- MoE down k64 -> g_moeout fp32 (slot rows) ----------------
__global__ void __launch_bounds__(256, 2) moe_down16() {
    extern __shared__ __half sm[];
    const int e = blockIdx.z;
    const int cnt = g_cnt[e];
    const int m0 = blockIdx.x << 7;
    if (m0 >= cnt) return;
    const int n0 = blockIdx.y << 7;
    const uint32_t sb = smem_u32(sm);
    const int tid = threadIdx.x, lane = tid & 31, wid = tid >> 5;
    const int wm = wid & 3, wn = wid >> 2;
    const int cm1 = cnt - 1;

    const __half* A = g_h16 + (size_t)e * CAP * Ff;
    const __half* B = g_Wd16 + (size_t)e * Ff * Dd;

    float acc[2][8][4];
#pragma unroll
    for (int a = 0; a < 2; a++)
#pragma unroll
        for (int c = 0; c < 8; c++)
#pragma unroll
            for (int d = 0; d < 4; d++) acc[a][c][d] = 0.f;

    const int ra = tid >> 3, ca = (tid & 7) << 3;
    const int rb = tid >> 4, cb = (tid & 15) << 3;
    {
        uint32_t base = sb;
#pragma unroll
        for (int i = 0; i < 4; i++)
            CP16(base + (uint32_t)((ra + i * 32) * RS + ca) * 2,
                 A + (size_t)min(m0 + ra + i * 32, cm1) * Ff + ca);
#pragma unroll
        for (int i = 0; i < 4; i++)
            CP16(base + (uint32_t)(OFB + (rb + i * 16) * RSB + cb) * 2,
                 B + (size_t)(rb + i * 16) * Dd + n0 + cb);
        CPCOMMIT();
    }
    const int nb = Ff >> 6;
    for (int it = 0; it < nb; it++) {
        if (it + 1 < nb) {
            uint32_t base = sb + (uint32_t)((it + 1) & 1) * STEd * 2;
            int k0 = (it + 1) << 6;
#pragma unroll
            for (int i = 0; i < 4; i++)
                CP16(base + (uint32_t)((ra + i * 32) * RS + ca) * 2,
                     A + (size_t)min(m0 + ra + i * 32, cm1) * Ff + k0 + ca);
#pragma unroll
            for (int i = 0; i < 4; i++)
                CP16(base + (uint32_t)(OFB + (rb + i * 16) * RSB + cb) * 2,
                     B + (size_t)(k0 + rb + i * 16) * Dd + n0 + cb);
        }
        CPCOMMIT();
        CPWAIT1();
        __syncthreads();
        uint32_t base = sb + (uint32_t)(it & 1) * STEd * 2;
#pragma unroll
        for (int ks = 0; ks < 4; ks++) {
            uint32_t a[2][4];
#pragma unroll
            for (int mt = 0; mt < 2; mt++)
                ldm4(a[mt], base + (uint32_t)((wm * 32 + mt * 16 + (lane & 15)) * RS +
                                              ks * 16 + (lane >> 4) * 8) * 2);
            uint32_t bq[4][4];
#pragma unroll
            for (int bt = 0; bt < 4; bt++)
                ldm4t(bq[bt], base + (uint32_t)(OFB +
                                                (ks * 16 + (lane & 7) + ((lane >> 3) & 1) * 8) * RSB +
                                                wn * 64 + bt * 16 + (lane >> 4) * 8) * 2);
#pragma unroll
            for (int mt = 0; mt < 2; mt++)
#pragma unroll
                for (int nt = 0; nt < 8; nt++)
                    mma_f16(acc[mt][nt], a[mt], &bq[nt >> 1][(nt & 1) * 2]);
        }
        __syncthreads();
    }
    const int lr = lane >> 2, lc2 = (lane & 3) * 2;
#pragma unroll
    for (int mt = 0; mt < 2; mt++)
#pragma unroll
        for (int half = 0; half < 2; half++) {
            int r = m0 + wm * 32 + mt * 16 + lr + half * 8;
            if (r < cnt) {
                float* op = g_moeout + ((size_t)e * CAP + r) * Dd;
#pragma unroll
                for (int nt = 0; nt < 8; nt++) {
                    int col = n0 + wn * 64 + nt * 8 + lc2;
                    *(float2*)(op + col) = make_float2(acc[mt][nt][half * 2],
                                                       acc[mt][nt][half * 2 + 1]);
                }
            }
        }
}

// ---------------- final gather ----------------
__global__ void final_k(float* __restrict__ out) {
    const size_t i4 = ((size_t)blockIdx.x * 256 + threadIdx.x) * 4;
    const int t = (int)(i4 >> 10);
    const int c = (int)(i4 & 1023);
    const int s0 = g_slotid[t * 2 + 0], s1 = g_slotid[t * 2 + 1];
    const float w0 = g_topw[t * 2 + 0], w1 = g_topw[t * 2 + 1];
    float4 hv = *(const float4*)(g_hidden + i4);
    float4 m0 = *(const float4*)(g_moeout + (size_t)s0 * Dd + c);
    float4 m1 = *(const float4*)(g_moeout + (size_t)s1 * Dd + c);
    hv.x += w0 * m0.x + w1 * m1.x;
    hv.y += w0 * m0.y + w1 * m1.y;
    hv.z += w0 * m0.z + w1 * m1.z;
    hv.w += w0 * m0.w + w1 * m1.w;
    *(float4*)(out + i4) = hv;
}

// ---------------- launch ----------------
extern "C" void kernel_launch(void* const* d_in, const int* in_sizes, int n_in,
                              void* d_out, int out_size) {
    (void)in_sizes; (void)n_in;
    const float* hs    = (const float*)d_in[0];
    const float* ln1   = (const float*)d_in[1];
    const float* ln2   = (const float*)d_in[2];
    const float* Wq    = (const float*)d_in[3];
    const float* Wk    = (const float*)d_in[4];
    const float* Wv    = (const float*)d_in[5];
    const float* Wo    = (const float*)d_in[6];
    const float* qn    = (const float*)d_in[7];
    const float* kn    = (const float*)d_in[8];
    const float* gamma = (const float*)d_in[9];
    const float* gw    = (const float*)d_in[10];
    const float* Wg    = (const float*)d_in[11];
    const float* Wu    = (const float*)d_in[12];
    const float* Wd    = (const float*)d_in[13];
    float* out = (float*)d_out;

    float *p_hidden, *p_xt;
    cudaGetSymbolAddress((void**)&p_hidden, g_hidden);
    cudaGetSymbolAddress((void**)&p_xt, g_xt);

    __half *wq16, *wk16, *wv16, *wo16, *wg16, *wu16, *wd16;
    __half *x16, *q16, *k16, *v16, *o16, *xt16;
    cudaGetSymbolAddress((void**)&wq16, g_Wq16);
    cudaGetSymbolAddress((void**)&wk16, g_Wk16);
    cudaGetSymbolAddress((void**)&wv16, g_Wv16);
    cudaGetSymbolAddress((void**)&wo16, g_Wo16);
    cudaGetSymbolAddress((void**)&wg16, g_Wg16);
    cudaGetSymbolAddress((void**)&wu16, g_Wu16);
    cudaGetSymbolAddress((void**)&wd16, g_Wd16);
    cudaGetSymbolAddress((void**)&x16, g_x16);
    cudaGetSymbolAddress((void**)&q16, g_q16);
    cudaGetSymbolAddress((void**)&k16, g_k16);
    cudaGetSymbolAddress((void**)&v16, g_v16);
    cudaGetSymbolAddress((void**)&o16, g_o16);
    cudaGetSymbolAddress((void**)&xt16, g_xt16);

    cudaFuncSetAttribute(hgemm16, cudaFuncAttributeMaxDynamicSharedMemorySize, SMEMd);
    cudaFuncSetAttribute(moe_down16, cudaFuncAttributeMaxDynamicSharedMemorySize, SMEMd);
    cudaFuncSetAttribute(moe_gu16, cudaFuncAttributeMaxDynamicSharedMemorySize, SMEMg);
    cudaFuncSetAttribute(fmha_k, cudaFuncAttributeMaxDynamicSharedMemorySize, SMEMf);

    // weight converts (streaming, same layout, 8 elems/thread)
    wconv_k<<<Dd * Dd / 2048, 256>>>(Wq, wq16);
    wconv_k<<<Dd * Dd / 2048, 256>>>(Wk, wk16);
    wconv_k<<<Dd * Dd / 2048, 256>>>(Wv, wv16);
    wconv_k<<<Dd * Dd / 2048, 256>>>(Wo, wo16);
    wconv_k<<<(int)((size_t)Ee * Dd * Ff / 2048), 256>>>(Wg, wg16);
    wconv_k<<<(int)((size_t)Ee * Dd * Ff / 2048), 256>>>(Wu, wu16);
    wconv_k<<<(int)((size_t)Ee * Ff * Dd / 2048), 256>>>(Wd, wd16);

    // --- attention branch ---
    rmsnorm_h<<<Tt, 256>>>(hs, ln1, x16, nullptr);
    hgemm16<<<dim3(32, 8), 256, SMEMd>>>(x16, wq16, nullptr, q16, nullptr, nullptr, Dd, Dd);
    hgemm16<<<dim3(32, 8), 256, SMEMd>>>(x16, wk16, nullptr, k16, nullptr, nullptr, Dd, Dd);
    hgemm16<<<dim3(32, 8), 256, SMEMd>>>(x16, wv16, nullptr, v16, nullptr, nullptr, Dd, Dd);
    headnorm_h<<<dim3(Tt * Hh / 8, 2), 256>>>(q16, k16, qn, kn);
    fmha_k<<<dim3(8, 64), 256, SMEMf>>>();
    hgemm16<<<dim3(32, 8), 256, SMEMd>>>(o16, wo16, p_hidden, nullptr, hs, gamma, Dd, Dd);

    // --- MoE branch ---
    rmsnorm_h<<<Tt, 256>>>(p_hidden, ln2, xt16, p_xt);
    int write_logits = (out_size >= Tt * Dd + Tt * Ee) ? 1 : 0;
    router_k<<<Tt, 256>>>(gw, out + (size_t)Tt * Dd, write_logits);
    zero_cnt_k<<<1, 32>>>();
    assign_k<<<Tt / 256, 256>>>();
    moe_gu16<<<dim3(CAP / 128, Ff / 128, Ee), 256, SMEMg>>>();
    moe_down16<<<dim3(CAP / 128, Dd / 128, Ee), 256, SMEMd>>>();
    final_k<<<Tt * Dd / 1024, 256>>>(out);
}

// round 7
// speedup vs baseline: 6.6179x; 1.0358x over previous
#include <cuda_runtime.h>
#include <cuda_fp16.h>
#include <math.h>
#include <stdint.h>

// ---------------- constants ----------------
#define Bb 4
#define Ss 1024
#define Tt 4096
#define Dd 1024
#define Hh 16
#define HDd 64
#define Ee 8
#define Ff 4096
#define CAP 4096
#define EPSf 1e-6f

#define RS  72             // A-tile smem row stride (halves), k64
#define RSB 136            // B-tile ([K][N]) smem row stride (halves)

// k64 stage layouts (halves)
#define OFB  9216          // dense/down: A[128][72] then B[64][136]
#define STEd 17920
#define OFG  9216          // gu: A[128][72], G[64][136], U[64][136]
#define OFU  17920
#define STEg 26624

#define SMEMd (2 * STEd * 2)    // 71680 B (2-stage, 2 CTA/SM)
#define SMEMg3 (3 * STEg * 2)   // 159744 B (3-stage, 1 CTA/SM)

// fmha smem (halves): Q[128][72], K0,V0,K1,V1 each [128][72]
#define FK0 9216
#define FV0 18432
#define FKV 18432
#define SMEMf (46080 * 2)

// ---------------- scratch ----------------
__device__ __align__(256) float g_hidden[(size_t)Tt * Dd];
__device__ __align__(256) float g_moeout[(size_t)Ee * CAP * Dd];
__device__ int   g_topidx[Tt * 2];
__device__ float g_topw[Tt * 2];
__device__ int   g_slotid[Tt * 2];
__device__ int   g_cnt[Ee];
__device__ int   g_assign[Ee * CAP];

__device__ __align__(256) __half g_x16[(size_t)Tt * Dd];
__device__ __align__(256) __half g_q16[(size_t)Tt * Dd];
__device__ __align__(256) __half g_k16[(size_t)Tt * Dd];
__device__ __align__(256) __half g_v16[(size_t)Tt * Dd];
__device__ __align__(256) __half g_o16[(size_t)Tt * Dd];
__device__ __align__(256) __half g_xt16[(size_t)Tt * Dd];
__device__ __align__(256) __half g_h16[(size_t)Ee * CAP * Ff];

// fp16 weights, ORIGINAL layout [K][N]
__device__ __align__(256) __half g_Wg16[(size_t)Ee * Dd * Ff];
__device__ __align__(256) __half g_Wu16[(size_t)Ee * Dd * Ff];
__device__ __align__(256) __half g_Wd16[(size_t)Ee * Ff * Dd];
__device__ __align__(256) __half g_Wq16[(size_t)Dd * Dd];
__device__ __align__(256) __half g_Wk16[(size_t)Dd * Dd];
__device__ __align__(256) __half g_Wv16[(size_t)Dd * Dd];
__device__ __align__(256) __half g_Wo16[(size_t)Dd * Dd];

// ---------------- helpers ----------------
__device__ __forceinline__ float warp_red_sum(float v) {
#pragma unroll
    for (int o = 16; o; o >>= 1) v += __shfl_xor_sync(0xffffffffu, v, o);
    return v;
}
__device__ __forceinline__ uint32_t smem_u32(const void* p) {
    uint32_t a;
    asm("{ .reg .u64 t; cvta.to.shared.u64 t, %1; cvt.u32.u64 %0, t; }" : "=r"(a) : "l"(p));
    return a;
}
#define CP16(sm, gp) \
    asm volatile("cp.async.ca.shared.global [%0], [%1], 16;" :: "r"(sm), "l"(gp))
#define CPCOMMIT() asm volatile("cp.async.commit_group;")
#define CPWAIT1() asm volatile("cp.async.wait_group 1;")
#define CPWAIT2() asm volatile("cp.async.wait_group 2;")

__device__ __forceinline__ void ldm4(uint32_t* r, uint32_t addr) {
    asm volatile("ldmatrix.sync.aligned.m8n8.x4.shared.b16 {%0,%1,%2,%3}, [%4];"
                 : "=r"(r[0]), "=r"(r[1]), "=r"(r[2]), "=r"(r[3]) : "r"(addr));
}
__device__ __forceinline__ void ldm4t(uint32_t* r, uint32_t addr) {
    asm volatile("ldmatrix.sync.aligned.m8n8.x4.trans.shared.b16 {%0,%1,%2,%3}, [%4];"
                 : "=r"(r[0]), "=r"(r[1]), "=r"(r[2]), "=r"(r[3]) : "r"(addr));
}
__device__ __forceinline__ void mma_f16(float* c, const uint32_t* a, const uint32_t* b) {
    asm volatile(
        "mma.sync.aligned.m16n8k16.row.col.f32.f16.f16.f32 "
        "{%0,%1,%2,%3},{%4,%5,%6,%7},{%8,%9},{%0,%1,%2,%3};"
        : "+f"(c[0]), "+f"(c[1]), "+f"(c[2]), "+f"(c[3])
        : "r"(a[0]), "r"(a[1]), "r"(a[2]), "r"(a[3]), "r"(b[0]), "r"(b[1]));
}
__device__ __forceinline__ uint32_t pack_h2(float a, float b) {
    __half2 h; h.x = __float2half_rn(a); h.y = __float2half_rn(b);
    return *(uint32_t*)&h;
}
// fast exp on FMA pipe (rel err ~4e-5)
__device__ __forceinline__ float fexp(float x) {
    x = fminf(fmaxf(x, -60.f), 60.f);
    float z = x * 1.442695041f;
    float j = z + 12582912.f;
    int i = __float_as_int(j) - 0x4b400000;
    float f = z - (j - 12582912.f);
    float p = fmaf(f, 0.009618129f, 0.055504110f);
    p = fmaf(f, p, 0.240226507f);
    p = fmaf(f, p, 0.693147181f);
    p = fmaf(f, p, 1.0f);
    return __int_as_float(__float_as_int(p) + (i << 23));
}
__device__ __forceinline__ float frcp(float d) {
    float r = __uint_as_float(0x7ef311c3u - __float_as_uint(d));
    r = r * (2.0f - d * r);
    r = r * (2.0f - d * r);
    r = r * (2.0f - d * r);
    return r;
}

// ---------------- streaming weight convert fp32 -> fp16 (8 elems/thread) ----------------
__global__ void wconv_k(const float* __restrict__ in, __half* __restrict__ o) {
    const size_t i = ((size_t)blockIdx.x * 256 + threadIdx.x) * 8;
    float4 a = *(const float4*)(in + i);
    float4 b = *(const float4*)(in + i + 4);
    uint4 p;
    p.x = pack_h2(a.x, a.y);
    p.y = pack_h2(a.z, a.w);
    p.z = pack_h2(b.x, b.y);
    p.w = pack_h2(b.z, b.w);
    *(uint4*)(o + i) = p;
}

// ---------------- RMSNorm -> fp16 ----------------
__global__ void rmsnorm_h(const float* __restrict__ in, const float* __restrict__ w,
                          __half* __restrict__ o16) {
    const int t = blockIdx.x;
    const float* x = in + (size_t)t * Dd;
    float ss = 0.f;
    float v4[4];
#pragma unroll
    for (int j = 0; j < 4; j++) {
        float v = x[threadIdx.x + j * 256];
        v4[j] = v;
        ss = fmaf(v, v, ss);
    }
    __shared__ float red[8];
    __shared__ float sres;
    float ws = warp_red_sum(ss);
    if ((threadIdx.x & 31) == 0) red[threadIdx.x >> 5] = ws;
    __syncthreads();
    if (threadIdx.x == 0) {
        float s = 0.f;
        for (int i = 0; i < 8; i++) s += red[i];
        sres = rsqrtf(s * (1.f / Dd) + EPSf);
    }
    __syncthreads();
    const float r = sres;
#pragma unroll
    for (int j = 0; j < 4; j++) {
        int i = threadIdx.x + j * 256;
        o16[(size_t)t * Dd + i] = __float2half_rn(v4[j] * r * w[i]);
    }
}

// ---------------- fused RMSNorm + router (block = token) ----------------
__global__ void rmsnorm_router_k(const float* __restrict__ in, const float* __restrict__ w,
                                 const float* __restrict__ Gw, __half* __restrict__ o16,
                                 float* __restrict__ logits_out, int write_logits) {
    const int t = blockIdx.x;
    const int tid = threadIdx.x;
    const float* x = in + (size_t)t * Dd;
    float ss = 0.f;
    float v4[4];
#pragma unroll
    for (int j = 0; j < 4; j++) {
        float v = x[tid + j * 256];
        v4[j] = v;
        ss = fmaf(v, v, ss);
    }
    __shared__ float red[8];
    __shared__ float red8[8][8];
    __shared__ float lgs[8];
    __shared__ float sres;
    float ws = warp_red_sum(ss);
    if ((tid & 31) == 0) red[tid >> 5] = ws;
    __syncthreads();
    if (tid == 0) {
        float s = 0.f;
        for (int i = 0; i < 8; i++) s += red[i];
        sres = rsqrtf(s * (1.f / Dd) + EPSf);
    }
    __syncthreads();
    const float r = sres;
    float s[8];
#pragma unroll
    for (int e = 0; e < 8; e++) s[e] = 0.f;
#pragma unroll
    for (int j = 0; j < 4; j++) {
        int i = tid + j * 256;
        float v = v4[j] * r * w[i];
        o16[(size_t)t * Dd + i] = __float2half_rn(v);
        float4 g0 = *(const float4*)(Gw + (size_t)i * 8);
        float4 g1 = *(const float4*)(Gw + (size_t)i * 8 + 4);
        s[0] = fmaf(v, g0.x, s[0]); s[1] = fmaf(v, g0.y, s[1]);
        s[2] = fmaf(v, g0.z, s[2]); s[3] = fmaf(v, g0.w, s[3]);
        s[4] = fmaf(v, g1.x, s[4]); s[5] = fmaf(v, g1.y, s[5]);
        s[6] = fmaf(v, g1.z, s[6]); s[7] = fmaf(v, g1.w, s[7]);
    }
#pragma unroll
    for (int e = 0; e < 8; e++) s[e] = warp_red_sum(s[e]);
    if ((tid & 31) == 0) {
#pragma unroll
        for (int e = 0; e < 8; e++) red8[tid >> 5][e] = s[e];
    }
    __syncthreads();
    if (tid == 0) {
        float lg[8];
#pragma unroll
        for (int e = 0; e < 8; e++) {
            float a = 0.f;
            for (int wdx = 0; wdx < 8; wdx++) a += red8[wdx][e];
            lg[e] = a;
            lgs[e] = a;
        }
        float mx = lg[0];
#pragma unroll
        for (int e = 1; e < 8; e++) mx = fmaxf(mx, lg[e]);
        float p[8];
        float sum = 0.f;
#pragma unroll
        for (int e = 0; e < 8; e++) { p[e] = __expf(lg[e] - mx); sum += p[e]; }
        int i0 = 0;
#pragma unroll
        for (int e = 1; e < 8; e++) if (p[e] > p[i0]) i0 = e;
        int i1 = (i0 == 0) ? 1 : 0;
#pragma unroll
        for (int e = 0; e < 8; e++) if (e != i0 && p[e] > p[i1]) i1 = e;
        float v0 = p[i0] / sum, v1 = p[i1] / sum;
        float inv = 1.f / (v0 + v1);
        g_topidx[t * 2 + 0] = i0;
        g_topidx[t * 2 + 1] = i1;
        g_topw[t * 2 + 0] = v0 * inv;
        g_topw[t * 2 + 1] = v1 * inv;
    }
    __syncthreads();
    if (write_logits && tid < 8) logits_out[(size_t)t * 8 + tid] = lgs[tid];
}

// ---------------- dense GEMM k64 + optional fused per-head RMSNorm epilogue ----------------
__global__ void __launch_bounds__(256, 2) hgemm16(
    const __half* __restrict__ A, const __half* __restrict__ B,
    float* __restrict__ Cf, __half* __restrict__ C16,
    const float* __restrict__ resid, const float* __restrict__ gamma,
    const float* __restrict__ nw, float nsc,
    int K, int N) {
    extern __shared__ __half sm[];
    const uint32_t sb = smem_u32(sm);
    const int tid = threadIdx.x, lane = tid & 31, wid = tid >> 5;
    const int m0 = blockIdx.x << 7, n0 = blockIdx.y << 7;
    const int wm = wid & 3, wn = wid >> 2;

    float acc[2][8][4];
#pragma unroll
    for (int a = 0; a < 2; a++)
#pragma unroll
        for (int b = 0; b < 8; b++)
#pragma unroll
            for (int c = 0; c < 4; c++) acc[a][b][c] = 0.f;

    const int ra = tid >> 3, ca = (tid & 7) << 3;
    const int rb = tid >> 4, cb = (tid & 15) << 3;
    {
        uint32_t base = sb;
#pragma unroll
        for (int i = 0; i < 4; i++)
            CP16(base + (uint32_t)((ra + i * 32) * RS + ca) * 2,
                 A + (size_t)(m0 + ra + i * 32) * K + ca);
#pragma unroll
        for (int i = 0; i < 4; i++)
            CP16(base + (uint32_t)(OFB + (rb + i * 16) * RSB + cb) * 2,
                 B + (size_t)(rb + i * 16) * N + n0 + cb);
        CPCOMMIT();
    }
    const int nb = K >> 6;
    for (int it = 0; it < nb; it++) {
        if (it + 1 < nb) {
            uint32_t base = sb + (uint32_t)((it + 1) & 1) * STEd * 2;
            int k0 = (it + 1) << 6;
#pragma unroll
            for (int i = 0; i < 4; i++)
                CP16(base + (uint32_t)((ra + i * 32) * RS + ca) * 2,
                     A + (size_t)(m0 + ra + i * 32) * K + k0 + ca);
#pragma unroll
            for (int i = 0; i < 4; i++)
                CP16(base + (uint32_t)(OFB + (rb + i * 16) * RSB + cb) * 2,
                     B + (size_t)(k0 + rb + i * 16) * N + n0 + cb);
        }
        CPCOMMIT();
        CPWAIT1();
        __syncthreads();
        uint32_t base = sb + (uint32_t)(it & 1) * STEd * 2;
#pragma unroll
        for (int ks = 0; ks < 4; ks++) {
            uint32_t a[2][4];
#pragma unroll
            for (int mt = 0; mt < 2; mt++)
                ldm4(a[mt], base + (uint32_t)((wm * 32 + mt * 16 + (lane & 15)) * RS +
                                              ks * 16 + (lane >> 4) * 8) * 2);
            uint32_t bq[4][4];
#pragma unroll
            for (int bt = 0; bt < 4; bt++)
                ldm4t(bq[bt], base + (uint32_t)(OFB +
                                                (ks * 16 + (lane & 7) + ((lane >> 3) & 1) * 8) * RSB +
                                                wn * 64 + bt * 16 + (lane >> 4) * 8) * 2);
#pragma unroll
            for (int mt = 0; mt < 2; mt++)
#pragma unroll
                for (int nt = 0; nt < 8; nt++)
                    mma_f16(acc[mt][nt], a[mt], &bq[nt >> 1][(nt & 1) * 2]);
        }
        __syncthreads();
    }
    const int lr = lane >> 2, lc2 = (lane & 3) * 2;
    if (C16 && nw) {
        // fused per-head RMSNorm: warp's 64 cols == one head
#pragma unroll
        for (int mt = 0; mt < 2; mt++)
#pragma unroll
            for (int half = 0; half < 2; half++) {
                float ss = 0.f;
#pragma unroll
                for (int nt = 0; nt < 8; nt++) {
                    float a0 = acc[mt][nt][half * 2], a1 = acc[mt][nt][half * 2 + 1];
                    ss = fmaf(a0, a0, fmaf(a1, a1, ss));
                }
                ss += __shfl_xor_sync(0xffffffffu, ss, 1);
                ss += __shfl_xor_sync(0xffffffffu, ss, 2);
                float r = rsqrtf(ss * (1.f / HDd) + EPSf) * nsc;
                int row = m0 + wm * 32 + mt * 16 + lr + half * 8;
#pragma unroll
                for (int nt = 0; nt < 8; nt++) {
                    int wcol = nt * 8 + lc2;
                    int col = n0 + wn * 64 + wcol;
                    *(uint32_t*)(C16 + (size_t)row * N + col) =
                        pack_h2(acc[mt][nt][half * 2] * r * nw[wcol],
                                acc[mt][nt][half * 2 + 1] * r * nw[wcol + 1]);
                }
            }
    } else {
#pragma unroll
        for (int mt = 0; mt < 2; mt++)
#pragma unroll
            for (int nt = 0; nt < 8; nt++) {
                int row = m0 + wm * 32 + mt * 16 + lr;
                int col = n0 + wn * 64 + nt * 8 + lc2;
                if (C16) {
                    *(uint32_t*)(C16 + (size_t)row * N + col) = pack_h2(acc[mt][nt][0], acc[mt][nt][1]);
                    *(uint32_t*)(C16 + (size_t)(row + 8) * N + col) = pack_h2(acc[mt][nt][2], acc[mt][nt][3]);
                } else if (resid) {
                    float ga = gamma[col], gb = gamma[col + 1];
                    float2 r0 = *(const float2*)(resid + (size_t)row * N + col);
                    float2 r1 = *(const float2*)(resid + (size_t)(row + 8) * N + col);
                    *(float2*)(Cf + (size_t)row * N + col) =
                        make_float2(fmaf(ga, acc[mt][nt][0], r0.x), fmaf(gb, acc[mt][nt][1], r0.y));
                    *(float2*)(Cf + (size_t)(row + 8) * N + col) =
                        make_float2(fmaf(ga, acc[mt][nt][2], r1.x), fmaf(gb, acc[mt][nt][3], r1.y));
                } else {
                    *(float2*)(Cf + (size_t)row * N + col) = make_float2(acc[mt][nt][0], acc[mt][nt][1]);
                    *(float2*)(Cf + (size_t)(row + 8) * N + col) = make_float2(acc[mt][nt][2], acc[mt][nt][3]);
                }
            }
    }
}

// ---------------- flash attention ----------------
__global__ void __launch_bounds__(256) fmha_k() {
    extern __shared__ __half sm[];
    const uint32_t sb = smem_u32(sm);
    const int z = blockIdx.y, b = z >> 4, h = z & 15;
    const int m0 = blockIdx.x << 7;
    const int tid = threadIdx.x, lane = tid & 31, wm = tid >> 5;
    const __half* Q = g_q16 + (size_t)b * Ss * Dd + h * HDd;
    const __half* Kp = g_k16 + (size_t)b * Ss * Dd + h * HDd;
    const __half* Vp = g_v16 + (size_t)b * Ss * Dd + h * HDd;

    {
#pragma unroll
        for (int i = 0; i < 4; i++) {
            int c = tid + (i << 8);
            int row = c >> 3, ch = (c & 7) << 3;
            CP16(sb + (uint32_t)(row * 72 + ch) * 2, Q + (size_t)(m0 + row) * Dd + ch);
        }
#pragma unroll
        for (int i = 0; i < 4; i++) {
            int c = tid + (i << 8);
            int row = c >> 3, ch = (c & 7) << 3;
            CP16(sb + (uint32_t)(FK0 + row * 72 + ch) * 2, Kp + (size_t)row * Dd + ch);
            CP16(sb + (uint32_t)(FV0 + row * 72 + ch) * 2, Vp + (size_t)row * Dd + ch);
        }
        CPCOMMIT();
    }
    uint32_t aq[4][4];
    float o_acc[8][4];
#pragma unroll
    for (int i = 0; i < 8; i++)
#pragma unroll
        for (int j = 0; j < 4; j++) o_acc[i][j] = 0.f;
    float m_prev0 = -1e30f, m_prev1 = -1e30f, l0 = 0.f, l1 = 0.f;

    for (int it = 0; it < 8; it++) {
        if (it < 7) {
            uint32_t kb = sb + (uint32_t)(FK0 + ((it + 1) & 1) * FKV) * 2;
            uint32_t vb = sb + (uint32_t)(FV0 + ((it + 1) & 1) * FKV) * 2;
            int s0 = (it + 1) << 7;
#pragma unroll
            for (int i = 0; i < 4; i++) {
                int c = tid + (i << 8);
                int row = c >> 3, ch = (c & 7) << 3;
                CP16(kb + (uint32_t)(row * 72 + ch) * 2, Kp + (size_t)(s0 + row) * Dd + ch);
                CP16(vb + (uint32_t)(row * 72 + ch) * 2, Vp + (size_t)(s0 + row) * Dd + ch);
            }
        }
        CPCOMMIT();
        CPWAIT1();
        __syncthreads();
        if (it == 0) {
#pragma unroll
            for (int kb = 0; kb < 4; kb++)
                ldm4(aq[kb], sb + (uint32_t)((wm * 16 + (lane & 15)) * 72 +
                                             kb * 16 + (lane >> 4) * 8) * 2);
        }
        const uint32_t kbase = sb + (uint32_t)(FK0 + (it & 1) * FKV) * 2;
        const uint32_t vbase = sb + (uint32_t)(FV0 + (it & 1) * FKV) * 2;
        float s_acc[16][4];
#pragma unroll
        for (int i = 0; i < 16; i++)
#pragma unroll
            for (int j = 0; j < 4; j++) s_acc[i][j] = 0.f;
#pragma unroll
        for (int kb = 0; kb < 4; kb++)
#pragma unroll
            for (int nb2 = 0; nb2 < 8; nb2++) {
                uint32_t bk[4];
                ldm4(bk, kbase + (uint32_t)((nb2 * 16 + ((lane >> 4) & 1) * 8 + (lane & 7)) * 72 +
                                            kb * 16 + ((lane >> 3) & 1) * 8) * 2);
                mma_f16(s_acc[nb2 * 2], aq[kb], bk);
                mma_f16(s_acc[nb2 * 2 + 1], aq[kb], bk + 2);
            }
        float mx0 = -1e30f, mx1 = -1e30f;
#pragma unroll
        for (int t = 0; t < 16; t++) {
            mx0 = fmaxf(mx0, fmaxf(s_acc[t][0], s_acc[t][1]));
            mx1 = fmaxf(mx1, fmaxf(s_acc[t][2], s_acc[t][3]));
        }
        mx0 = fmaxf(mx0, __shfl_xor_sync(0xffffffffu, mx0, 1));
        mx0 = fmaxf(mx0, __shfl_xor_sync(0xffffffffu, mx0, 2));
        mx1 = fmaxf(mx1, __shfl_xor_sync(0xffffffffu, mx1, 1));
        mx1 = fmaxf(mx1, __shfl_xor_sync(0xffffffffu, mx1, 2));
        float mn0 = fmaxf(m_prev0, mx0), mn1 = fmaxf(m_prev1, mx1);
        float sc0 = fexp(m_prev0 - mn0), sc1 = fexp(m_prev1 - mn1);
        m_prev0 = mn0; m_prev1 = mn1;
        float rs0 = 0.f, rs1 = 0.f;
#pragma unroll
        for (int t = 0; t < 16; t++) {
            s_acc[t][0] = fexp(s_acc[t][0] - mn0);
            s_acc[t][1] = fexp(s_acc[t][1] - mn0);
            s_acc[t][2] = fexp(s_acc[t][2] - mn1);
            s_acc[t][3] = fexp(s_acc[t][3] - mn1);
            rs0 += s_acc[t][0] + s_acc[t][1];
            rs1 += s_acc[t][2] + s_acc[t][3];
        }
        rs0 += __shfl_xor_sync(0xffffffffu, rs0, 1);
        rs0 += __shfl_xor_sync(0xffffffffu, rs0, 2);
        rs1 += __shfl_xor_sync(0xffffffffu, rs1, 1);
        rs1 += __shfl_xor_sync(0xffffffffu, rs1, 2);
        l0 = l0 * sc0 + rs0;
        l1 = l1 * sc1 + rs1;
#pragma unroll
        for (int ot = 0; ot < 8; ot++) {
            o_acc[ot][0] *= sc0; o_acc[ot][1] *= sc0;
            o_acc[ot][2] *= sc1; o_acc[ot][3] *= sc1;
        }
#pragma unroll
        for (int pb = 0; pb < 8; pb++) {
            uint32_t ap[4];
            ap[0] = pack_h2(s_acc[2 * pb][0], s_acc[2 * pb][1]);
            ap[1] = pack_h2(s_acc[2 * pb][2], s_acc[2 * pb][3]);
            ap[2] = pack_h2(s_acc[2 * pb + 1][0], s_acc[2 * pb + 1][1]);
            ap[3] = pack_h2(s_acc[2 * pb + 1][2], s_acc[2 * pb + 1][3]);
#pragma unroll
            for (int nb2 = 0; nb2 < 4; nb2++) {
                uint32_t bv[4];
                ldm4t(bv, vbase + (uint32_t)((pb * 16 + (lane & 7) + ((lane >> 3) & 1) * 8) * 72 +
                                             nb2 * 16 + (lane >> 4) * 8) * 2);
                mma_f16(o_acc[nb2 * 2], ap, bv);
                mma_f16(o_acc[nb2 * 2 + 1], ap, bv + 2);
            }
        }
        __syncthreads();
    }
    const float inv0 = 1.f / l0, inv1 = 1.f / l1;
    __half* O = g_o16 + (size_t)b * Ss * Dd + h * HDd;
    const int r = m0 + wm * 16 + (lane >> 2), c2 = (lane & 3) * 2;
#pragma unroll
    for (int ot = 0; ot < 8; ot++) {
        int col = ot * 8 + c2;
        *(uint32_t*)(O + (size_t)r * Dd + col) =
            pack_h2(o_acc[ot][0] * inv0, o_acc[ot][1] * inv0);
        *(uint32_t*)(O + (size_t)(r + 8) * Dd + col) =
            pack_h2(o_acc[ot][2] * inv1, o_acc[ot][3] * inv1);
    }
}

// ---------------- routing compaction ----------------
__global__ void zero_cnt_k() { if (threadIdx.x < Ee) g_cnt[threadIdx.x] = 0; }

__global__ void assign_k() {
    const int t = blockIdx.x * 256 + threadIdx.x;
    if (t >= Tt) return;
#pragma unroll
    for (int j = 0; j < 2; j++) {
        int e = g_topidx[t * 2 + j];
        int pos = atomicAdd(&g_cnt[e], 1);
        g_assign[e * CAP + pos] = t;
        g_slotid[t * 2 + j] = e * CAP + pos;
    }
}

// ---------------- MoE gate/up k64, 3-stage + SiLU -> fp16 h ----------------
__global__ void __launch_bounds__(256) moe_gu16() {
    extern __shared__ __half sm[];
    __shared__ int toks[128];
    const int e = blockIdx.z;
    const int cnt = g_cnt[e];
    const int m0 = blockIdx.x << 7;
    if (m0 >= cnt) return;
    const int n0 = blockIdx.y << 7;
    const uint32_t sb = smem_u32(sm);
    const int tid = threadIdx.x, lane = tid & 31, wid = tid >> 5;
    const int wm = wid & 3, wn = wid >> 2;
    if (tid < 128) toks[tid] = g_assign[e * CAP + min(m0 + tid, cnt - 1)];
    __syncthreads();

    const size_t eo = (size_t)e * Dd * Ff;
    const __half* G = g_Wg16 + eo;
    const __half* U = g_Wu16 + eo;

    float ag[2][8][4], au[2][8][4];
#pragma unroll
    for (int a = 0; a < 2; a++)
#pragma unroll
        for (int c = 0; c < 8; c++)
#pragma unroll
            for (int d = 0; d < 4; d++) { ag[a][c][d] = 0.f; au[a][c][d] = 0.f; }

    const int ra = tid >> 3, ca = (tid & 7) << 3;
    const int rb = tid >> 4, cb = (tid & 15) << 3;

    auto issue = [&](int stg) {
        uint32_t base = sb + (uint32_t)(stg % 3) * STEg * 2;
        int k0 = stg << 6;
#pragma unroll
        for (int i = 0; i < 4; i++)
            CP16(base + (uint32_t)((ra + i * 32) * RS + ca) * 2,
                 g_xt16 + (size_t)toks[ra + i * 32] * Dd + k0 + ca);
#pragma unroll
        for (int i = 0; i < 4; i++) {
            CP16(base + (uint32_t)(OFG + (rb + i * 16) * RSB + cb) * 2,
                 G + (size_t)(k0 + rb + i * 16) * Ff + n0 + cb);
            CP16(base + (uint32_t)(OFU + (rb + i * 16) * RSB + cb) * 2,
                 U + (size_t)(k0 + rb + i * 16) * Ff + n0 + cb);
        }
    };
    issue(0); CPCOMMIT();
    issue(1); CPCOMMIT();

    const int nb = Dd >> 6;  // 16
    for (int it = 0; it < nb; it++) {
        if (it + 2 < nb) issue(it + 2);
        CPCOMMIT();
        CPWAIT2();
        __syncthreads();
        uint32_t base = sb + (uint32_t)(it % 3) * STEg * 2;
#pragma unroll
        for (int ks = 0; ks < 4; ks++) {
            uint32_t a[2][4];
#pragma unroll
            for (int mt = 0; mt < 2; mt++)
                ldm4(a[mt], base + (uint32_t)((wm * 32 + mt * 16 + (lane & 15)) * RS +
                                              ks * 16 + (lane >> 4) * 8) * 2);
            uint32_t roff = (uint32_t)((ks * 16 + (lane & 7) + ((lane >> 3) & 1) * 8) * RSB) * 2;
            uint32_t coff[4];
#pragma unroll
            for (int bt = 0; bt < 4; bt++)
                coff[bt] = (uint32_t)(wn * 64 + bt * 16 + (lane >> 4) * 8) * 2;
            {
                uint32_t bg[4][4];
#pragma unroll
                for (int bt = 0; bt < 4; bt++)
                    ldm4t(bg[bt], base + OFG * 2 + roff + coff[bt]);
#pragma unroll
                for (int mt = 0; mt < 2; mt++)
#pragma unroll
                    for (int nt = 0; nt < 8; nt++)
                        mma_f16(ag[mt][nt], a[mt], &bg[nt >> 1][(nt & 1) * 2]);
            }
            {
                uint32_t bu[4][4];
#pragma unroll
                for (int bt = 0; bt < 4; bt++)
                    ldm4t(bu[bt], base + OFU * 2 + roff + coff[bt]);
#pragma unroll
                for (int mt = 0; mt < 2; mt++)
#pragma unroll
                    for (int nt = 0; nt < 8; nt++)
                        mma_f16(au[mt][nt], a[mt], &bu[nt >> 1][(nt & 1) * 2]);
            }
        }
        __syncthreads();
    }
    const int lr = lane >> 2, lc2 = (lane & 3) * 2;
#pragma unroll
    for (int mt = 0; mt < 2; mt++)
#pragma unroll
        for (int nt = 0; nt < 8; nt++) {
            int r = m0 + wm * 32 + mt * 16 + lr;
            int col = n0 + wn * 64 + nt * 8 + lc2;
#pragma unroll
            for (int half = 0; half < 2; half++) {
                int rr = r + half * 8;
                if (rr < cnt) {
                    float gv0 = ag[mt][nt][half * 2], gv1 = ag[mt][nt][half * 2 + 1];
                    float uv0 = au[mt][nt][half * 2], uv1 = au[mt][nt][half * 2 + 1];
                    float v0 = gv0 * frcp(1.f + fexp(-gv0)) * uv0;
                    float v1 = gv1 * frcp(1.f + fexp(-gv1)) * uv1;
                    *(uint32_t*)(g_h16 + ((size_t)e * CAP + rr) * Ff + col) = pack_h2(v0, v1);
                }
            }
        }
}

// ---------------- MoE down k64 -> g_moeout fp32 (slot rows) ----------------
__global__ void __launch_bounds__(256, 2) moe_down16() {
    extern __shared__ __half sm[];
    const int e = blockIdx.z;
    const int cnt = g_cnt[e];
    const int m0 = blockIdx.x << 7;
    if (m0 >= cnt) return;
    const int n0 = blockIdx.y << 7;
    const uint32_t sb = smem_u32(sm);
    const int tid = threadIdx.x, lane = tid & 31, wid = tid >> 5;
    const int wm = wid & 3, wn = wid >> 2;
    const int cm1 = cnt - 1;

    const __half* A = g_h16 + (size_t)e * CAP * Ff;
    const __half* B = g_Wd16 + (size_t)e * Ff * Dd;

    float acc[2][8][4];
#pragma unroll
    for (int a = 0; a < 2; a++)
#pragma unroll
        for (int c = 0; c < 8; c++)
#pragma unroll
            for (int d = 0; d < 4; d++) acc[a][c][d] = 0.f;

    const int ra = tid >> 3, ca = (tid & 7) << 3;
    const int rb = tid >> 4, cb = (tid & 15) << 3;
    {
        uint32_t base = sb;
#pragma unroll
        for (int i = 0; i < 4; i++)
            CP16(base + (uint32_t)((ra + i * 32) * RS + ca) * 2,
                 A + (size_t)min(m0 + ra + i * 32, cm1) * Ff + ca);
#pragma unroll
        for (int i = 0; i < 4; i++)
            CP16(base + (uint32_t)(OFB + (rb + i * 16) * RSB + cb) * 2,
                 B + (size_t)(rb + i * 16) * Dd + n0 + cb);
        CPCOMMIT();
    }
    const int nb = Ff >> 6;
    for (int it = 0; it < nb; it++) {
        if (it + 1 < nb) {
            uint32_t base = sb + (uint32_t)((it + 1) & 1) * STEd * 2;
            int k0 = (it + 1) << 6;
#pragma unroll
            for (int i = 0; i < 4; i++)
                CP16(base + (uint32_t)((ra + i * 32) * RS + ca) * 2,
                     A + (size_t)min(m0 + ra + i * 32, cm1) * Ff + k0 + ca);
#pragma unroll
            for (int i = 0; i < 4; i++)
                CP16(base + (uint32_t)(OFB + (rb + i * 16) * RSB + cb) * 2,
                     B + (size_t)(k0 + rb + i * 16) * Dd + n0 + cb);
        }
        CPCOMMIT();
        CPWAIT1();
        __syncthreads();
        uint32_t base = sb + (uint32_t)(it & 1) * STEd * 2;
#pragma unroll
        for (int ks = 0; ks < 4; ks++) {
            uint32_t a[2][4];
#pragma unroll
            for (int mt = 0; mt < 2; mt++)
                ldm4(a[mt], base + (uint32_t)((wm * 32 + mt * 16 + (lane & 15)) * RS +
                                              ks * 16 + (lane >> 4) * 8) * 2);
            uint32_t bq[4][4];
#pragma unroll
            for (int bt = 0; bt < 4; bt++)
                ldm4t(bq[bt], base + (uint32_t)(OFB +
                                                (ks * 16 + (lane & 7) + ((lane >> 3) & 1) * 8) * RSB +
                                                wn * 64 + bt * 16 + (lane >> 4) * 8) * 2);
#pragma unroll
            for (int mt = 0; mt < 2; mt++)
#pragma unroll
                for (int nt = 0; nt < 8; nt++)
                    mma_f16(acc[mt][nt], a[mt], &bq[nt >> 1][(nt & 1) * 2]);
        }
        __syncthreads();
    }
    const int lr = lane >> 2, lc2 = (lane & 3) * 2;
#pragma unroll
    for (int mt = 0; mt < 2; mt++)
#pragma unroll
        for (int half = 0; half < 2; half++) {
            int r = m0 + wm * 32 + mt * 16 + lr + half * 8;
            if (r < cnt) {
                float* op = g_moeout + ((size_t)e * CAP + r) * Dd;
#pragma unroll
                for (int nt = 0; nt < 8; nt++) {
                    int col = n0 + wn * 64 + nt * 8 + lc2;
                    *(float2*)(op + col) = make_float2(acc[mt][nt][half * 2],
                                                       acc[mt][nt][half * 2 + 1]);
                }
            }
        }
}

// ---------------- final gather ----------------
__global__ void final_k(float* __restrict__ out) {
    const size_t i4 = ((size_t)blockIdx.x * 256 + threadIdx.x) * 4;
    const int t = (int)(i4 >> 10);
    const int c = (int)(i4 & 1023);
    const int s0 = g_slotid[t * 2 + 0], s1 = g_slotid[t * 2 + 1];
    const float w0 = g_topw[t * 2 + 0], w1 = g_topw[t * 2 + 1];
    float4 hv = *(const float4*)(g_hidden + i4);
    float4 m0 = *(const float4*)(g_moeout + (size_t)s0 * Dd + c);
    float4 m1 = *(const float4*)(g_moeout + (size_t)s1 * Dd + c);
    hv.x += w0 * m0.x + w1 * m1.x;
    hv.y += w0 * m0.y + w1 * m1.y;
    hv.z += w0 * m0.z + w1 * m1.z;
    hv.w += w0 * m0.w + w1 * m1.w;
    *(float4*)(out + i4) = hv;
}

// ---------------- launch ----------------
extern "C" void kernel_launch(void* const* d_in, const int* in_sizes, int n_in,
                              void* d_out, int out_size) {
    (void)in_sizes; (void)n_in;
    const float* hs    = (const float*)d_in[0];
    const float* ln1   = (const float*)d_in[1];
    const float* ln2   = (const float*)d_in[2];
    const float* Wq    = (const float*)d_in[3];
    const float* Wk    = (const float*)d_in[4];
    const float* Wv    = (const float*)d_in[5];
    const float* Wo    = (const float*)d_in[6];
    const float* qn    = (const float*)d_in[7];
    const float* kn    = (const float*)d_in[8];
    const float* gamma = (const float*)d_in[9];
    const float* gw    = (const float*)d_in[10];
    const float* Wg    = (const float*)d_in[11];
    const float* Wu    = (const float*)d_in[12];
    const float* Wd    = (const float*)d_in[13];
    float* out = (float*)d_out;

    float* p_hidden;
    cudaGetSymbolAddress((void**)&p_hidden, g_hidden);

    __half *wq16, *wk16, *wv16, *wo16, *wg16, *wu16, *wd16;
    __half *x16, *q16, *k16, *v16, *o16, *xt16;
    cudaGetSymbolAddress((void**)&wq16, g_Wq16);
    cudaGetSymbolAddress((void**)&wk16, g_Wk16);
    cudaGetSymbolAddress((void**)&wv16, g_Wv16);
    cudaGetSymbolAddress((void**)&wo16, g_Wo16);
    cudaGetSymbolAddress((void**)&wg16, g_Wg16);
    cudaGetSymbolAddress((void**)&wu16, g_Wu16);
    cudaGetSymbolAddress((void**)&wd16, g_Wd16);
    cudaGetSymbolAddress((void**)&x16, g_x16);
    cudaGetSymbolAddress((void**)&q16, g_q16);
    cudaGetSymbolAddress((void**)&k16, g_k16);
    cudaGetSymbolAddress((void**)&v16, g_v16);
    cudaGetSymbolAddress((void**)&o16, g_o16);
    cudaGetSymbolAddress((void**)&xt16, g_xt16);

    cudaFuncSetAttribute(hgemm16, cudaFuncAttributeMaxDynamicSharedMemorySize, SMEMd);
    cudaFuncSetAttribute(moe_down16, cudaFuncAttributeMaxDynamicSharedMemorySize, SMEMd);
    cudaFuncSetAttribute(moe_gu16, cudaFuncAttributeMaxDynamicSharedMemorySize, SMEMg3);
    cudaFuncSetAttribute(fmha_k, cudaFuncAttributeMaxDynamicSharedMemorySize, SMEMf);

    // side stream for big weight converts (created once; fallback to stream 0)
    static cudaStream_t s2 = 0;
    static cudaEvent_t evF = 0, evJ = 0;
    static int sinit = 0;
    if (!sinit) {
        if (cudaStreamCreateWithFlags(&s2, cudaStreamNonBlocking) != cudaSuccess) s2 = 0;
        cudaEventCreateWithFlags(&evF, cudaEventDisableTiming);
        cudaEventCreateWithFlags(&evJ, cudaEventDisableTiming);
        sinit = 1;
    }

    // fork: big MoE weight converts overlap with attention branch
    cudaEventRecord(evF, 0);
    cudaStreamWaitEvent(s2, evF, 0);
    wconv_k<<<(int)((size_t)Ee * Dd * Ff / 2048), 256, 0, s2>>>(Wg, wg16);
    wconv_k<<<(int)((size_t)Ee * Dd * Ff / 2048), 256, 0, s2>>>(Wu, wu16);
    wconv_k<<<(int)((size_t)Ee * Ff * Dd / 2048), 256, 0, s2>>>(Wd, wd16);
    cudaEventRecord(evJ, s2);

    // small converts on main stream
    wconv_k<<<Dd * Dd / 2048, 256>>>(Wq, wq16);
    wconv_k<<<Dd * Dd / 2048, 256>>>(Wk, wk16);
    wconv_k<<<Dd * Dd / 2048, 256>>>(Wv, wv16);
    wconv_k<<<Dd * Dd / 2048, 256>>>(Wo, wo16);

    // --- attention branch ---
    rmsnorm_h<<<Tt, 256>>>(hs, ln1, x16);
    hgemm16<<<dim3(32, 8), 256, SMEMd>>>(x16, wq16, nullptr, q16, nullptr, nullptr, qn, 0.125f, Dd, Dd);
    hgemm16<<<dim3(32, 8), 256, SMEMd>>>(x16, wk16, nullptr, k16, nullptr, nullptr, kn, 1.0f, Dd, Dd);
    hgemm16<<<dim3(32, 8), 256, SMEMd>>>(x16, wv16, nullptr, v16, nullptr, nullptr, nullptr, 1.f, Dd, Dd);
    fmha_k<<<dim3(8, 64), 256, SMEMf>>>();
    hgemm16<<<dim3(32, 8), 256, SMEMd>>>(o16, wo16, p_hidden, nullptr, hs, gamma, nullptr, 1.f, Dd, Dd);

    // --- MoE branch ---
    int write_logits = (out_size >= Tt * Dd + Tt * Ee) ? 1 : 0;
    rmsnorm_router_k<<<Tt, 256>>>(p_hidden, ln2, gw, xt16, out + (size_t)Tt * Dd, write_logits);
    zero_cnt_k<<<1, 32>>>();
    assign_k<<<Tt / 256, 256>>>();
    cudaStreamWaitEvent(0, evJ, 0);   // join: MoE weights ready
    moe_gu16<<<dim3(CAP / 128, Ff / 128, Ee), 256, SMEMg3>>>();
    moe_down16<<<dim3(CAP / 128, Dd / 128, Ee), 256, SMEMd>>>();
    final_k<<<Tt * Dd / 1024, 256>>>(out);
}